// round 8
// baseline (speedup 1.0000x reference)
#include <cuda_runtime.h>
#include <cuda_fp16.h>
#include <math.h>
#include <stdint.h>

#define MP 120000
#define GTC 938     // ceil(MP / 128)

// ---------------- scratch (static device globals; no runtime allocs) ----------
__device__ float  g_V[MP * 64];
__device__ __half g_H16[MP * 64];
__device__ __half g_B16[MP * 64];
__device__ __half g_W1a16[4 * 4096];
__device__ __half g_W1b16[4 * 4096];
__device__ __half g_Wp16[4 * 4096];
__device__ __half g_Wa16[4 * 4096];
__device__ uint4  g_Wf[4 * 27 * 512];   // conv W in mma-fragment order
__device__ float  g_ms[4 * MP * 64];
__device__ float  g_vsum4[4 * MP * 64];
__device__ float  g_vcnt4[4 * MP];

__device__ __forceinline__ float lrelu(float x, float a) { return x > 0.f ? x : a * x; }

__device__ __forceinline__ uint32_t smem_u32(const void* p) {
    uint32_t a;
    asm("{ .reg .u64 t; cvta.to.shared.u64 t, %1; cvt.u32.u64 %0, t; }" : "=r"(a) : "l"(p));
    return a;
}

__device__ __forceinline__ void ldm4(uint32_t r[4], uint32_t addr) {
    asm volatile("ldmatrix.sync.aligned.m8n8.x4.shared.b16 {%0,%1,%2,%3}, [%4];"
                 : "=r"(r[0]), "=r"(r[1]), "=r"(r[2]), "=r"(r[3]) : "r"(addr));
}

__device__ __forceinline__ void mma16816(float c[4], const uint32_t a[4],
                                         uint32_t b0, uint32_t b1) {
    asm volatile(
        "mma.sync.aligned.m16n8k16.row.col.f32.f16.f16.f32 "
        "{%0,%1,%2,%3},{%4,%5,%6,%7},{%8,%9},{%0,%1,%2,%3};"
        : "+f"(c[0]), "+f"(c[1]), "+f"(c[2]), "+f"(c[3])
        : "r"(a[0]), "r"(a[1]), "r"(a[2]), "r"(a[3]), "r"(b0), "r"(b1));
}

#define CP16(dst, src) \
    asm volatile("cp.async.cg.shared.global [%0], [%1], 16;" :: "r"(dst), "l"(src))
#define CP_COMMIT() asm volatile("cp.async.commit_group;" ::: "memory")
#define CP_WAIT(n)  asm volatile("cp.async.wait_group %0;" :: "n"(n) : "memory")
#define STS_ZERO(dst) do { uint32_t _z = 0; \
    asm volatile("st.shared.v4.b32 [%0], {%1,%1,%1,%1};" :: "r"(dst), "r"(_z)); } while (0)

// ========== MMA core (M-tile 128): A(128x64) x W(64x64)^T, 8 warps ============
__device__ __forceinline__ void mma_tile_64(uint32_t a_s, uint32_t w_s,
                                            int lane, int wm, int wn,
                                            float acc[2][4][4]) {
#pragma unroll
    for (int kb = 0; kb < 4; kb++) {
        uint32_t a[2][4], wh[2][4];
#pragma unroll
        for (int mt = 0; mt < 2; mt++) {
            int r = wm + mt * 16 + (lane & 15);
            int lc = kb * 2 + (lane >> 4);
            ldm4(a[mt], a_s + r * 128 + ((lc ^ (r & 7)) << 4));
        }
#pragma unroll
        for (int np = 0; np < 2; np++) {
            int r = wn + np * 16 + (lane & 7) + ((lane & 16) ? 8 : 0);
            int lc = kb * 2 + ((lane >> 3) & 1);
            ldm4(wh[np], w_s + r * 128 + ((lc ^ (r & 7)) << 4));
        }
#pragma unroll
        for (int mt = 0; mt < 2; mt++)
#pragma unroll
            for (int nt = 0; nt < 4; nt++) {
                int np = nt >> 1, q = (nt & 1) * 2;
                mma16816(acc[mt][nt], a[mt], wh[np][q], wh[np][q + 1]);
            }
    }
}

// =================== weight prep: transpose + fp16 (1x1/proj/attn) ============
__global__ void wprep_kernel(const float* __restrict__ w1a, const float* __restrict__ w1b,
                             const float* __restrict__ wp, const float* __restrict__ wa,
                             __half* __restrict__ o1a, __half* __restrict__ o1b,
                             __half* __restrict__ op, __half* __restrict__ oa) {
    int g = blockIdx.x * 256 + threadIdx.x;
    if (g >= 16 * 4096) return;
    int t = g >> 12;
    int rc = g & 4095;
    int d = rc >> 6, c = rc & 63;
    if (t < 4)
        o1a[(size_t)t * 4096 + d * 64 + c] = __float2half_rn(w1a[(size_t)t * 4096 + c * 64 + d]);
    else if (t < 8)
        o1b[(size_t)(t - 4) * 4096 + d * 64 + c] = __float2half_rn(w1b[(size_t)(t - 4) * 4096 + c * 64 + d]);
    else if (t < 12)
        op[(size_t)(t - 8) * 4096 + d * 64 + c] = __float2half_rn(wp[(size_t)(t - 8) * 4096 + c * 64 + d]);
    else
        oa[(size_t)(t - 12) * 4096 + d * 64 + c] = __float2half_rn(wa[(size_t)(t - 12) * 4096 + c * 64 + d]);
}

// ===== conv W -> mma-fragment order: Wf[lt][wn][kb][p][lane] = uint4 ==========
__global__ void wfrag_kernel(const float* __restrict__ w3, uint4* __restrict__ Wf) {
    int idx = blockIdx.x * 256 + threadIdx.x;
    if (idx >= 4 * 27 * 512) return;
    int lane = idx & 31;
    int p    = (idx >> 5) & 1;
    int kb   = (idx >> 6) & 3;
    int wn   = (idx >> 8) & 1;
    int lt   = idx >> 9;
    int g = lane >> 2, t = lane & 3;
    const float* W = w3 + (size_t)lt * 4096;   // [c][d]
    uint32_t r[4];
#pragma unroll
    for (int j = 0; j < 4; j++) {
        int nt = 2 * p + (j >> 1);
        int breg = j & 1;
        int n = wn * 32 + nt * 8 + g;
        int cb = kb * 16 + breg * 8 + 2 * t;
        unsigned short h0 = __half_as_ushort(__float2half_rn(W[cb * 64 + n]));
        unsigned short h1 = __half_as_ushort(__float2half_rn(W[(cb + 1) * 64 + n]));
        r[j] = (uint32_t)h0 | ((uint32_t)h1 << 16);
    }
    Wf[idx] = make_uint4(r[0], r[1], r[2], r[3]);
}

// ============= first-layer GEMM: fp32 input, fp16 out  =======================
__global__ __launch_bounds__(256) void gemm64hf_kernel(
    const float* __restrict__ Xf, const __half* __restrict__ W,
    const float* __restrict__ s, const float* __restrict__ b,
    __half* __restrict__ outh) {
    __shared__ __align__(16) char smA[16384];
    __shared__ __align__(16) char smW[8192];
    const uint32_t a_s = smem_u32(smA);
    const uint32_t w_s = smem_u32(smW);
    const int tid = threadIdx.x;
    const int lane = tid & 31, wid = tid >> 5;
    const int m0 = blockIdx.x * 128;

#pragma unroll
    for (int j = 0; j < 2; j++) {
        int f = tid + j * 256;
        int r = f >> 3, c = f & 7;
        CP16(w_s + r * 128 + ((c ^ (r & 7)) << 4), W + (size_t)r * 64 + c * 8);
    }
    CP_COMMIT();
#pragma unroll
    for (int j = 0; j < 4; j++) {
        int f = tid + j * 256;
        int r = f >> 3, c = f & 7;
        uint32_t dst = a_s + r * 128 + ((c ^ (r & 7)) << 4);
        int m = m0 + r;
        if (m < MP) {
            float4 v0 = *(const float4*)&Xf[(size_t)m * 64 + c * 8];
            float4 v1 = *(const float4*)&Xf[(size_t)m * 64 + c * 8 + 4];
            __half2 h0 = __float22half2_rn(make_float2(v0.x, v0.y));
            __half2 h1 = __float22half2_rn(make_float2(v0.z, v0.w));
            __half2 h2 = __float22half2_rn(make_float2(v1.x, v1.y));
            __half2 h3 = __float22half2_rn(make_float2(v1.z, v1.w));
            uint32_t q0 = *(uint32_t*)&h0, q1 = *(uint32_t*)&h1;
            uint32_t q2 = *(uint32_t*)&h2, q3 = *(uint32_t*)&h3;
            asm volatile("st.shared.v4.b32 [%0], {%1,%2,%3,%4};"
                         :: "r"(dst), "r"(q0), "r"(q1), "r"(q2), "r"(q3));
        } else {
            STS_ZERO(dst);
        }
    }
    CP_WAIT(0);
    __syncthreads();

    const int wm = (wid >> 1) * 32;
    const int wn = (wid & 1) * 32;
    float acc[2][4][4] = {};
    mma_tile_64(a_s, w_s, lane, wm, wn, acc);

    const int qr = lane >> 2, qc = lane & 3;
#pragma unroll
    for (int mt = 0; mt < 2; mt++)
#pragma unroll
        for (int nt = 0; nt < 4; nt++) {
            int col = wn + nt * 8 + qc * 2;
            float2 s2 = *(const float2*)&s[col];
            float2 b2 = *(const float2*)&b[col];
            int r0 = m0 + wm + mt * 16 + qr;
            int r1 = r0 + 8;
            if (r0 < MP) *(__half2*)&outh[(size_t)r0 * 64 + col] = __float22half2_rn(
                make_float2(lrelu(acc[mt][nt][0] * s2.x + b2.x, 0.01f),
                            lrelu(acc[mt][nt][1] * s2.y + b2.y, 0.01f)));
            if (r1 < MP) *(__half2*)&outh[(size_t)r1 * 64 + col] = __float22half2_rn(
                make_float2(lrelu(acc[mt][nt][2] * s2.x + b2.x, 0.01f),
                            lrelu(acc[mt][nt][3] * s2.y + b2.y, 0.01f)));
        }
}

// ====== fused double GEMM: (X@W1)*s1+b1 -> lrelu -> @W2*s2+b2 -> lrelu ========
__global__ __launch_bounds__(256) void gemm64h2_kernel(
    const __half* __restrict__ X,
    const __half* __restrict__ W1, const float* __restrict__ s1, const float* __restrict__ b1,
    const __half* __restrict__ W2, const float* __restrict__ s2, const float* __restrict__ b2,
    __half* __restrict__ outh) {
    __shared__ __align__(16) char smA[16384];
    __shared__ __align__(16) char smB[16384];
    __shared__ __align__(16) char smW1[8192];
    __shared__ __align__(16) char smW2[8192];
    const uint32_t a_s = smem_u32(smA);
    const uint32_t b_s = smem_u32(smB);
    const uint32_t w1_s = smem_u32(smW1);
    const uint32_t w2_s = smem_u32(smW2);
    const int tid = threadIdx.x;
    const int lane = tid & 31, wid = tid >> 5;
    const int m0 = blockIdx.x * 128;

#pragma unroll
    for (int j = 0; j < 4; j++) {
        int f = tid + j * 256;
        int r = f >> 3, c = f & 7;
        uint32_t dst = a_s + r * 128 + ((c ^ (r & 7)) << 4);
        if (m0 + r < MP) CP16(dst, X + (size_t)(m0 + r) * 64 + c * 8);
        else STS_ZERO(dst);
    }
#pragma unroll
    for (int j = 0; j < 2; j++) {
        int f = tid + j * 256;
        int r = f >> 3, c = f & 7;
        CP16(w1_s + r * 128 + ((c ^ (r & 7)) << 4), W1 + (size_t)r * 64 + c * 8);
        CP16(w2_s + r * 128 + ((c ^ (r & 7)) << 4), W2 + (size_t)r * 64 + c * 8);
    }
    CP_COMMIT();
    CP_WAIT(0);
    __syncthreads();

    const int wm = (wid >> 1) * 32;
    const int wn = (wid & 1) * 32;
    const int qr = lane >> 2, qc = lane & 3;

    float acc[2][4][4] = {};
    mma_tile_64(a_s, w1_s, lane, wm, wn, acc);

#pragma unroll
    for (int mt = 0; mt < 2; mt++)
#pragma unroll
        for (int nt = 0; nt < 4; nt++) {
            int col = wn + nt * 8 + qc * 2;
            float2 sv = *(const float2*)&s1[col];
            float2 bv = *(const float2*)&b1[col];
            int lr0 = wm + mt * 16 + qr;
            int lr1 = lr0 + 8;
            __half2 h0 = __float22half2_rn(
                make_float2(lrelu(acc[mt][nt][0] * sv.x + bv.x, 0.01f),
                            lrelu(acc[mt][nt][1] * sv.y + bv.y, 0.01f)));
            __half2 h1 = __float22half2_rn(
                make_float2(lrelu(acc[mt][nt][2] * sv.x + bv.x, 0.01f),
                            lrelu(acc[mt][nt][3] * sv.y + bv.y, 0.01f)));
            uint32_t d0 = lr0 * 128 + (((col >> 3) ^ (lr0 & 7)) << 4) + ((col * 2) & 15);
            uint32_t d1 = lr1 * 128 + (((col >> 3) ^ (lr1 & 7)) << 4) + ((col * 2) & 15);
            *(__half2*)(smB + d0) = h0;
            *(__half2*)(smB + d1) = h1;
        }
    __syncthreads();

    float acc2[2][4][4] = {};
    mma_tile_64(b_s, w2_s, lane, wm, wn, acc2);

#pragma unroll
    for (int mt = 0; mt < 2; mt++)
#pragma unroll
        for (int nt = 0; nt < 4; nt++) {
            int col = wn + nt * 8 + qc * 2;
            float2 sv = *(const float2*)&s2[col];
            float2 bv = *(const float2*)&b2[col];
            int r0 = m0 + wm + mt * 16 + qr;
            int r1 = r0 + 8;
            if (r0 < MP) *(__half2*)&outh[(size_t)r0 * 64 + col] = __float22half2_rn(
                make_float2(lrelu(acc2[mt][nt][0] * sv.x + bv.x, 0.01f),
                            lrelu(acc2[mt][nt][1] * sv.y + bv.y, 0.01f)));
            if (r1 < MP) *(__half2*)&outh[(size_t)r1 * 64 + col] = __float22half2_rn(
                make_float2(lrelu(acc2[mt][nt][2] * sv.x + bv.x, 0.01f),
                            lrelu(acc2[mt][nt][3] * sv.y + bv.y, 0.01f)));
        }
}

// ============ final 1x1: fp16 in, fp32 out with residual ======================
__global__ __launch_bounds__(256) void gemm64h_res_kernel(
    const __half* __restrict__ X, const __half* __restrict__ W,
    const float* __restrict__ s, const float* __restrict__ b,
    float* __restrict__ outf, const float* __restrict__ feats) {
    __shared__ __align__(16) char smA[16384];
    __shared__ __align__(16) char smW[8192];
    const uint32_t a_s = smem_u32(smA);
    const uint32_t w_s = smem_u32(smW);
    const int tid = threadIdx.x;
    const int lane = tid & 31, wid = tid >> 5;
    const int m0 = blockIdx.x * 128;

#pragma unroll
    for (int j = 0; j < 4; j++) {
        int f = tid + j * 256;
        int r = f >> 3, c = f & 7;
        uint32_t dst = a_s + r * 128 + ((c ^ (r & 7)) << 4);
        if (m0 + r < MP) CP16(dst, X + (size_t)(m0 + r) * 64 + c * 8);
        else STS_ZERO(dst);
    }
#pragma unroll
    for (int j = 0; j < 2; j++) {
        int f = tid + j * 256;
        int r = f >> 3, c = f & 7;
        CP16(w_s + r * 128 + ((c ^ (r & 7)) << 4), W + (size_t)r * 64 + c * 8);
    }
    CP_COMMIT();
    CP_WAIT(0);
    __syncthreads();

    const int wm = (wid >> 1) * 32;
    const int wn = (wid & 1) * 32;
    float acc[2][4][4] = {};
    mma_tile_64(a_s, w_s, lane, wm, wn, acc);

    const int qr = lane >> 2, qc = lane & 3;
#pragma unroll
    for (int mt = 0; mt < 2; mt++)
#pragma unroll
        for (int nt = 0; nt < 4; nt++) {
            int col = wn + nt * 8 + qc * 2;
            float2 sv = *(const float2*)&s[col];
            float2 bv = *(const float2*)&b[col];
            int r0 = m0 + wm + mt * 16 + qr;
            int r1 = r0 + 8;
            if (r0 < MP) {
                float2 fr = *(const float2*)&feats[(size_t)r0 * 64 + col];
                *(float2*)&outf[(size_t)r0 * 64 + col] = make_float2(
                    lrelu(lrelu(acc[mt][nt][0] * sv.x + bv.x, 0.01f) + fr.x, 0.1f),
                    lrelu(lrelu(acc[mt][nt][1] * sv.y + bv.y, 0.01f) + fr.y, 0.1f));
            }
            if (r1 < MP) {
                float2 fr = *(const float2*)&feats[(size_t)r1 * 64 + col];
                *(float2*)&outf[(size_t)r1 * 64 + col] = make_float2(
                    lrelu(lrelu(acc[mt][nt][2] * sv.x + bv.x, 0.01f) + fr.x, 0.1f),
                    lrelu(lrelu(acc[mt][nt][3] * sv.y + bv.y, 0.01f) + fr.y, 0.1f));
            }
        }
}

// ====== conv 27-tap, M-tile 128, 2 CTA/SM, warp = 16 rows x ALL 64 cols =======
// A read ONCE per tap per CTA; W from fragment-ordered global (L1-resident).
// smem: nidxT[27][128] int (13824 -> 14336) | A stages 16KB x3 = 63488 bytes
#define CV_A(st) (14336 + (st) * 16384)
#define CV_TOT   63488

__device__ __forceinline__ void cv_fillA(uint32_t sb, int stage, int k,
                                         const int* __restrict__ nidxT,
                                         const __half* __restrict__ H, int tid) {
    uint32_t a_s = sb + CV_A(stage);
#pragma unroll
    for (int j = 0; j < 4; j++) {
        int t = tid + j * 256;
        int r = t >> 3, c = t & 7;
        int row = nidxT[k * 128 + r];
        uint32_t dst = a_s + r * 128 + ((c ^ (r & 7)) << 4);
        if (row >= 0) CP16(dst, H + (size_t)row * 64 + c * 8);
        else STS_ZERO(dst);
    }
}

__global__ __launch_bounds__(256, 2) void conv27_mma_kernel(
    const __half* __restrict__ H, const int* __restrict__ nbr,
    const uint4* __restrict__ Wf,
    const float* __restrict__ s, const float* __restrict__ b,
    __half* __restrict__ out) {
    extern __shared__ char smc[];
    const uint32_t sb = smem_u32(smc);
    const int tid = threadIdx.x;
    const int lane = tid & 31, wid = tid >> 5;
    const int m0 = blockIdx.x * 128;
    int* nidxT = (int*)smc;
    for (int t = tid; t < 27 * 128; t += 256) {
        int k = t >> 7, r = t & 127;
        int m = m0 + r;
        nidxT[t] = (m < MP) ? nbr[(size_t)m * 27 + k] : -1;
    }
    __syncthreads();

    cv_fillA(sb, 0, 0, nidxT, H, tid);
    CP_COMMIT();
    cv_fillA(sb, 1, 1, nidxT, H, tid);
    CP_COMMIT();

    const int wm = wid * 16;          // warp owns rows [wm, wm+16), all 64 cols
    float acc[8][4] = {};
    int stage = 0;

    for (int k = 0; k < 27; k++) {
        if (k < 26) CP_WAIT(1);
        else        CP_WAIT(0);
        __syncthreads();
        if (k < 25) {
            int ns = stage + 2;
            if (ns >= 3) ns -= 3;
            cv_fillA(sb, ns, k + 2, nidxT, H, tid);
            CP_COMMIT();
        }
        uint32_t a_s = sb + CV_A(stage);
        const uint4* wk = Wf + (size_t)k * 512 + lane;
#pragma unroll
        for (int kb = 0; kb < 4; kb++) {
            uint32_t a[4];
            {
                int r = wm + (lane & 15);
                int lc = kb * 2 + (lane >> 4);
                ldm4(a, a_s + r * 128 + ((lc ^ (r & 7)) << 4));
            }
            uint4 w0 = wk[kb * 64];              // wn0, p0: n-blocks 0,1
            uint4 w1 = wk[kb * 64 + 32];         // wn0, p1: n-blocks 2,3
            uint4 w2 = wk[256 + kb * 64];        // wn1, p0: n-blocks 4,5
            uint4 w3r = wk[256 + kb * 64 + 32];  // wn1, p1: n-blocks 6,7
            mma16816(acc[0], a, w0.x, w0.y);
            mma16816(acc[1], a, w0.z, w0.w);
            mma16816(acc[2], a, w1.x, w1.y);
            mma16816(acc[3], a, w1.z, w1.w);
            mma16816(acc[4], a, w2.x, w2.y);
            mma16816(acc[5], a, w2.z, w2.w);
            mma16816(acc[6], a, w3r.x, w3r.y);
            mma16816(acc[7], a, w3r.z, w3r.w);
        }
        if (++stage == 3) stage = 0;
    }

    const int qr = lane >> 2, qc = lane & 3;
#pragma unroll
    for (int ntg = 0; ntg < 8; ntg++) {
        int col = ntg * 8 + qc * 2;
        float2 s2 = *(const float2*)&s[col];
        float2 b2 = *(const float2*)&b[col];
        int r0 = m0 + wm + qr;
        int r1 = r0 + 8;
        if (r0 < MP) *(__half2*)&out[(size_t)r0 * 64 + col] = __float22half2_rn(
            make_float2(lrelu(acc[ntg][0] * s2.x + b2.x, 0.01f),
                        lrelu(acc[ntg][1] * s2.y + b2.y, 0.01f)));
        if (r1 < MP) *(__half2*)&out[(size_t)r1 * 64 + col] = __float22half2_rn(
            make_float2(lrelu(acc[ntg][2] * s2.x + b2.x, 0.01f),
                        lrelu(acc[ntg][3] * s2.y + b2.y, 0.01f)));
    }
}

// =================== batched scatter-mean over all 4 scales ===================
__global__ void zero_all_kernel(float* __restrict__ vsum4, float* __restrict__ vcnt4) {
    int gid = blockIdx.x * 256 + threadIdx.x;
    if (gid < 4 * MP * 16) ((float4*)vsum4)[gid] = make_float4(0.f, 0.f, 0.f, 0.f);
    if (gid < 4 * MP) vcnt4[gid] = 0.f;
}

__global__ void scatter_all_kernel(const float* __restrict__ V, const int* __restrict__ inv,
                                   float* __restrict__ vsum4, float* __restrict__ vcnt4) {
    int gid = blockIdx.x * 256 + threadIdx.x;
    if (gid >= 4 * MP * 64) return;
    int si = gid / (MP * 64);
    int rem = gid - si * (MP * 64);
    int m = rem >> 6, c = rem & 63;
    int sg = inv[si * MP + m];
    atomicAdd(&vsum4[(size_t)si * MP * 64 + sg * 64 + c], V[rem]);
    if (c == 0) atomicAdd(&vcnt4[si * MP + sg], 1.0f);
}

// ============ tensorized proj: Os=(V-mean)*V (fp16) @ proj_w, grid (GTC,4) ====
__global__ __launch_bounds__(256) void proj_mma_kernel(
    const float* __restrict__ V, const int* __restrict__ inv,
    const float* __restrict__ vsum4, const float* __restrict__ vcnt4,
    const __half* __restrict__ Wp, const float* __restrict__ pb,
    const float* __restrict__ ps, const float* __restrict__ pbb,
    float* __restrict__ ms) {
    __shared__ __align__(16) char smA[16384];
    __shared__ __align__(16) char smW[8192];
    const uint32_t a_s = smem_u32(smA);
    const uint32_t w_s = smem_u32(smW);
    const int tid = threadIdx.x;
    const int lane = tid & 31, wid = tid >> 5;
    const int m0 = blockIdx.x * 128;
    const int si = blockIdx.y;
    const int* seg = inv + (size_t)si * MP;
    const float* vsum = vsum4 + (size_t)si * MP * 64;
    const float* vcnt = vcnt4 + (size_t)si * MP;
    float* msO = ms + (size_t)si * MP * 64;

#pragma unroll
    for (int j = 0; j < 2; j++) {
        int f = tid + j * 256;
        int r = f >> 3, c = f & 7;
        CP16(w_s + r * 128 + ((c ^ (r & 7)) << 4),
             Wp + (size_t)si * 4096 + r * 64 + c * 8);
    }
    CP_COMMIT();
#pragma unroll
    for (int j = 0; j < 4; j++) {
        int f = tid + j * 256;
        int r = f >> 3, c = f & 7;
        uint32_t dst = a_s + r * 128 + ((c ^ (r & 7)) << 4);
        int m = m0 + r;
        if (m < MP) {
            int sg = seg[m];
            float rc = 1.0f / fmaxf(vcnt[sg], 1.0f);
            float4 v0 = *(const float4*)&V[(size_t)m * 64 + c * 8];
            float4 v1 = *(const float4*)&V[(size_t)m * 64 + c * 8 + 4];
            float4 u0 = *(const float4*)&vsum[(size_t)sg * 64 + c * 8];
            float4 u1 = *(const float4*)&vsum[(size_t)sg * 64 + c * 8 + 4];
            __half2 h0 = __float22half2_rn(make_float2((v0.x - u0.x * rc) * v0.x,
                                                       (v0.y - u0.y * rc) * v0.y));
            __half2 h1 = __float22half2_rn(make_float2((v0.z - u0.z * rc) * v0.z,
                                                       (v0.w - u0.w * rc) * v0.w));
            __half2 h2 = __float22half2_rn(make_float2((v1.x - u1.x * rc) * v1.x,
                                                       (v1.y - u1.y * rc) * v1.y));
            __half2 h3 = __float22half2_rn(make_float2((v1.z - u1.z * rc) * v1.z,
                                                       (v1.w - u1.w * rc) * v1.w));
            uint32_t q0 = *(uint32_t*)&h0, q1 = *(uint32_t*)&h1;
            uint32_t q2 = *(uint32_t*)&h2, q3 = *(uint32_t*)&h3;
            asm volatile("st.shared.v4.b32 [%0], {%1,%2,%3,%4};"
                         :: "r"(dst), "r"(q0), "r"(q1), "r"(q2), "r"(q3));
        } else {
            STS_ZERO(dst);
        }
    }
    CP_WAIT(0);
    __syncthreads();

    const int wm = (wid >> 1) * 32;
    const int wn = (wid & 1) * 32;
    float acc[2][4][4] = {};
    mma_tile_64(a_s, w_s, lane, wm, wn, acc);

    const int qr = lane >> 2, qc = lane & 3;
#pragma unroll
    for (int mt = 0; mt < 2; mt++)
#pragma unroll
        for (int nt = 0; nt < 4; nt++) {
            int col = wn + nt * 8 + qc * 2;
            float2 bv = *(const float2*)&pb[si * 64 + col];
            float2 sv = *(const float2*)&ps[si * 64 + col];
            float2 b2 = *(const float2*)&pbb[si * 64 + col];
            int r0 = m0 + wm + mt * 16 + qr;
            int r1 = r0 + 8;
            if (r0 < MP) *(float2*)&msO[(size_t)r0 * 64 + col] = make_float2(
                lrelu((acc[mt][nt][0] + bv.x) * sv.x + b2.x, 0.01f),
                lrelu((acc[mt][nt][1] + bv.y) * sv.y + b2.y, 0.01f));
            if (r1 < MP) *(float2*)&msO[(size_t)r1 * 64 + col] = make_float2(
                lrelu((acc[mt][nt][2] + bv.x) * sv.x + b2.x, 0.01f),
                lrelu((acc[mt][nt][3] + bv.y) * sv.y + b2.y, 0.01f));
        }
}

// ===== tensorized attn: sumx built in-kernel (fp16), 4 GEMMs, fused output ====
__global__ __launch_bounds__(256) void attn_mma_kernel(
    const float* __restrict__ ms, const __half* __restrict__ Wa,
    const float* __restrict__ ab, const float* __restrict__ as_,
    const float* __restrict__ abb, float* __restrict__ fused) {
    __shared__ __align__(16) char smA[16384];
    __shared__ __align__(16) char smW[8192];
    const uint32_t a_s = smem_u32(smA);
    const uint32_t w_s = smem_u32(smW);
    const int tid = threadIdx.x;
    const int lane = tid & 31, wid = tid >> 5;
    const int m0 = blockIdx.x * 128;

#pragma unroll
    for (int j = 0; j < 4; j++) {
        int f = tid + j * 256;
        int r = f >> 3, c = f & 7;
        uint32_t dst = a_s + r * 128 + ((c ^ (r & 7)) << 4);
        int m = m0 + r;
        if (m < MP) {
            float sx[8] = {};
#pragma unroll
            for (int i = 0; i < 4; i++) {
                float4 v0 = *(const float4*)&ms[((size_t)i * MP + m) * 64 + c * 8];
                float4 v1 = *(const float4*)&ms[((size_t)i * MP + m) * 64 + c * 8 + 4];
                sx[0] += v0.x; sx[1] += v0.y; sx[2] += v0.z; sx[3] += v0.w;
                sx[4] += v1.x; sx[5] += v1.y; sx[6] += v1.z; sx[7] += v1.w;
            }
            __half2 h0 = __float22half2_rn(make_float2(sx[0], sx[1]));
            __half2 h1 = __float22half2_rn(make_float2(sx[2], sx[3]));
            __half2 h2 = __float22half2_rn(make_float2(sx[4], sx[5]));
            __half2 h3 = __float22half2_rn(make_float2(sx[6], sx[7]));
            uint32_t q0 = *(uint32_t*)&h0, q1 = *(uint32_t*)&h1;
            uint32_t q2 = *(uint32_t*)&h2, q3 = *(uint32_t*)&h3;
            asm volatile("st.shared.v4.b32 [%0], {%1,%2,%3,%4};"
                         :: "r"(dst), "r"(q0), "r"(q1), "r"(q2), "r"(q3));
        } else {
            STS_ZERO(dst);
        }
    }

    const int wm = (wid >> 1) * 32;
    const int wn = (wid & 1) * 32;
    const int qr = lane >> 2, qc = lane & 3;
    float fac[2][4][4] = {};

    for (int i = 0; i < 4; i++) {
        __syncthreads();
#pragma unroll
        for (int j = 0; j < 2; j++) {
            int f = tid + j * 256;
            int r = f >> 3, c = f & 7;
            CP16(w_s + r * 128 + ((c ^ (r & 7)) << 4),
                 Wa + (size_t)i * 4096 + r * 64 + c * 8);
        }
        CP_COMMIT();
        CP_WAIT(0);
        __syncthreads();

        float acc[2][4][4] = {};
        mma_tile_64(a_s, w_s, lane, wm, wn, acc);

#pragma unroll
        for (int mt = 0; mt < 2; mt++)
#pragma unroll
            for (int nt = 0; nt < 4; nt++) {
                int col = wn + nt * 8 + qc * 2;
                float2 bv = *(const float2*)&ab[i * 64 + col];
                float2 sv = *(const float2*)&as_[i * 64 + col];
                float2 b2 = *(const float2*)&abb[i * 64 + col];
                int r0 = m0 + wm + mt * 16 + qr;
                int r1 = r0 + 8;
                if (r0 < MP) {
                    float2 mv = *(const float2*)&ms[((size_t)i * MP + r0) * 64 + col];
                    float a0 = 1.0f / (1.0f + __expf(-((acc[mt][nt][0] + bv.x) * sv.x + b2.x)));
                    float a1 = 1.0f / (1.0f + __expf(-((acc[mt][nt][1] + bv.y) * sv.y + b2.y)));
                    fac[mt][nt][0] += a0 * mv.x;
                    fac[mt][nt][1] += a1 * mv.y;
                }
                if (r1 < MP) {
                    float2 mv = *(const float2*)&ms[((size_t)i * MP + r1) * 64 + col];
                    float a2 = 1.0f / (1.0f + __expf(-((acc[mt][nt][2] + bv.x) * sv.x + b2.x)));
                    float a3 = 1.0f / (1.0f + __expf(-((acc[mt][nt][3] + bv.y) * sv.y + b2.y)));
                    fac[mt][nt][2] += a2 * mv.x;
                    fac[mt][nt][3] += a3 * mv.y;
                }
            }
    }

#pragma unroll
    for (int mt = 0; mt < 2; mt++)
#pragma unroll
        for (int nt = 0; nt < 4; nt++) {
            int col = wn + nt * 8 + qc * 2;
            int r0 = m0 + wm + mt * 16 + qr;
            int r1 = r0 + 8;
            if (r0 < MP) *(float2*)&fused[(size_t)r0 * 64 + col] =
                make_float2(fac[mt][nt][0], fac[mt][nt][1]);
            if (r1 < MP) *(float2*)&fused[(size_t)r1 * 64 + col] =
                make_float2(fac[mt][nt][2], fac[mt][nt][3]);
        }
}

// ================================ N=20 heads ==================================
__global__ __launch_bounds__(256) void gemm_n20_kernel(
    const float* __restrict__ X, const float* __restrict__ W,
    const float* __restrict__ b, float* __restrict__ out) {
    __shared__ float Xs[128 * 68];
    __shared__ float Ws[64 * 20];
    __shared__ float bs[20];
    const int tid = threadIdx.x;
    const int m0 = blockIdx.x * 128;
#pragma unroll
    for (int j = 0; j < 8; j++) {
        int f = tid + 256 * j;
        int r = f >> 4, c4 = f & 15;
        int m = m0 + r;
        float4 v = make_float4(0.f, 0.f, 0.f, 0.f);
        if (m < MP) v = *(const float4*)&X[(size_t)m * 64 + c4 * 4];
        *(float4*)&Xs[r * 68 + c4 * 4] = v;
    }
    for (int f = tid; f < 64 * 20; f += 256) Ws[f] = W[f];
    if (tid < 20) bs[tid] = b[tid];
    __syncthreads();
    int r = tid >> 1, half = tid & 1, n0 = half * 10;
    int m = m0 + r;
    if (m < MP) {
        float acc[10];
#pragma unroll
        for (int j = 0; j < 10; j++) acc[j] = bs[n0 + j];
#pragma unroll 8
        for (int c = 0; c < 64; c++) {
            float x = Xs[r * 68 + c];
#pragma unroll
            for (int j = 0; j < 10; j++) acc[j] += x * Ws[c * 20 + n0 + j];
        }
#pragma unroll
        for (int j = 0; j < 10; j++) out[(size_t)m * 20 + n0 + j] = acc[j];
    }
}

// ==============================================================================
extern "C" void kernel_launch(void* const* d_in, const int* in_sizes, int n_in,
                              void* d_out, int out_size) {
    const float* feats   = (const float*)d_in[0];
    const float* w1a     = (const float*)d_in[1];
    const float* s1a     = (const float*)d_in[2];
    const float* b1a     = (const float*)d_in[3];
    const float* w3      = (const float*)d_in[4];
    const float* s3      = (const float*)d_in[5];
    const float* b3      = (const float*)d_in[6];
    const float* w1b     = (const float*)d_in[7];
    const float* s1b     = (const float*)d_in[8];
    const float* b1b     = (const float*)d_in[9];
    const float* aux_w   = (const float*)d_in[10];
    const float* aux_b   = (const float*)d_in[11];
    const float* proj_w  = (const float*)d_in[12];
    const float* proj_b  = (const float*)d_in[13];
    const float* proj_s  = (const float*)d_in[14];
    const float* proj_bb = (const float*)d_in[15];
    const float* attn_w  = (const float*)d_in[16];
    const float* attn_b  = (const float*)d_in[17];
    const float* attn_s  = (const float*)d_in[18];
    const float* attn_bb = (const float*)d_in[19];
    const float* head_w  = (const float*)d_in[20];
    const float* head_b  = (const float*)d_in[21];
    const int*   nbr     = (const int*)d_in[22];
    const int*   inv     = (const int*)d_in[23];

    float* out    = (float*)d_out;
    float* fused  = out;
    float* logits = out + (size_t)MP * 64;
    float* aux    = out + (size_t)MP * 84;

    float *pV, *pms, *pvs, *pvc;
    __half *pH16, *pB16, *pW1a, *pW1b, *pWp, *pWa;
    uint4 *pWf;
    cudaGetSymbolAddress((void**)&pV, g_V);
    cudaGetSymbolAddress((void**)&pms, g_ms);
    cudaGetSymbolAddress((void**)&pvs, g_vsum4);
    cudaGetSymbolAddress((void**)&pvc, g_vcnt4);
    cudaGetSymbolAddress((void**)&pH16, g_H16);
    cudaGetSymbolAddress((void**)&pB16, g_B16);
    cudaGetSymbolAddress((void**)&pW1a, g_W1a16);
    cudaGetSymbolAddress((void**)&pW1b, g_W1b16);
    cudaGetSymbolAddress((void**)&pWp, g_Wp16);
    cudaGetSymbolAddress((void**)&pWa, g_Wa16);
    cudaGetSymbolAddress((void**)&pWf, g_Wf);

    cudaFuncSetAttribute(conv27_mma_kernel, cudaFuncAttributeMaxDynamicSharedMemorySize, CV_TOT);

    wprep_kernel<<<(16 * 4096 + 255) / 256, 256>>>(w1a, w1b, proj_w, attn_w,
                                                   pW1a, pW1b, pWp, pWa);
    wfrag_kernel<<<216, 256>>>(w3, pWf);

    gemm64hf_kernel<<<GTC, 256>>>(feats, pW1a, s1a, b1a, pH16);
    for (int i = 0; i < 4; i++) {
        conv27_mma_kernel<<<GTC, 256, CV_TOT>>>(pH16, nbr, pWf + (size_t)i * 27 * 512,
                                                s3 + i * 64, b3 + i * 64, pB16);
        if (i < 3) {
            gemm64h2_kernel<<<GTC, 256>>>(pB16,
                                          pW1b + (size_t)i * 4096, s1b + i * 64, b1b + i * 64,
                                          pW1a + (size_t)(i + 1) * 4096, s1a + (i + 1) * 64,
                                          b1a + (i + 1) * 64, pH16);
        } else {
            gemm64h_res_kernel<<<GTC, 256>>>(pB16, pW1b + (size_t)i * 4096, s1b + i * 64,
                                             b1b + i * 64, pV, feats);
        }
    }

    gemm_n20_kernel<<<938, 256>>>(pV, aux_w, aux_b, aux);

    zero_all_kernel<<<30000, 256>>>(pvs, pvc);
    scatter_all_kernel<<<120000, 256>>>(pV, inv, pvs, pvc);
    {
        dim3 grid(GTC, 4);
        proj_mma_kernel<<<grid, 256>>>(pV, inv, pvs, pvc, pWp,
                                       proj_b, proj_s, proj_bb, pms);
    }
    attn_mma_kernel<<<GTC, 256>>>(pms, pWa, attn_b, attn_s, attn_bb, fused);
    gemm_n20_kernel<<<938, 256>>>(fused, head_w, head_b, logits);
}

// round 9
// speedup vs baseline: 1.0238x; 1.0238x over previous
#include <cuda_runtime.h>
#include <cuda_fp16.h>
#include <math.h>
#include <stdint.h>

#define MP 120000
#define GTC 938     // ceil(MP / 128)

// ---------------- scratch (static device globals; no runtime allocs) ----------
__device__ float  g_V[MP * 64];
__device__ __half g_H16[MP * 64];
__device__ __half g_B16[MP * 64];
__device__ __half g_W1a16[4 * 4096];
__device__ __half g_W1b16[4 * 4096];
__device__ __half g_Wp16[4 * 4096];
__device__ __half g_Wa16[4 * 4096];
__device__ uint4  g_Wf[4 * 27 * 512];   // conv W in mma-fragment order
__device__ float  g_ms[4 * MP * 64];
__device__ float  g_vsum4[4 * MP * 64];
__device__ float  g_vcnt4[4 * MP];

__device__ __forceinline__ float lrelu(float x, float a) { return x > 0.f ? x : a * x; }

__device__ __forceinline__ uint32_t smem_u32(const void* p) {
    uint32_t a;
    asm("{ .reg .u64 t; cvta.to.shared.u64 t, %1; cvt.u32.u64 %0, t; }" : "=r"(a) : "l"(p));
    return a;
}

__device__ __forceinline__ void ldm4(uint32_t r[4], uint32_t addr) {
    asm volatile("ldmatrix.sync.aligned.m8n8.x4.shared.b16 {%0,%1,%2,%3}, [%4];"
                 : "=r"(r[0]), "=r"(r[1]), "=r"(r[2]), "=r"(r[3]) : "r"(addr));
}

__device__ __forceinline__ void mma16816(float c[4], const uint32_t a[4],
                                         uint32_t b0, uint32_t b1) {
    asm volatile(
        "mma.sync.aligned.m16n8k16.row.col.f32.f16.f16.f32 "
        "{%0,%1,%2,%3},{%4,%5,%6,%7},{%8,%9},{%0,%1,%2,%3};"
        : "+f"(c[0]), "+f"(c[1]), "+f"(c[2]), "+f"(c[3])
        : "r"(a[0]), "r"(a[1]), "r"(a[2]), "r"(a[3]), "r"(b0), "r"(b1));
}

#define CP16(dst, src) \
    asm volatile("cp.async.cg.shared.global [%0], [%1], 16;" :: "r"(dst), "l"(src))
#define CP_COMMIT() asm volatile("cp.async.commit_group;" ::: "memory")
#define CP_WAIT(n)  asm volatile("cp.async.wait_group %0;" :: "n"(n) : "memory")
#define STS_ZERO(dst) do { uint32_t _z = 0; \
    asm volatile("st.shared.v4.b32 [%0], {%1,%1,%1,%1};" :: "r"(dst), "r"(_z)); } while (0)

// ========== MMA core (M-tile 128): A(128x64) x W(64x64)^T, 8 warps ============
__device__ __forceinline__ void mma_tile_64(uint32_t a_s, uint32_t w_s,
                                            int lane, int wm, int wn,
                                            float acc[2][4][4]) {
#pragma unroll
    for (int kb = 0; kb < 4; kb++) {
        uint32_t a[2][4], wh[2][4];
#pragma unroll
        for (int mt = 0; mt < 2; mt++) {
            int r = wm + mt * 16 + (lane & 15);
            int lc = kb * 2 + (lane >> 4);
            ldm4(a[mt], a_s + r * 128 + ((lc ^ (r & 7)) << 4));
        }
#pragma unroll
        for (int np = 0; np < 2; np++) {
            int r = wn + np * 16 + (lane & 7) + ((lane & 16) ? 8 : 0);
            int lc = kb * 2 + ((lane >> 3) & 1);
            ldm4(wh[np], w_s + r * 128 + ((lc ^ (r & 7)) << 4));
        }
#pragma unroll
        for (int mt = 0; mt < 2; mt++)
#pragma unroll
            for (int nt = 0; nt < 4; nt++) {
                int np = nt >> 1, q = (nt & 1) * 2;
                mma16816(acc[mt][nt], a[mt], wh[np][q], wh[np][q + 1]);
            }
    }
}

// =================== weight prep: transpose + fp16 (1x1/proj/attn) ============
__global__ void wprep_kernel(const float* __restrict__ w1a, const float* __restrict__ w1b,
                             const float* __restrict__ wp, const float* __restrict__ wa,
                             __half* __restrict__ o1a, __half* __restrict__ o1b,
                             __half* __restrict__ op, __half* __restrict__ oa) {
    int g = blockIdx.x * 256 + threadIdx.x;
    if (g >= 16 * 4096) return;
    int t = g >> 12;
    int rc = g & 4095;
    int d = rc >> 6, c = rc & 63;
    if (t < 4)
        o1a[(size_t)t * 4096 + d * 64 + c] = __float2half_rn(w1a[(size_t)t * 4096 + c * 64 + d]);
    else if (t < 8)
        o1b[(size_t)(t - 4) * 4096 + d * 64 + c] = __float2half_rn(w1b[(size_t)(t - 4) * 4096 + c * 64 + d]);
    else if (t < 12)
        op[(size_t)(t - 8) * 4096 + d * 64 + c] = __float2half_rn(wp[(size_t)(t - 8) * 4096 + c * 64 + d]);
    else
        oa[(size_t)(t - 12) * 4096 + d * 64 + c] = __float2half_rn(wa[(size_t)(t - 12) * 4096 + c * 64 + d]);
}

// ===== conv W -> mma-fragment order: Wf[lt][wn][kb][p][lane] = uint4 ==========
__global__ void wfrag_kernel(const float* __restrict__ w3, uint4* __restrict__ Wf) {
    int idx = blockIdx.x * 256 + threadIdx.x;
    if (idx >= 4 * 27 * 512) return;
    int lane = idx & 31;
    int p    = (idx >> 5) & 1;
    int kb   = (idx >> 6) & 3;
    int wn   = (idx >> 8) & 1;
    int lt   = idx >> 9;
    int g = lane >> 2, t = lane & 3;
    const float* W = w3 + (size_t)lt * 4096;   // [c][d]
    uint32_t r[4];
#pragma unroll
    for (int j = 0; j < 4; j++) {
        int nt = 2 * p + (j >> 1);
        int breg = j & 1;
        int n = wn * 32 + nt * 8 + g;
        int cb = kb * 16 + breg * 8 + 2 * t;
        unsigned short h0 = __half_as_ushort(__float2half_rn(W[cb * 64 + n]));
        unsigned short h1 = __half_as_ushort(__float2half_rn(W[(cb + 1) * 64 + n]));
        r[j] = (uint32_t)h0 | ((uint32_t)h1 << 16);
    }
    Wf[idx] = make_uint4(r[0], r[1], r[2], r[3]);
}

// ============= first-layer GEMM: fp32 input, fp16 out  =======================
__global__ __launch_bounds__(256) void gemm64hf_kernel(
    const float* __restrict__ Xf, const __half* __restrict__ W,
    const float* __restrict__ s, const float* __restrict__ b,
    __half* __restrict__ outh) {
    __shared__ __align__(16) char smA[16384];
    __shared__ __align__(16) char smW[8192];
    const uint32_t a_s = smem_u32(smA);
    const uint32_t w_s = smem_u32(smW);
    const int tid = threadIdx.x;
    const int lane = tid & 31, wid = tid >> 5;
    const int m0 = blockIdx.x * 128;

#pragma unroll
    for (int j = 0; j < 2; j++) {
        int f = tid + j * 256;
        int r = f >> 3, c = f & 7;
        CP16(w_s + r * 128 + ((c ^ (r & 7)) << 4), W + (size_t)r * 64 + c * 8);
    }
    CP_COMMIT();
#pragma unroll
    for (int j = 0; j < 4; j++) {
        int f = tid + j * 256;
        int r = f >> 3, c = f & 7;
        uint32_t dst = a_s + r * 128 + ((c ^ (r & 7)) << 4);
        int m = m0 + r;
        if (m < MP) {
            float4 v0 = *(const float4*)&Xf[(size_t)m * 64 + c * 8];
            float4 v1 = *(const float4*)&Xf[(size_t)m * 64 + c * 8 + 4];
            __half2 h0 = __float22half2_rn(make_float2(v0.x, v0.y));
            __half2 h1 = __float22half2_rn(make_float2(v0.z, v0.w));
            __half2 h2 = __float22half2_rn(make_float2(v1.x, v1.y));
            __half2 h3 = __float22half2_rn(make_float2(v1.z, v1.w));
            uint32_t q0 = *(uint32_t*)&h0, q1 = *(uint32_t*)&h1;
            uint32_t q2 = *(uint32_t*)&h2, q3 = *(uint32_t*)&h3;
            asm volatile("st.shared.v4.b32 [%0], {%1,%2,%3,%4};"
                         :: "r"(dst), "r"(q0), "r"(q1), "r"(q2), "r"(q3));
        } else {
            STS_ZERO(dst);
        }
    }
    CP_WAIT(0);
    __syncthreads();

    const int wm = (wid >> 1) * 32;
    const int wn = (wid & 1) * 32;
    float acc[2][4][4] = {};
    mma_tile_64(a_s, w_s, lane, wm, wn, acc);

    const int qr = lane >> 2, qc = lane & 3;
#pragma unroll
    for (int mt = 0; mt < 2; mt++)
#pragma unroll
        for (int nt = 0; nt < 4; nt++) {
            int col = wn + nt * 8 + qc * 2;
            float2 s2 = *(const float2*)&s[col];
            float2 b2 = *(const float2*)&b[col];
            int r0 = m0 + wm + mt * 16 + qr;
            int r1 = r0 + 8;
            if (r0 < MP) *(__half2*)&outh[(size_t)r0 * 64 + col] = __float22half2_rn(
                make_float2(lrelu(acc[mt][nt][0] * s2.x + b2.x, 0.01f),
                            lrelu(acc[mt][nt][1] * s2.y + b2.y, 0.01f)));
            if (r1 < MP) *(__half2*)&outh[(size_t)r1 * 64 + col] = __float22half2_rn(
                make_float2(lrelu(acc[mt][nt][2] * s2.x + b2.x, 0.01f),
                            lrelu(acc[mt][nt][3] * s2.y + b2.y, 0.01f)));
        }
}

// ====== fused double GEMM: (X@W1)*s1+b1 -> lrelu -> @W2*s2+b2 -> lrelu ========
__global__ __launch_bounds__(256) void gemm64h2_kernel(
    const __half* __restrict__ X,
    const __half* __restrict__ W1, const float* __restrict__ s1, const float* __restrict__ b1,
    const __half* __restrict__ W2, const float* __restrict__ s2, const float* __restrict__ b2,
    __half* __restrict__ outh) {
    __shared__ __align__(16) char smA[16384];
    __shared__ __align__(16) char smB[16384];
    __shared__ __align__(16) char smW1[8192];
    __shared__ __align__(16) char smW2[8192];
    const uint32_t a_s = smem_u32(smA);
    const uint32_t b_s = smem_u32(smB);
    const uint32_t w1_s = smem_u32(smW1);
    const uint32_t w2_s = smem_u32(smW2);
    const int tid = threadIdx.x;
    const int lane = tid & 31, wid = tid >> 5;
    const int m0 = blockIdx.x * 128;

#pragma unroll
    for (int j = 0; j < 4; j++) {
        int f = tid + j * 256;
        int r = f >> 3, c = f & 7;
        uint32_t dst = a_s + r * 128 + ((c ^ (r & 7)) << 4);
        if (m0 + r < MP) CP16(dst, X + (size_t)(m0 + r) * 64 + c * 8);
        else STS_ZERO(dst);
    }
#pragma unroll
    for (int j = 0; j < 2; j++) {
        int f = tid + j * 256;
        int r = f >> 3, c = f & 7;
        CP16(w1_s + r * 128 + ((c ^ (r & 7)) << 4), W1 + (size_t)r * 64 + c * 8);
        CP16(w2_s + r * 128 + ((c ^ (r & 7)) << 4), W2 + (size_t)r * 64 + c * 8);
    }
    CP_COMMIT();
    CP_WAIT(0);
    __syncthreads();

    const int wm = (wid >> 1) * 32;
    const int wn = (wid & 1) * 32;
    const int qr = lane >> 2, qc = lane & 3;

    float acc[2][4][4] = {};
    mma_tile_64(a_s, w1_s, lane, wm, wn, acc);

#pragma unroll
    for (int mt = 0; mt < 2; mt++)
#pragma unroll
        for (int nt = 0; nt < 4; nt++) {
            int col = wn + nt * 8 + qc * 2;
            float2 sv = *(const float2*)&s1[col];
            float2 bv = *(const float2*)&b1[col];
            int lr0 = wm + mt * 16 + qr;
            int lr1 = lr0 + 8;
            __half2 h0 = __float22half2_rn(
                make_float2(lrelu(acc[mt][nt][0] * sv.x + bv.x, 0.01f),
                            lrelu(acc[mt][nt][1] * sv.y + bv.y, 0.01f)));
            __half2 h1 = __float22half2_rn(
                make_float2(lrelu(acc[mt][nt][2] * sv.x + bv.x, 0.01f),
                            lrelu(acc[mt][nt][3] * sv.y + bv.y, 0.01f)));
            uint32_t d0 = lr0 * 128 + (((col >> 3) ^ (lr0 & 7)) << 4) + ((col * 2) & 15);
            uint32_t d1 = lr1 * 128 + (((col >> 3) ^ (lr1 & 7)) << 4) + ((col * 2) & 15);
            *(__half2*)(smB + d0) = h0;
            *(__half2*)(smB + d1) = h1;
        }
    __syncthreads();

    float acc2[2][4][4] = {};
    mma_tile_64(b_s, w2_s, lane, wm, wn, acc2);

#pragma unroll
    for (int mt = 0; mt < 2; mt++)
#pragma unroll
        for (int nt = 0; nt < 4; nt++) {
            int col = wn + nt * 8 + qc * 2;
            float2 sv = *(const float2*)&s2[col];
            float2 bv = *(const float2*)&b2[col];
            int r0 = m0 + wm + mt * 16 + qr;
            int r1 = r0 + 8;
            if (r0 < MP) *(__half2*)&outh[(size_t)r0 * 64 + col] = __float22half2_rn(
                make_float2(lrelu(acc2[mt][nt][0] * sv.x + bv.x, 0.01f),
                            lrelu(acc2[mt][nt][1] * sv.y + bv.y, 0.01f)));
            if (r1 < MP) *(__half2*)&outh[(size_t)r1 * 64 + col] = __float22half2_rn(
                make_float2(lrelu(acc2[mt][nt][2] * sv.x + bv.x, 0.01f),
                            lrelu(acc2[mt][nt][3] * sv.y + bv.y, 0.01f)));
        }
}

// ============ final 1x1: fp16 in, fp32 out with residual ======================
__global__ __launch_bounds__(256) void gemm64h_res_kernel(
    const __half* __restrict__ X, const __half* __restrict__ W,
    const float* __restrict__ s, const float* __restrict__ b,
    float* __restrict__ outf, const float* __restrict__ feats) {
    __shared__ __align__(16) char smA[16384];
    __shared__ __align__(16) char smW[8192];
    const uint32_t a_s = smem_u32(smA);
    const uint32_t w_s = smem_u32(smW);
    const int tid = threadIdx.x;
    const int lane = tid & 31, wid = tid >> 5;
    const int m0 = blockIdx.x * 128;

#pragma unroll
    for (int j = 0; j < 4; j++) {
        int f = tid + j * 256;
        int r = f >> 3, c = f & 7;
        uint32_t dst = a_s + r * 128 + ((c ^ (r & 7)) << 4);
        if (m0 + r < MP) CP16(dst, X + (size_t)(m0 + r) * 64 + c * 8);
        else STS_ZERO(dst);
    }
#pragma unroll
    for (int j = 0; j < 2; j++) {
        int f = tid + j * 256;
        int r = f >> 3, c = f & 7;
        CP16(w_s + r * 128 + ((c ^ (r & 7)) << 4), W + (size_t)r * 64 + c * 8);
    }
    CP_COMMIT();
    CP_WAIT(0);
    __syncthreads();

    const int wm = (wid >> 1) * 32;
    const int wn = (wid & 1) * 32;
    float acc[2][4][4] = {};
    mma_tile_64(a_s, w_s, lane, wm, wn, acc);

    const int qr = lane >> 2, qc = lane & 3;
#pragma unroll
    for (int mt = 0; mt < 2; mt++)
#pragma unroll
        for (int nt = 0; nt < 4; nt++) {
            int col = wn + nt * 8 + qc * 2;
            float2 sv = *(const float2*)&s[col];
            float2 bv = *(const float2*)&b[col];
            int r0 = m0 + wm + mt * 16 + qr;
            int r1 = r0 + 8;
            if (r0 < MP) {
                float2 fr = *(const float2*)&feats[(size_t)r0 * 64 + col];
                *(float2*)&outf[(size_t)r0 * 64 + col] = make_float2(
                    lrelu(lrelu(acc[mt][nt][0] * sv.x + bv.x, 0.01f) + fr.x, 0.1f),
                    lrelu(lrelu(acc[mt][nt][1] * sv.y + bv.y, 0.01f) + fr.y, 0.1f));
            }
            if (r1 < MP) {
                float2 fr = *(const float2*)&feats[(size_t)r1 * 64 + col];
                *(float2*)&outf[(size_t)r1 * 64 + col] = make_float2(
                    lrelu(lrelu(acc[mt][nt][2] * sv.x + bv.x, 0.01f) + fr.x, 0.1f),
                    lrelu(lrelu(acc[mt][nt][3] * sv.y + bv.y, 0.01f) + fr.y, 0.1f));
            }
        }
}

// ====== conv 27-tap, M-tile 128, 2 CTA/SM, warp = 16 rows x ALL 64 cols =======
// A read ONCE per tap per CTA; W fragments double-buffered in registers
// (prefetch issued before the barrier / previous kb's MMAs hide LDG latency).
// smem: nidxT[27][128] int (13824 -> 14336) | A stages 16KB x3 = 63488 bytes
#define CV_A(st) (14336 + (st) * 16384)
#define CV_TOT   63488

__device__ __forceinline__ void cv_fillA(uint32_t sb, int stage, int k,
                                         const int* __restrict__ nidxT,
                                         const __half* __restrict__ H, int tid) {
    uint32_t a_s = sb + CV_A(stage);
#pragma unroll
    for (int j = 0; j < 4; j++) {
        int t = tid + j * 256;
        int r = t >> 3, c = t & 7;
        int row = nidxT[k * 128 + r];
        uint32_t dst = a_s + r * 128 + ((c ^ (r & 7)) << 4);
        if (row >= 0) CP16(dst, H + (size_t)row * 64 + c * 8);
        else STS_ZERO(dst);
    }
}

__global__ __launch_bounds__(256, 2) void conv27_mma_kernel(
    const __half* __restrict__ H, const int* __restrict__ nbr,
    const uint4* __restrict__ Wf,
    const float* __restrict__ s, const float* __restrict__ b,
    __half* __restrict__ out) {
    extern __shared__ char smc[];
    const uint32_t sb = smem_u32(smc);
    const int tid = threadIdx.x;
    const int lane = tid & 31, wid = tid >> 5;
    const int m0 = blockIdx.x * 128;
    int* nidxT = (int*)smc;
    for (int t = tid; t < 27 * 128; t += 256) {
        int k = t >> 7, r = t & 127;
        int m = m0 + r;
        nidxT[t] = (m < MP) ? nbr[(size_t)m * 27 + k] : -1;
    }
    __syncthreads();

    cv_fillA(sb, 0, 0, nidxT, H, tid);
    CP_COMMIT();
    cv_fillA(sb, 1, 1, nidxT, H, tid);
    CP_COMMIT();

    const int wm = wid * 16;          // warp owns rows [wm, wm+16), all 64 cols
    float acc[8][4] = {};
    int stage = 0;

    for (int k = 0; k < 27; k++) {
        const uint4* wk = Wf + (size_t)k * 512 + lane;
        uint4 wbuf[2][4];
        // prefetch kb=0 W fragments; latency overlaps the cp.async wait + barrier
        wbuf[0][0] = wk[0];
        wbuf[0][1] = wk[32];
        wbuf[0][2] = wk[256];
        wbuf[0][3] = wk[288];

        if (k < 26) CP_WAIT(1);
        else        CP_WAIT(0);
        __syncthreads();
        if (k < 25) {
            int ns = stage + 2;
            if (ns >= 3) ns -= 3;
            cv_fillA(sb, ns, k + 2, nidxT, H, tid);
            CP_COMMIT();
        }
        uint32_t a_s = sb + CV_A(stage);
#pragma unroll
        for (int kb = 0; kb < 4; kb++) {
            int cur = kb & 1;
            if (kb < 3) {
                int nkb = kb + 1;
                wbuf[cur ^ 1][0] = wk[nkb * 64];
                wbuf[cur ^ 1][1] = wk[nkb * 64 + 32];
                wbuf[cur ^ 1][2] = wk[256 + nkb * 64];
                wbuf[cur ^ 1][3] = wk[256 + nkb * 64 + 32];
            }
            uint32_t a[4];
            {
                int r = wm + (lane & 15);
                int lc = kb * 2 + (lane >> 4);
                ldm4(a, a_s + r * 128 + ((lc ^ (r & 7)) << 4));
            }
            mma16816(acc[0], a, wbuf[cur][0].x, wbuf[cur][0].y);
            mma16816(acc[1], a, wbuf[cur][0].z, wbuf[cur][0].w);
            mma16816(acc[2], a, wbuf[cur][1].x, wbuf[cur][1].y);
            mma16816(acc[3], a, wbuf[cur][1].z, wbuf[cur][1].w);
            mma16816(acc[4], a, wbuf[cur][2].x, wbuf[cur][2].y);
            mma16816(acc[5], a, wbuf[cur][2].z, wbuf[cur][2].w);
            mma16816(acc[6], a, wbuf[cur][3].x, wbuf[cur][3].y);
            mma16816(acc[7], a, wbuf[cur][3].z, wbuf[cur][3].w);
        }
        if (++stage == 3) stage = 0;
    }

    const int qr = lane >> 2, qc = lane & 3;
#pragma unroll
    for (int ntg = 0; ntg < 8; ntg++) {
        int col = ntg * 8 + qc * 2;
        float2 s2 = *(const float2*)&s[col];
        float2 b2 = *(const float2*)&b[col];
        int r0 = m0 + wm + qr;
        int r1 = r0 + 8;
        if (r0 < MP) *(__half2*)&out[(size_t)r0 * 64 + col] = __float22half2_rn(
            make_float2(lrelu(acc[ntg][0] * s2.x + b2.x, 0.01f),
                        lrelu(acc[ntg][1] * s2.y + b2.y, 0.01f)));
        if (r1 < MP) *(__half2*)&out[(size_t)r1 * 64 + col] = __float22half2_rn(
            make_float2(lrelu(acc[ntg][2] * s2.x + b2.x, 0.01f),
                        lrelu(acc[ntg][3] * s2.y + b2.y, 0.01f)));
    }
}

// =================== batched scatter-mean over all 4 scales ===================
__global__ void zero_all_kernel(float* __restrict__ vsum4, float* __restrict__ vcnt4) {
    int gid = blockIdx.x * 256 + threadIdx.x;
    if (gid < 4 * MP * 16) ((float4*)vsum4)[gid] = make_float4(0.f, 0.f, 0.f, 0.f);
    if (gid < 4 * MP) vcnt4[gid] = 0.f;
}

__global__ void scatter_all_kernel(const float* __restrict__ V, const int* __restrict__ inv,
                                   float* __restrict__ vsum4, float* __restrict__ vcnt4) {
    int gid = blockIdx.x * 256 + threadIdx.x;
    if (gid >= 4 * MP * 64) return;
    int si = gid / (MP * 64);
    int rem = gid - si * (MP * 64);
    int m = rem >> 6, c = rem & 63;
    int sg = inv[si * MP + m];
    atomicAdd(&vsum4[(size_t)si * MP * 64 + sg * 64 + c], V[rem]);
    if (c == 0) atomicAdd(&vcnt4[si * MP + sg], 1.0f);
}

// ============ tensorized proj: Os=(V-mean)*V (fp16) @ proj_w, grid (GTC,4) ====
__global__ __launch_bounds__(256) void proj_mma_kernel(
    const float* __restrict__ V, const int* __restrict__ inv,
    const float* __restrict__ vsum4, const float* __restrict__ vcnt4,
    const __half* __restrict__ Wp, const float* __restrict__ pb,
    const float* __restrict__ ps, const float* __restrict__ pbb,
    float* __restrict__ ms) {
    __shared__ __align__(16) char smA[16384];
    __shared__ __align__(16) char smW[8192];
    const uint32_t a_s = smem_u32(smA);
    const uint32_t w_s = smem_u32(smW);
    const int tid = threadIdx.x;
    const int lane = tid & 31, wid = tid >> 5;
    const int m0 = blockIdx.x * 128;
    const int si = blockIdx.y;
    const int* seg = inv + (size_t)si * MP;
    const float* vsum = vsum4 + (size_t)si * MP * 64;
    const float* vcnt = vcnt4 + (size_t)si * MP;
    float* msO = ms + (size_t)si * MP * 64;

#pragma unroll
    for (int j = 0; j < 2; j++) {
        int f = tid + j * 256;
        int r = f >> 3, c = f & 7;
        CP16(w_s + r * 128 + ((c ^ (r & 7)) << 4),
             Wp + (size_t)si * 4096 + r * 64 + c * 8);
    }
    CP_COMMIT();
#pragma unroll
    for (int j = 0; j < 4; j++) {
        int f = tid + j * 256;
        int r = f >> 3, c = f & 7;
        uint32_t dst = a_s + r * 128 + ((c ^ (r & 7)) << 4);
        int m = m0 + r;
        if (m < MP) {
            int sg = seg[m];
            float rc = 1.0f / fmaxf(vcnt[sg], 1.0f);
            float4 v0 = *(const float4*)&V[(size_t)m * 64 + c * 8];
            float4 v1 = *(const float4*)&V[(size_t)m * 64 + c * 8 + 4];
            float4 u0 = *(const float4*)&vsum[(size_t)sg * 64 + c * 8];
            float4 u1 = *(const float4*)&vsum[(size_t)sg * 64 + c * 8 + 4];
            __half2 h0 = __float22half2_rn(make_float2((v0.x - u0.x * rc) * v0.x,
                                                       (v0.y - u0.y * rc) * v0.y));
            __half2 h1 = __float22half2_rn(make_float2((v0.z - u0.z * rc) * v0.z,
                                                       (v0.w - u0.w * rc) * v0.w));
            __half2 h2 = __float22half2_rn(make_float2((v1.x - u1.x * rc) * v1.x,
                                                       (v1.y - u1.y * rc) * v1.y));
            __half2 h3 = __float22half2_rn(make_float2((v1.z - u1.z * rc) * v1.z,
                                                       (v1.w - u1.w * rc) * v1.w));
            uint32_t q0 = *(uint32_t*)&h0, q1 = *(uint32_t*)&h1;
            uint32_t q2 = *(uint32_t*)&h2, q3 = *(uint32_t*)&h3;
            asm volatile("st.shared.v4.b32 [%0], {%1,%2,%3,%4};"
                         :: "r"(dst), "r"(q0), "r"(q1), "r"(q2), "r"(q3));
        } else {
            STS_ZERO(dst);
        }
    }
    CP_WAIT(0);
    __syncthreads();

    const int wm = (wid >> 1) * 32;
    const int wn = (wid & 1) * 32;
    float acc[2][4][4] = {};
    mma_tile_64(a_s, w_s, lane, wm, wn, acc);

    const int qr = lane >> 2, qc = lane & 3;
#pragma unroll
    for (int mt = 0; mt < 2; mt++)
#pragma unroll
        for (int nt = 0; nt < 4; nt++) {
            int col = wn + nt * 8 + qc * 2;
            float2 bv = *(const float2*)&pb[si * 64 + col];
            float2 sv = *(const float2*)&ps[si * 64 + col];
            float2 b2 = *(const float2*)&pbb[si * 64 + col];
            int r0 = m0 + wm + mt * 16 + qr;
            int r1 = r0 + 8;
            if (r0 < MP) *(float2*)&msO[(size_t)r0 * 64 + col] = make_float2(
                lrelu((acc[mt][nt][0] + bv.x) * sv.x + b2.x, 0.01f),
                lrelu((acc[mt][nt][1] + bv.y) * sv.y + b2.y, 0.01f));
            if (r1 < MP) *(float2*)&msO[(size_t)r1 * 64 + col] = make_float2(
                lrelu((acc[mt][nt][2] + bv.x) * sv.x + b2.x, 0.01f),
                lrelu((acc[mt][nt][3] + bv.y) * sv.y + b2.y, 0.01f));
        }
}

// ===== tensorized attn: sumx built in-kernel (fp16), 4 GEMMs, fused output ====
__global__ __launch_bounds__(256) void attn_mma_kernel(
    const float* __restrict__ ms, const __half* __restrict__ Wa,
    const float* __restrict__ ab, const float* __restrict__ as_,
    const float* __restrict__ abb, float* __restrict__ fused) {
    __shared__ __align__(16) char smA[16384];
    __shared__ __align__(16) char smW[8192];
    const uint32_t a_s = smem_u32(smA);
    const uint32_t w_s = smem_u32(smW);
    const int tid = threadIdx.x;
    const int lane = tid & 31, wid = tid >> 5;
    const int m0 = blockIdx.x * 128;

#pragma unroll
    for (int j = 0; j < 4; j++) {
        int f = tid + j * 256;
        int r = f >> 3, c = f & 7;
        uint32_t dst = a_s + r * 128 + ((c ^ (r & 7)) << 4);
        int m = m0 + r;
        if (m < MP) {
            float sx[8] = {};
#pragma unroll
            for (int i = 0; i < 4; i++) {
                float4 v0 = *(const float4*)&ms[((size_t)i * MP + m) * 64 + c * 8];
                float4 v1 = *(const float4*)&ms[((size_t)i * MP + m) * 64 + c * 8 + 4];
                sx[0] += v0.x; sx[1] += v0.y; sx[2] += v0.z; sx[3] += v0.w;
                sx[4] += v1.x; sx[5] += v1.y; sx[6] += v1.z; sx[7] += v1.w;
            }
            __half2 h0 = __float22half2_rn(make_float2(sx[0], sx[1]));
            __half2 h1 = __float22half2_rn(make_float2(sx[2], sx[3]));
            __half2 h2 = __float22half2_rn(make_float2(sx[4], sx[5]));
            __half2 h3 = __float22half2_rn(make_float2(sx[6], sx[7]));
            uint32_t q0 = *(uint32_t*)&h0, q1 = *(uint32_t*)&h1;
            uint32_t q2 = *(uint32_t*)&h2, q3 = *(uint32_t*)&h3;
            asm volatile("st.shared.v4.b32 [%0], {%1,%2,%3,%4};"
                         :: "r"(dst), "r"(q0), "r"(q1), "r"(q2), "r"(q3));
        } else {
            STS_ZERO(dst);
        }
    }

    const int wm = (wid >> 1) * 32;
    const int wn = (wid & 1) * 32;
    const int qr = lane >> 2, qc = lane & 3;
    float fac[2][4][4] = {};

    for (int i = 0; i < 4; i++) {
        __syncthreads();
#pragma unroll
        for (int j = 0; j < 2; j++) {
            int f = tid + j * 256;
            int r = f >> 3, c = f & 7;
            CP16(w_s + r * 128 + ((c ^ (r & 7)) << 4),
                 Wa + (size_t)i * 4096 + r * 64 + c * 8);
        }
        CP_COMMIT();
        CP_WAIT(0);
        __syncthreads();

        float acc[2][4][4] = {};
        mma_tile_64(a_s, w_s, lane, wm, wn, acc);

#pragma unroll
        for (int mt = 0; mt < 2; mt++)
#pragma unroll
            for (int nt = 0; nt < 4; nt++) {
                int col = wn + nt * 8 + qc * 2;
                float2 bv = *(const float2*)&ab[i * 64 + col];
                float2 sv = *(const float2*)&as_[i * 64 + col];
                float2 b2 = *(const float2*)&abb[i * 64 + col];
                int r0 = m0 + wm + mt * 16 + qr;
                int r1 = r0 + 8;
                if (r0 < MP) {
                    float2 mv = *(const float2*)&ms[((size_t)i * MP + r0) * 64 + col];
                    float a0 = 1.0f / (1.0f + __expf(-((acc[mt][nt][0] + bv.x) * sv.x + b2.x)));
                    float a1 = 1.0f / (1.0f + __expf(-((acc[mt][nt][1] + bv.y) * sv.y + b2.y)));
                    fac[mt][nt][0] += a0 * mv.x;
                    fac[mt][nt][1] += a1 * mv.y;
                }
                if (r1 < MP) {
                    float2 mv = *(const float2*)&ms[((size_t)i * MP + r1) * 64 + col];
                    float a2 = 1.0f / (1.0f + __expf(-((acc[mt][nt][2] + bv.x) * sv.x + b2.x)));
                    float a3 = 1.0f / (1.0f + __expf(-((acc[mt][nt][3] + bv.y) * sv.y + b2.y)));
                    fac[mt][nt][2] += a2 * mv.x;
                    fac[mt][nt][3] += a3 * mv.y;
                }
            }
    }

#pragma unroll
    for (int mt = 0; mt < 2; mt++)
#pragma unroll
        for (int nt = 0; nt < 4; nt++) {
            int col = wn + nt * 8 + qc * 2;
            int r0 = m0 + wm + mt * 16 + qr;
            int r1 = r0 + 8;
            if (r0 < MP) *(float2*)&fused[(size_t)r0 * 64 + col] =
                make_float2(fac[mt][nt][0], fac[mt][nt][1]);
            if (r1 < MP) *(float2*)&fused[(size_t)r1 * 64 + col] =
                make_float2(fac[mt][nt][2], fac[mt][nt][3]);
        }
}

// ================================ N=20 heads ==================================
__global__ __launch_bounds__(256) void gemm_n20_kernel(
    const float* __restrict__ X, const float* __restrict__ W,
    const float* __restrict__ b, float* __restrict__ out) {
    __shared__ float Xs[128 * 68];
    __shared__ float Ws[64 * 20];
    __shared__ float bs[20];
    const int tid = threadIdx.x;
    const int m0 = blockIdx.x * 128;
#pragma unroll
    for (int j = 0; j < 8; j++) {
        int f = tid + 256 * j;
        int r = f >> 4, c4 = f & 15;
        int m = m0 + r;
        float4 v = make_float4(0.f, 0.f, 0.f, 0.f);
        if (m < MP) v = *(const float4*)&X[(size_t)m * 64 + c4 * 4];
        *(float4*)&Xs[r * 68 + c4 * 4] = v;
    }
    for (int f = tid; f < 64 * 20; f += 256) Ws[f] = W[f];
    if (tid < 20) bs[tid] = b[tid];
    __syncthreads();
    int r = tid >> 1, half = tid & 1, n0 = half * 10;
    int m = m0 + r;
    if (m < MP) {
        float acc[10];
#pragma unroll
        for (int j = 0; j < 10; j++) acc[j] = bs[n0 + j];
#pragma unroll 8
        for (int c = 0; c < 64; c++) {
            float x = Xs[r * 68 + c];
#pragma unroll
            for (int j = 0; j < 10; j++) acc[j] += x * Ws[c * 20 + n0 + j];
        }
#pragma unroll
        for (int j = 0; j < 10; j++) out[(size_t)m * 20 + n0 + j] = acc[j];
    }
}

// ==============================================================================
extern "C" void kernel_launch(void* const* d_in, const int* in_sizes, int n_in,
                              void* d_out, int out_size) {
    const float* feats   = (const float*)d_in[0];
    const float* w1a     = (const float*)d_in[1];
    const float* s1a     = (const float*)d_in[2];
    const float* b1a     = (const float*)d_in[3];
    const float* w3      = (const float*)d_in[4];
    const float* s3      = (const float*)d_in[5];
    const float* b3      = (const float*)d_in[6];
    const float* w1b     = (const float*)d_in[7];
    const float* s1b     = (const float*)d_in[8];
    const float* b1b     = (const float*)d_in[9];
    const float* aux_w   = (const float*)d_in[10];
    const float* aux_b   = (const float*)d_in[11];
    const float* proj_w  = (const float*)d_in[12];
    const float* proj_b  = (const float*)d_in[13];
    const float* proj_s  = (const float*)d_in[14];
    const float* proj_bb = (const float*)d_in[15];
    const float* attn_w  = (const float*)d_in[16];
    const float* attn_b  = (const float*)d_in[17];
    const float* attn_s  = (const float*)d_in[18];
    const float* attn_bb = (const float*)d_in[19];
    const float* head_w  = (const float*)d_in[20];
    const float* head_b  = (const float*)d_in[21];
    const int*   nbr     = (const int*)d_in[22];
    const int*   inv     = (const int*)d_in[23];

    float* out    = (float*)d_out;
    float* fused  = out;
    float* logits = out + (size_t)MP * 64;
    float* aux    = out + (size_t)MP * 84;

    float *pV, *pms, *pvs, *pvc;
    __half *pH16, *pB16, *pW1a, *pW1b, *pWp, *pWa;
    uint4 *pWf;
    cudaGetSymbolAddress((void**)&pV, g_V);
    cudaGetSymbolAddress((void**)&pms, g_ms);
    cudaGetSymbolAddress((void**)&pvs, g_vsum4);
    cudaGetSymbolAddress((void**)&pvc, g_vcnt4);
    cudaGetSymbolAddress((void**)&pH16, g_H16);
    cudaGetSymbolAddress((void**)&pB16, g_B16);
    cudaGetSymbolAddress((void**)&pW1a, g_W1a16);
    cudaGetSymbolAddress((void**)&pW1b, g_W1b16);
    cudaGetSymbolAddress((void**)&pWp, g_Wp16);
    cudaGetSymbolAddress((void**)&pWa, g_Wa16);
    cudaGetSymbolAddress((void**)&pWf, g_Wf);

    cudaFuncSetAttribute(conv27_mma_kernel, cudaFuncAttributeMaxDynamicSharedMemorySize, CV_TOT);

    wprep_kernel<<<(16 * 4096 + 255) / 256, 256>>>(w1a, w1b, proj_w, attn_w,
                                                   pW1a, pW1b, pWp, pWa);
    wfrag_kernel<<<216, 256>>>(w3, pWf);

    gemm64hf_kernel<<<GTC, 256>>>(feats, pW1a, s1a, b1a, pH16);
    for (int i = 0; i < 4; i++) {
        conv27_mma_kernel<<<GTC, 256, CV_TOT>>>(pH16, nbr, pWf + (size_t)i * 27 * 512,
                                                s3 + i * 64, b3 + i * 64, pB16);
        if (i < 3) {
            gemm64h2_kernel<<<GTC, 256>>>(pB16,
                                          pW1b + (size_t)i * 4096, s1b + i * 64, b1b + i * 64,
                                          pW1a + (size_t)(i + 1) * 4096, s1a + (i + 1) * 64,
                                          b1a + (i + 1) * 64, pH16);
        } else {
            gemm64h_res_kernel<<<GTC, 256>>>(pB16, pW1b + (size_t)i * 4096, s1b + i * 64,
                                             b1b + i * 64, pV, feats);
        }
    }

    gemm_n20_kernel<<<938, 256>>>(pV, aux_w, aux_b, aux);

    zero_all_kernel<<<30000, 256>>>(pvs, pvc);
    scatter_all_kernel<<<120000, 256>>>(pV, inv, pvs, pvc);
    {
        dim3 grid(GTC, 4);
        proj_mma_kernel<<<grid, 256>>>(pV, inv, pvs, pvc, pWp,
                                       proj_b, proj_s, proj_bb, pms);
    }
    attn_mma_kernel<<<GTC, 256>>>(pms, pWa, attn_b, attn_s, attn_bb, fused);
    gemm_n20_kernel<<<938, 256>>>(fused, head_w, head_b, logits);
}

// round 11
// speedup vs baseline: 1.5610x; 1.5247x over previous
#include <cuda_runtime.h>
#include <cuda_fp16.h>
#include <math.h>
#include <stdint.h>

#define MP 120000
#define GTC 938     // ceil(MP / 128)

// ---------------- scratch (static device globals; no runtime allocs) ----------
__device__ float  g_V[MP * 64];
__device__ __half g_H16[MP * 64];
__device__ float  g_acc[MP * 64];        // conv fp32 accumulator
__device__ __half g_W1a16[4 * 4096];
__device__ __half g_W1b16[4 * 4096];
__device__ __half g_Wp16[4 * 4096];
__device__ __half g_Wa16[4 * 4096];
__device__ __half g_W13t[4 * 4096];      // tap-13 weights transposed [d][c] fp16
__device__ __half g_W3n[4 * 27 * 4096];  // conv weights original [c][d] fp16
__device__ int2   g_ent[26 * MP];        // valid (m, src) pairs per non-self tap
__device__ int    g_ecnt[26];
__device__ float  g_ms[4 * MP * 64];
__device__ float  g_vsum4[4 * MP * 64];
__device__ float  g_vcnt4[4 * MP];

__device__ __forceinline__ float lrelu(float x, float a) { return x > 0.f ? x : a * x; }

__device__ __forceinline__ uint32_t smem_u32(const void* p) {
    uint32_t a;
    asm("{ .reg .u64 t; cvta.to.shared.u64 t, %1; cvt.u32.u64 %0, t; }" : "=r"(a) : "l"(p));
    return a;
}

__device__ __forceinline__ void ldm4(uint32_t r[4], uint32_t addr) {
    asm volatile("ldmatrix.sync.aligned.m8n8.x4.shared.b16 {%0,%1,%2,%3}, [%4];"
                 : "=r"(r[0]), "=r"(r[1]), "=r"(r[2]), "=r"(r[3]) : "r"(addr));
}

__device__ __forceinline__ void mma16816(float c[4], const uint32_t a[4],
                                         uint32_t b0, uint32_t b1) {
    asm volatile(
        "mma.sync.aligned.m16n8k16.row.col.f32.f16.f16.f32 "
        "{%0,%1,%2,%3},{%4,%5,%6,%7},{%8,%9},{%0,%1,%2,%3};"
        : "+f"(c[0]), "+f"(c[1]), "+f"(c[2]), "+f"(c[3])
        : "r"(a[0]), "r"(a[1]), "r"(a[2]), "r"(a[3]), "r"(b0), "r"(b1));
}

#define CP16(dst, src) \
    asm volatile("cp.async.cg.shared.global [%0], [%1], 16;" :: "r"(dst), "l"(src))
#define CP_COMMIT() asm volatile("cp.async.commit_group;" ::: "memory")
#define CP_WAIT(n)  asm volatile("cp.async.wait_group %0;" :: "n"(n) : "memory")
#define STS_ZERO(dst) do { uint32_t _z = 0; \
    asm volatile("st.shared.v4.b32 [%0], {%1,%1,%1,%1};" :: "r"(dst), "r"(_z)); } while (0)

// ========== MMA core (M-tile 128): A(128x64) x W(64x64)^T, 8 warps ============
__device__ __forceinline__ void mma_tile_64(uint32_t a_s, uint32_t w_s,
                                            int lane, int wm, int wn,
                                            float acc[2][4][4]) {
#pragma unroll
    for (int kb = 0; kb < 4; kb++) {
        uint32_t a[2][4], wh[2][4];
#pragma unroll
        for (int mt = 0; mt < 2; mt++) {
            int r = wm + mt * 16 + (lane & 15);
            int lc = kb * 2 + (lane >> 4);
            ldm4(a[mt], a_s + r * 128 + ((lc ^ (r & 7)) << 4));
        }
#pragma unroll
        for (int np = 0; np < 2; np++) {
            int r = wn + np * 16 + (lane & 7) + ((lane & 16) ? 8 : 0);
            int lc = kb * 2 + ((lane >> 3) & 1);
            ldm4(wh[np], w_s + r * 128 + ((lc ^ (r & 7)) << 4));
        }
#pragma unroll
        for (int mt = 0; mt < 2; mt++)
#pragma unroll
            for (int nt = 0; nt < 4; nt++) {
                int np = nt >> 1, q = (nt & 1) * 2;
                mma16816(acc[mt][nt], a[mt], wh[np][q], wh[np][q + 1]);
            }
    }
}

// ====== weight prep: transpose+fp16 for 1x1/proj/attn/W13t; zero ecnt =========
__global__ void wprep_kernel(const float* __restrict__ w1a, const float* __restrict__ w1b,
                             const float* __restrict__ wp, const float* __restrict__ wa,
                             const float* __restrict__ w3,
                             __half* __restrict__ o1a, __half* __restrict__ o1b,
                             __half* __restrict__ op, __half* __restrict__ oa,
                             __half* __restrict__ o13, int* __restrict__ ecnt) {
    int g = blockIdx.x * 256 + threadIdx.x;
    if (g < 26) ecnt[g] = 0;
    if (g >= 20 * 4096) return;
    int t = g >> 12;
    int rc = g & 4095;
    int d = rc >> 6, c = rc & 63;
    if (t < 4)
        o1a[(size_t)t * 4096 + d * 64 + c] = __float2half_rn(w1a[(size_t)t * 4096 + c * 64 + d]);
    else if (t < 8)
        o1b[(size_t)(t - 4) * 4096 + d * 64 + c] = __float2half_rn(w1b[(size_t)(t - 4) * 4096 + c * 64 + d]);
    else if (t < 12)
        op[(size_t)(t - 8) * 4096 + d * 64 + c] = __float2half_rn(wp[(size_t)(t - 8) * 4096 + c * 64 + d]);
    else if (t < 16)
        oa[(size_t)(t - 12) * 4096 + d * 64 + c] = __float2half_rn(wa[(size_t)(t - 12) * 4096 + c * 64 + d]);
    else {
        int lt = t - 16;
        o13[(size_t)lt * 4096 + d * 64 + c] =
            __float2half_rn(w3[((size_t)lt * 27 + 13) * 4096 + c * 64 + d]);
    }
}

__global__ void w3n_kernel(const float* __restrict__ w3, __half* __restrict__ o) {
    int g = blockIdx.x * 256 + threadIdx.x;
    if (g >= 4 * 27 * 4096) return;
    o[g] = __float2half_rn(w3[g]);
}

__global__ void entprep_kernel(const int* __restrict__ nbr,
                               int2* __restrict__ ent, int* __restrict__ ecnt) {
    int m = blockIdx.x * 256 + threadIdx.x;
    if (m >= MP) return;
#pragma unroll
    for (int k = 0; k < 27; k++) {
        if (k == 13) continue;
        int src = nbr[(size_t)m * 27 + k];
        if (src >= 0) {
            int idx = (k < 13) ? k : k - 1;
            int pos = atomicAdd(&ecnt[idx], 1);
            ent[(size_t)idx * MP + pos] = make_int2(m, src);
        }
    }
}

// ============= first-layer GEMM: fp32 input, fp16 out  =======================
__global__ __launch_bounds__(256) void gemm64hf_kernel(
    const float* __restrict__ Xf, const __half* __restrict__ W,
    const float* __restrict__ s, const float* __restrict__ b,
    __half* __restrict__ outh) {
    __shared__ __align__(16) char smA[16384];
    __shared__ __align__(16) char smW[8192];
    const uint32_t a_s = smem_u32(smA);
    const uint32_t w_s = smem_u32(smW);
    const int tid = threadIdx.x;
    const int lane = tid & 31, wid = tid >> 5;
    const int m0 = blockIdx.x * 128;

#pragma unroll
    for (int j = 0; j < 2; j++) {
        int f = tid + j * 256;
        int r = f >> 3, c = f & 7;
        CP16(w_s + r * 128 + ((c ^ (r & 7)) << 4), W + (size_t)r * 64 + c * 8);
    }
    CP_COMMIT();
#pragma unroll
    for (int j = 0; j < 4; j++) {
        int f = tid + j * 256;
        int r = f >> 3, c = f & 7;
        uint32_t dst = a_s + r * 128 + ((c ^ (r & 7)) << 4);
        int m = m0 + r;
        if (m < MP) {
            float4 v0 = *(const float4*)&Xf[(size_t)m * 64 + c * 8];
            float4 v1 = *(const float4*)&Xf[(size_t)m * 64 + c * 8 + 4];
            __half2 h0 = __float22half2_rn(make_float2(v0.x, v0.y));
            __half2 h1 = __float22half2_rn(make_float2(v0.z, v0.w));
            __half2 h2 = __float22half2_rn(make_float2(v1.x, v1.y));
            __half2 h3 = __float22half2_rn(make_float2(v1.z, v1.w));
            uint32_t q0 = *(uint32_t*)&h0, q1 = *(uint32_t*)&h1;
            uint32_t q2 = *(uint32_t*)&h2, q3 = *(uint32_t*)&h3;
            asm volatile("st.shared.v4.b32 [%0], {%1,%2,%3,%4};"
                         :: "r"(dst), "r"(q0), "r"(q1), "r"(q2), "r"(q3));
        } else {
            STS_ZERO(dst);
        }
    }
    CP_WAIT(0);
    __syncthreads();

    const int wm = (wid >> 1) * 32;
    const int wn = (wid & 1) * 32;
    float acc[2][4][4] = {};
    mma_tile_64(a_s, w_s, lane, wm, wn, acc);

    const int qr = lane >> 2, qc = lane & 3;
#pragma unroll
    for (int mt = 0; mt < 2; mt++)
#pragma unroll
        for (int nt = 0; nt < 4; nt++) {
            int col = wn + nt * 8 + qc * 2;
            float2 s2 = *(const float2*)&s[col];
            float2 b2 = *(const float2*)&b[col];
            int r0 = m0 + wm + mt * 16 + qr;
            int r1 = r0 + 8;
            if (r0 < MP) *(__half2*)&outh[(size_t)r0 * 64 + col] = __float22half2_rn(
                make_float2(lrelu(acc[mt][nt][0] * s2.x + b2.x, 0.01f),
                            lrelu(acc[mt][nt][1] * s2.y + b2.y, 0.01f)));
            if (r1 < MP) *(__half2*)&outh[(size_t)r1 * 64 + col] = __float22half2_rn(
                make_float2(lrelu(acc[mt][nt][2] * s2.x + b2.x, 0.01f),
                            lrelu(acc[mt][nt][3] * s2.y + b2.y, 0.01f)));
        }
}

// ============ self-tap GEMM: acc = H16 @ W13t (raw fp32 out) ==================
__global__ __launch_bounds__(256) void gemm_self_kernel(
    const __half* __restrict__ X, const __half* __restrict__ W,
    float* __restrict__ acco) {
    __shared__ __align__(16) char smA[16384];
    __shared__ __align__(16) char smW[8192];
    const uint32_t a_s = smem_u32(smA);
    const uint32_t w_s = smem_u32(smW);
    const int tid = threadIdx.x;
    const int lane = tid & 31, wid = tid >> 5;
    const int m0 = blockIdx.x * 128;

#pragma unroll
    for (int j = 0; j < 4; j++) {
        int f = tid + j * 256;
        int r = f >> 3, c = f & 7;
        uint32_t dst = a_s + r * 128 + ((c ^ (r & 7)) << 4);
        if (m0 + r < MP) CP16(dst, X + (size_t)(m0 + r) * 64 + c * 8);
        else STS_ZERO(dst);
    }
#pragma unroll
    for (int j = 0; j < 2; j++) {
        int f = tid + j * 256;
        int r = f >> 3, c = f & 7;
        CP16(w_s + r * 128 + ((c ^ (r & 7)) << 4), W + (size_t)r * 64 + c * 8);
    }
    CP_COMMIT();
    CP_WAIT(0);
    __syncthreads();

    const int wm = (wid >> 1) * 32;
    const int wn = (wid & 1) * 32;
    float acc[2][4][4] = {};
    mma_tile_64(a_s, w_s, lane, wm, wn, acc);

    const int qr = lane >> 2, qc = lane & 3;
#pragma unroll
    for (int mt = 0; mt < 2; mt++)
#pragma unroll
        for (int nt = 0; nt < 4; nt++) {
            int col = wn + nt * 8 + qc * 2;
            int r0 = m0 + wm + mt * 16 + qr;
            int r1 = r0 + 8;
            if (r0 < MP) *(float2*)&acco[(size_t)r0 * 64 + col] =
                make_float2(acc[mt][nt][0], acc[mt][nt][1]);
            if (r1 < MP) *(float2*)&acco[(size_t)r1 * 64 + col] =
                make_float2(acc[mt][nt][2], acc[mt][nt][3]);
        }
}

// ======= sparse conv: acc[m] += H[src] @ W3[tap], entries per tap =============
__global__ __launch_bounds__(256) void sparse_conv_kernel(
    const __half* __restrict__ H, const __half* __restrict__ W3n,
    const int2* __restrict__ ent, const int* __restrict__ ecnt,
    float* __restrict__ acc) {
    const int kk = blockIdx.y;             // 0..25
    const int cnt = ecnt[kk];
    const int base = blockIdx.x * 64;
    if (base >= cnt) return;
    const int tap = (kk < 13) ? kk : kk + 1;

    __shared__ __align__(16) __half Ws[64 * 64];   // [c][j]
    __shared__ __align__(16) __half Hs[64][64];
    __shared__ int2 es[64];
    const int tid = threadIdx.x;

    const uint4* wsrc = (const uint4*)(W3n + (size_t)tap * 4096);
#pragma unroll
    for (int j = 0; j < 2; j++)
        ((uint4*)Ws)[tid + j * 256] = wsrc[tid + j * 256];
    if (tid < 64) {
        int e = base + tid;
        es[tid] = (e < cnt) ? ent[(size_t)kk * MP + e] : make_int2(-1, -1);
    }
    __syncthreads();
    {
        int e = tid >> 2, q = tid & 3;
        int src = es[e].y;
        if (src >= 0) {
            *(uint4*)&Hs[e][q * 8]      = *(const uint4*)&H[(size_t)src * 64 + q * 8];
            *(uint4*)&Hs[e][32 + q * 8] = *(const uint4*)&H[(size_t)src * 64 + 32 + q * 8];
        }
    }
    __syncthreads();

    const int wrp = tid >> 5, lane = tid & 31;
#pragma unroll
    for (int ei = 0; ei < 8; ei++) {
        int e = wrp * 8 + ei;
        int m = es[e].x;
        if (m < 0) continue;
        float v0 = 0.f, v1 = 0.f;
#pragma unroll
        for (int d = 0; d < 64; d++) {
            float h = __half2float(Hs[e][d]);
            float2 wf = __half22float2(*(const __half2*)&Ws[d * 64 + lane * 2]);
            v0 += h * wf.x;
            v1 += h * wf.y;
        }
        atomicAdd(&acc[(size_t)m * 64 + lane * 2], v0);
        atomicAdd(&acc[(size_t)m * 64 + lane * 2 + 1], v1);
    }
}

// === fused: conv-epilogue(acc,s3,b3) -> GEMM w1b -> epi -> GEMM w1a_next ======
__global__ __launch_bounds__(256) void gemm64h2f_kernel(
    const float* __restrict__ accin, const float* __restrict__ cs, const float* __restrict__ cb,
    const __half* __restrict__ W1, const float* __restrict__ s1, const float* __restrict__ b1,
    const __half* __restrict__ W2, const float* __restrict__ s2, const float* __restrict__ b2,
    __half* __restrict__ outh) {
    __shared__ __align__(16) char smA[16384];
    __shared__ __align__(16) char smB[16384];
    __shared__ __align__(16) char smW1[8192];
    __shared__ __align__(16) char smW2[8192];
    const uint32_t a_s = smem_u32(smA);
    const uint32_t b_s = smem_u32(smB);
    const uint32_t w1_s = smem_u32(smW1);
    const uint32_t w2_s = smem_u32(smW2);
    const int tid = threadIdx.x;
    const int lane = tid & 31, wid = tid >> 5;
    const int m0 = blockIdx.x * 128;

#pragma unroll
    for (int j = 0; j < 2; j++) {
        int f = tid + j * 256;
        int r = f >> 3, c = f & 7;
        CP16(w1_s + r * 128 + ((c ^ (r & 7)) << 4), W1 + (size_t)r * 64 + c * 8);
        CP16(w2_s + r * 128 + ((c ^ (r & 7)) << 4), W2 + (size_t)r * 64 + c * 8);
    }
    CP_COMMIT();
#pragma unroll
    for (int j = 0; j < 4; j++) {
        int f = tid + j * 256;
        int r = f >> 3, c = f & 7;
        uint32_t dst = a_s + r * 128 + ((c ^ (r & 7)) << 4);
        int m = m0 + r;
        if (m < MP) {
            float4 v0 = *(const float4*)&accin[(size_t)m * 64 + c * 8];
            float4 v1 = *(const float4*)&accin[(size_t)m * 64 + c * 8 + 4];
            float4 s0 = *(const float4*)&cs[c * 8];
            float4 s1v = *(const float4*)&cs[c * 8 + 4];
            float4 b0 = *(const float4*)&cb[c * 8];
            float4 b1v = *(const float4*)&cb[c * 8 + 4];
            __half2 h0 = __float22half2_rn(make_float2(lrelu(v0.x * s0.x + b0.x, 0.01f),
                                                       lrelu(v0.y * s0.y + b0.y, 0.01f)));
            __half2 h1 = __float22half2_rn(make_float2(lrelu(v0.z * s0.z + b0.z, 0.01f),
                                                       lrelu(v0.w * s0.w + b0.w, 0.01f)));
            __half2 h2 = __float22half2_rn(make_float2(lrelu(v1.x * s1v.x + b1v.x, 0.01f),
                                                       lrelu(v1.y * s1v.y + b1v.y, 0.01f)));
            __half2 h3 = __float22half2_rn(make_float2(lrelu(v1.z * s1v.z + b1v.z, 0.01f),
                                                       lrelu(v1.w * s1v.w + b1v.w, 0.01f)));
            uint32_t q0 = *(uint32_t*)&h0, q1 = *(uint32_t*)&h1;
            uint32_t q2 = *(uint32_t*)&h2, q3 = *(uint32_t*)&h3;
            asm volatile("st.shared.v4.b32 [%0], {%1,%2,%3,%4};"
                         :: "r"(dst), "r"(q0), "r"(q1), "r"(q2), "r"(q3));
        } else {
            STS_ZERO(dst);
        }
    }
    CP_WAIT(0);
    __syncthreads();

    const int wm = (wid >> 1) * 32;
    const int wn = (wid & 1) * 32;
    const int qr = lane >> 2, qc = lane & 3;

    float acc[2][4][4] = {};
    mma_tile_64(a_s, w1_s, lane, wm, wn, acc);

#pragma unroll
    for (int mt = 0; mt < 2; mt++)
#pragma unroll
        for (int nt = 0; nt < 4; nt++) {
            int col = wn + nt * 8 + qc * 2;
            float2 sv = *(const float2*)&s1[col];
            float2 bv = *(const float2*)&b1[col];
            int lr0 = wm + mt * 16 + qr;
            int lr1 = lr0 + 8;
            __half2 h0 = __float22half2_rn(
                make_float2(lrelu(acc[mt][nt][0] * sv.x + bv.x, 0.01f),
                            lrelu(acc[mt][nt][1] * sv.y + bv.y, 0.01f)));
            __half2 h1 = __float22half2_rn(
                make_float2(lrelu(acc[mt][nt][2] * sv.x + bv.x, 0.01f),
                            lrelu(acc[mt][nt][3] * sv.y + bv.y, 0.01f)));
            uint32_t d0 = lr0 * 128 + (((col >> 3) ^ (lr0 & 7)) << 4) + ((col * 2) & 15);
            uint32_t d1 = lr1 * 128 + (((col >> 3) ^ (lr1 & 7)) << 4) + ((col * 2) & 15);
            *(__half2*)(smB + d0) = h0;
            *(__half2*)(smB + d1) = h1;
        }
    __syncthreads();

    float acc2[2][4][4] = {};
    mma_tile_64(b_s, w2_s, lane, wm, wn, acc2);

#pragma unroll
    for (int mt = 0; mt < 2; mt++)
#pragma unroll
        for (int nt = 0; nt < 4; nt++) {
            int col = wn + nt * 8 + qc * 2;
            float2 sv = *(const float2*)&s2[col];
            float2 bv = *(const float2*)&b2[col];
            int r0 = m0 + wm + mt * 16 + qr;
            int r1 = r0 + 8;
            if (r0 < MP) *(__half2*)&outh[(size_t)r0 * 64 + col] = __float22half2_rn(
                make_float2(lrelu(acc2[mt][nt][0] * sv.x + bv.x, 0.01f),
                            lrelu(acc2[mt][nt][1] * sv.y + bv.y, 0.01f)));
            if (r1 < MP) *(__half2*)&outh[(size_t)r1 * 64 + col] = __float22half2_rn(
                make_float2(lrelu(acc2[mt][nt][2] * sv.x + bv.x, 0.01f),
                            lrelu(acc2[mt][nt][3] * sv.y + bv.y, 0.01f)));
        }
}

// === fused last: conv-epilogue(acc) -> GEMM w1b -> epi + residual -> V fp32 ===
__global__ __launch_bounds__(256) void gemm64h_resf_kernel(
    const float* __restrict__ accin, const float* __restrict__ cs, const float* __restrict__ cb,
    const __half* __restrict__ W, const float* __restrict__ s, const float* __restrict__ b,
    float* __restrict__ outf, const float* __restrict__ feats) {
    __shared__ __align__(16) char smA[16384];
    __shared__ __align__(16) char smW[8192];
    const uint32_t a_s = smem_u32(smA);
    const uint32_t w_s = smem_u32(smW);
    const int tid = threadIdx.x;
    const int lane = tid & 31, wid = tid >> 5;
    const int m0 = blockIdx.x * 128;

#pragma unroll
    for (int j = 0; j < 2; j++) {
        int f = tid + j * 256;
        int r = f >> 3, c = f & 7;
        CP16(w_s + r * 128 + ((c ^ (r & 7)) << 4), W + (size_t)r * 64 + c * 8);
    }
    CP_COMMIT();
#pragma unroll
    for (int j = 0; j < 4; j++) {
        int f = tid + j * 256;
        int r = f >> 3, c = f & 7;
        uint32_t dst = a_s + r * 128 + ((c ^ (r & 7)) << 4);
        int m = m0 + r;
        if (m < MP) {
            float4 v0 = *(const float4*)&accin[(size_t)m * 64 + c * 8];
            float4 v1 = *(const float4*)&accin[(size_t)m * 64 + c * 8 + 4];
            float4 s0 = *(const float4*)&cs[c * 8];
            float4 s1v = *(const float4*)&cs[c * 8 + 4];
            float4 b0 = *(const float4*)&cb[c * 8];
            float4 b1v = *(const float4*)&cb[c * 8 + 4];
            __half2 h0 = __float22half2_rn(make_float2(lrelu(v0.x * s0.x + b0.x, 0.01f),
                                                       lrelu(v0.y * s0.y + b0.y, 0.01f)));
            __half2 h1 = __float22half2_rn(make_float2(lrelu(v0.z * s0.z + b0.z, 0.01f),
                                                       lrelu(v0.w * s0.w + b0.w, 0.01f)));
            __half2 h2 = __float22half2_rn(make_float2(lrelu(v1.x * s1v.x + b1v.x, 0.01f),
                                                       lrelu(v1.y * s1v.y + b1v.y, 0.01f)));
            __half2 h3 = __float22half2_rn(make_float2(lrelu(v1.z * s1v.z + b1v.z, 0.01f),
                                                       lrelu(v1.w * s1v.w + b1v.w, 0.01f)));
            uint32_t q0 = *(uint32_t*)&h0, q1 = *(uint32_t*)&h1;
            uint32_t q2 = *(uint32_t*)&h2, q3 = *(uint32_t*)&h3;
            asm volatile("st.shared.v4.b32 [%0], {%1,%2,%3,%4};"
                         :: "r"(dst), "r"(q0), "r"(q1), "r"(q2), "r"(q3));
        } else {
            STS_ZERO(dst);
        }
    }
    CP_WAIT(0);
    __syncthreads();

    const int wm = (wid >> 1) * 32;
    const int wn = (wid & 1) * 32;
    float acc[2][4][4] = {};
    mma_tile_64(a_s, w_s, lane, wm, wn, acc);

    const int qr = lane >> 2, qc = lane & 3;
#pragma unroll
    for (int mt = 0; mt < 2; mt++)
#pragma unroll
        for (int nt = 0; nt < 4; nt++) {
            int col = wn + nt * 8 + qc * 2;
            float2 sv = *(const float2*)&s[col];
            float2 bv = *(const float2*)&b[col];
            int r0 = m0 + wm + mt * 16 + qr;
            int r1 = r0 + 8;
            if (r0 < MP) {
                float2 fr = *(const float2*)&feats[(size_t)r0 * 64 + col];
                *(float2*)&outf[(size_t)r0 * 64 + col] = make_float2(
                    lrelu(lrelu(acc[mt][nt][0] * sv.x + bv.x, 0.01f) + fr.x, 0.1f),
                    lrelu(lrelu(acc[mt][nt][1] * sv.y + bv.y, 0.01f) + fr.y, 0.1f));
            }
            if (r1 < MP) {
                float2 fr = *(const float2*)&feats[(size_t)r1 * 64 + col];
                *(float2*)&outf[(size_t)r1 * 64 + col] = make_float2(
                    lrelu(lrelu(acc[mt][nt][2] * sv.x + bv.x, 0.01f) + fr.x, 0.1f),
                    lrelu(lrelu(acc[mt][nt][3] * sv.y + bv.y, 0.01f) + fr.y, 0.1f));
            }
        }
}

// =================== batched scatter-mean over all 4 scales ===================
__global__ void zero_all_kernel(float* __restrict__ vsum4, float* __restrict__ vcnt4) {
    int gid = blockIdx.x * 256 + threadIdx.x;
    if (gid < 4 * MP * 16) ((float4*)vsum4)[gid] = make_float4(0.f, 0.f, 0.f, 0.f);
    if (gid < 4 * MP) vcnt4[gid] = 0.f;
}

__global__ void scatter_all_kernel(const float* __restrict__ V, const int* __restrict__ inv,
                                   float* __restrict__ vsum4, float* __restrict__ vcnt4) {
    int gid = blockIdx.x * 256 + threadIdx.x;
    if (gid >= 4 * MP * 64) return;
    int si = gid / (MP * 64);
    int rem = gid - si * (MP * 64);
    int m = rem >> 6, c = rem & 63;
    int sg = inv[si * MP + m];
    atomicAdd(&vsum4[(size_t)si * MP * 64 + sg * 64 + c], V[rem]);
    if (c == 0) atomicAdd(&vcnt4[si * MP + sg], 1.0f);
}

// ============ tensorized proj: Os=(V-mean)*V (fp16) @ proj_w, grid (GTC,4) ====
__global__ __launch_bounds__(256) void proj_mma_kernel(
    const float* __restrict__ V, const int* __restrict__ inv,
    const float* __restrict__ vsum4, const float* __restrict__ vcnt4,
    const __half* __restrict__ Wp, const float* __restrict__ pb,
    const float* __restrict__ ps, const float* __restrict__ pbb,
    float* __restrict__ ms) {
    __shared__ __align__(16) char smA[16384];
    __shared__ __align__(16) char smW[8192];
    const uint32_t a_s = smem_u32(smA);
    const uint32_t w_s = smem_u32(smW);
    const int tid = threadIdx.x;
    const int lane = tid & 31, wid = tid >> 5;
    const int m0 = blockIdx.x * 128;
    const int si = blockIdx.y;
    const int* seg = inv + (size_t)si * MP;
    const float* vsum = vsum4 + (size_t)si * MP * 64;
    const float* vcnt = vcnt4 + (size_t)si * MP;
    float* msO = ms + (size_t)si * MP * 64;

#pragma unroll
    for (int j = 0; j < 2; j++) {
        int f = tid + j * 256;
        int r = f >> 3, c = f & 7;
        CP16(w_s + r * 128 + ((c ^ (r & 7)) << 4),
             Wp + (size_t)si * 4096 + r * 64 + c * 8);
    }
    CP_COMMIT();
#pragma unroll
    for (int j = 0; j < 4; j++) {
        int f = tid + j * 256;
        int r = f >> 3, c = f & 7;
        uint32_t dst = a_s + r * 128 + ((c ^ (r & 7)) << 4);
        int m = m0 + r;
        if (m < MP) {
            int sg = seg[m];
            float rc = 1.0f / fmaxf(vcnt[sg], 1.0f);
            float4 v0 = *(const float4*)&V[(size_t)m * 64 + c * 8];
            float4 v1 = *(const float4*)&V[(size_t)m * 64 + c * 8 + 4];
            float4 u0 = *(const float4*)&vsum[(size_t)sg * 64 + c * 8];
            float4 u1 = *(const float4*)&vsum[(size_t)sg * 64 + c * 8 + 4];
            __half2 h0 = __float22half2_rn(make_float2((v0.x - u0.x * rc) * v0.x,
                                                       (v0.y - u0.y * rc) * v0.y));
            __half2 h1 = __float22half2_rn(make_float2((v0.z - u0.z * rc) * v0.z,
                                                       (v0.w - u0.w * rc) * v0.w));
            __half2 h2 = __float22half2_rn(make_float2((v1.x - u1.x * rc) * v1.x,
                                                       (v1.y - u1.y * rc) * v1.y));
            __half2 h3 = __float22half2_rn(make_float2((v1.z - u1.z * rc) * v1.z,
                                                       (v1.w - u1.w * rc) * v1.w));
            uint32_t q0 = *(uint32_t*)&h0, q1 = *(uint32_t*)&h1;
            uint32_t q2 = *(uint32_t*)&h2, q3 = *(uint32_t*)&h3;
            asm volatile("st.shared.v4.b32 [%0], {%1,%2,%3,%4};"
                         :: "r"(dst), "r"(q0), "r"(q1), "r"(q2), "r"(q3));
        } else {
            STS_ZERO(dst);
        }
    }
    CP_WAIT(0);
    __syncthreads();

    const int wm = (wid >> 1) * 32;
    const int wn = (wid & 1) * 32;
    float acc[2][4][4] = {};
    mma_tile_64(a_s, w_s, lane, wm, wn, acc);

    const int qr = lane >> 2, qc = lane & 3;
#pragma unroll
    for (int mt = 0; mt < 2; mt++)
#pragma unroll
        for (int nt = 0; nt < 4; nt++) {
            int col = wn + nt * 8 + qc * 2;
            float2 bv = *(const float2*)&pb[si * 64 + col];
            float2 sv = *(const float2*)&ps[si * 64 + col];
            float2 b2 = *(const float2*)&pbb[si * 64 + col];
            int r0 = m0 + wm + mt * 16 + qr;
            int r1 = r0 + 8;
            if (r0 < MP) *(float2*)&msO[(size_t)r0 * 64 + col] = make_float2(
                lrelu((acc[mt][nt][0] + bv.x) * sv.x + b2.x, 0.01f),
                lrelu((acc[mt][nt][1] + bv.y) * sv.y + b2.y, 0.01f));
            if (r1 < MP) *(float2*)&msO[(size_t)r1 * 64 + col] = make_float2(
                lrelu((acc[mt][nt][2] + bv.x) * sv.x + b2.x, 0.01f),
                lrelu((acc[mt][nt][3] + bv.y) * sv.y + b2.y, 0.01f));
        }
}

// ===== tensorized attn: sumx built in-kernel (fp16), 4 GEMMs, fused output ====
__global__ __launch_bounds__(256) void attn_mma_kernel(
    const float* __restrict__ ms, const __half* __restrict__ Wa,
    const float* __restrict__ ab, const float* __restrict__ as_,
    const float* __restrict__ abb, float* __restrict__ fused) {
    __shared__ __align__(16) char smA[16384];
    __shared__ __align__(16) char smW[8192];
    const uint32_t a_s = smem_u32(smA);
    const uint32_t w_s = smem_u32(smW);
    const int tid = threadIdx.x;
    const int lane = tid & 31, wid = tid >> 5;
    const int m0 = blockIdx.x * 128;

#pragma unroll
    for (int j = 0; j < 4; j++) {
        int f = tid + j * 256;
        int r = f >> 3, c = f & 7;
        uint32_t dst = a_s + r * 128 + ((c ^ (r & 7)) << 4);
        int m = m0 + r;
        if (m < MP) {
            float sx[8] = {};
#pragma unroll
            for (int i = 0; i < 4; i++) {
                float4 v0 = *(const float4*)&ms[((size_t)i * MP + m) * 64 + c * 8];
                float4 v1 = *(const float4*)&ms[((size_t)i * MP + m) * 64 + c * 8 + 4];
                sx[0] += v0.x; sx[1] += v0.y; sx[2] += v0.z; sx[3] += v0.w;
                sx[4] += v1.x; sx[5] += v1.y; sx[6] += v1.z; sx[7] += v1.w;
            }
            __half2 h0 = __float22half2_rn(make_float2(sx[0], sx[1]));
            __half2 h1 = __float22half2_rn(make_float2(sx[2], sx[3]));
            __half2 h2 = __float22half2_rn(make_float2(sx[4], sx[5]));
            __half2 h3 = __float22half2_rn(make_float2(sx[6], sx[7]));
            uint32_t q0 = *(uint32_t*)&h0, q1 = *(uint32_t*)&h1;
            uint32_t q2 = *(uint32_t*)&h2, q3 = *(uint32_t*)&h3;
            asm volatile("st.shared.v4.b32 [%0], {%1,%2,%3,%4};"
                         :: "r"(dst), "r"(q0), "r"(q1), "r"(q2), "r"(q3));
        } else {
            STS_ZERO(dst);
        }
    }

    const int wm = (wid >> 1) * 32;
    const int wn = (wid & 1) * 32;
    const int qr = lane >> 2, qc = lane & 3;
    float fac[2][4][4] = {};

    for (int i = 0; i < 4; i++) {
        __syncthreads();
#pragma unroll
        for (int j = 0; j < 2; j++) {
            int f = tid + j * 256;
            int r = f >> 3, c = f & 7;
            CP16(w_s + r * 128 + ((c ^ (r & 7)) << 4),
                 Wa + (size_t)i * 4096 + r * 64 + c * 8);
        }
        CP_COMMIT();
        CP_WAIT(0);
        __syncthreads();

        float acc[2][4][4] = {};
        mma_tile_64(a_s, w_s, lane, wm, wn, acc);

#pragma unroll
        for (int mt = 0; mt < 2; mt++)
#pragma unroll
            for (int nt = 0; nt < 4; nt++) {
                int col = wn + nt * 8 + qc * 2;
                float2 bv = *(const float2*)&ab[i * 64 + col];
                float2 sv = *(const float2*)&as_[i * 64 + col];
                float2 b2 = *(const float2*)&abb[i * 64 + col];
                int r0 = m0 + wm + mt * 16 + qr;
                int r1 = r0 + 8;
                if (r0 < MP) {
                    float2 mv = *(const float2*)&ms[((size_t)i * MP + r0) * 64 + col];
                    float a0 = 1.0f / (1.0f + __expf(-((acc[mt][nt][0] + bv.x) * sv.x + b2.x)));
                    float a1 = 1.0f / (1.0f + __expf(-((acc[mt][nt][1] + bv.y) * sv.y + b2.y)));
                    fac[mt][nt][0] += a0 * mv.x;
                    fac[mt][nt][1] += a1 * mv.y;
                }
                if (r1 < MP) {
                    float2 mv = *(const float2*)&ms[((size_t)i * MP + r1) * 64 + col];
                    float a2 = 1.0f / (1.0f + __expf(-((acc[mt][nt][2] + bv.x) * sv.x + b2.x)));
                    float a3 = 1.0f / (1.0f + __expf(-((acc[mt][nt][3] + bv.y) * sv.y + b2.y)));
                    fac[mt][nt][2] += a2 * mv.x;
                    fac[mt][nt][3] += a3 * mv.y;
                }
            }
    }

#pragma unroll
    for (int mt = 0; mt < 2; mt++)
#pragma unroll
        for (int nt = 0; nt < 4; nt++) {
            int col = wn + nt * 8 + qc * 2;
            int r0 = m0 + wm + mt * 16 + qr;
            int r1 = r0 + 8;
            if (r0 < MP) *(float2*)&fused[(size_t)r0 * 64 + col] =
                make_float2(fac[mt][nt][0], fac[mt][nt][1]);
            if (r1 < MP) *(float2*)&fused[(size_t)r1 * 64 + col] =
                make_float2(fac[mt][nt][2], fac[mt][nt][3]);
        }
}

// ================================ N=20 heads ==================================
__global__ __launch_bounds__(256) void gemm_n20_kernel(
    const float* __restrict__ X, const float* __restrict__ W,
    const float* __restrict__ b, float* __restrict__ out) {
    __shared__ float Xs[128 * 68];
    __shared__ float Ws[64 * 20];
    __shared__ float bs[20];
    const int tid = threadIdx.x;
    const int m0 = blockIdx.x * 128;
#pragma unroll
    for (int j = 0; j < 8; j++) {
        int f = tid + 256 * j;
        int r = f >> 4, c4 = f & 15;
        int m = m0 + r;
        float4 v = make_float4(0.f, 0.f, 0.f, 0.f);
        if (m < MP) v = *(const float4*)&X[(size_t)m * 64 + c4 * 4];
        *(float4*)&Xs[r * 68 + c4 * 4] = v;
    }
    for (int f = tid; f < 64 * 20; f += 256) Ws[f] = W[f];
    if (tid < 20) bs[tid] = b[tid];
    __syncthreads();
    int r = tid >> 1, half = tid & 1, n0 = half * 10;
    int m = m0 + r;
    if (m < MP) {
        float acc[10];
#pragma unroll
        for (int j = 0; j < 10; j++) acc[j] = bs[n0 + j];
#pragma unroll 8
        for (int c = 0; c < 64; c++) {
            float x = Xs[r * 68 + c];
#pragma unroll
            for (int j = 0; j < 10; j++) acc[j] += x * Ws[c * 20 + n0 + j];
        }
#pragma unroll
        for (int j = 0; j < 10; j++) out[(size_t)m * 20 + n0 + j] = acc[j];
    }
}

// ==============================================================================
extern "C" void kernel_launch(void* const* d_in, const int* in_sizes, int n_in,
                              void* d_out, int out_size) {
    const float* feats   = (const float*)d_in[0];
    const float* w1a     = (const float*)d_in[1];
    const float* s1a     = (const float*)d_in[2];
    const float* b1a     = (const float*)d_in[3];
    const float* w3      = (const float*)d_in[4];
    const float* s3      = (const float*)d_in[5];
    const float* b3      = (const float*)d_in[6];
    const float* w1b     = (const float*)d_in[7];
    const float* s1b     = (const float*)d_in[8];
    const float* b1b     = (const float*)d_in[9];
    const float* aux_w   = (const float*)d_in[10];
    const float* aux_b   = (const float*)d_in[11];
    const float* proj_w  = (const float*)d_in[12];
    const float* proj_b  = (const float*)d_in[13];
    const float* proj_s  = (const float*)d_in[14];
    const float* proj_bb = (const float*)d_in[15];
    const float* attn_w  = (const float*)d_in[16];
    const float* attn_b  = (const float*)d_in[17];
    const float* attn_s  = (const float*)d_in[18];
    const float* attn_bb = (const float*)d_in[19];
    const float* head_w  = (const float*)d_in[20];
    const float* head_b  = (const float*)d_in[21];
    const int*   nbr     = (const int*)d_in[22];
    const int*   inv     = (const int*)d_in[23];

    float* out    = (float*)d_out;
    float* fused  = out;
    float* logits = out + (size_t)MP * 64;
    float* aux    = out + (size_t)MP * 84;

    float *pV, *pms, *pvs, *pvc, *pacc;
    __half *pH16, *pW1a, *pW1b, *pWp, *pWa, *pW13, *pW3n;
    int2 *pent; int *pecnt;
    cudaGetSymbolAddress((void**)&pV, g_V);
    cudaGetSymbolAddress((void**)&pms, g_ms);
    cudaGetSymbolAddress((void**)&pvs, g_vsum4);
    cudaGetSymbolAddress((void**)&pvc, g_vcnt4);
    cudaGetSymbolAddress((void**)&pacc, g_acc);
    cudaGetSymbolAddress((void**)&pH16, g_H16);
    cudaGetSymbolAddress((void**)&pW1a, g_W1a16);
    cudaGetSymbolAddress((void**)&pW1b, g_W1b16);
    cudaGetSymbolAddress((void**)&pWp, g_Wp16);
    cudaGetSymbolAddress((void**)&pWa, g_Wa16);
    cudaGetSymbolAddress((void**)&pW13, g_W13t);
    cudaGetSymbolAddress((void**)&pW3n, g_W3n);
    cudaGetSymbolAddress((void**)&pent, g_ent);
    cudaGetSymbolAddress((void**)&pecnt, g_ecnt);

    wprep_kernel<<<320, 256>>>(w1a, w1b, proj_w, attn_w, w3,
                               pW1a, pW1b, pWp, pWa, pW13, pecnt);
    w3n_kernel<<<1728, 256>>>(w3, pW3n);
    entprep_kernel<<<469, 256>>>(nbr, pent, pecnt);

    gemm64hf_kernel<<<GTC, 256>>>(feats, pW1a, s1a, b1a, pH16);
    for (int i = 0; i < 4; i++) {
        gemm_self_kernel<<<GTC, 256>>>(pH16, pW13 + (size_t)i * 4096, pacc);
        {
            dim3 grid(1875, 26);
            sparse_conv_kernel<<<grid, 256>>>(pH16, pW3n + (size_t)i * 27 * 4096,
                                              pent, pecnt, pacc);
        }
        if (i < 3) {
            gemm64h2f_kernel<<<GTC, 256>>>(pacc, s3 + i * 64, b3 + i * 64,
                                           pW1b + (size_t)i * 4096, s1b + i * 64, b1b + i * 64,
                                           pW1a + (size_t)(i + 1) * 4096, s1a + (i + 1) * 64,
                                           b1a + (i + 1) * 64, pH16);
        } else {
            gemm64h_resf_kernel<<<GTC, 256>>>(pacc, s3 + i * 64, b3 + i * 64,
                                              pW1b + (size_t)i * 4096, s1b + i * 64,
                                              b1b + i * 64, pV, feats);
        }
    }

    gemm_n20_kernel<<<938, 256>>>(pV, aux_w, aux_b, aux);

    zero_all_kernel<<<30000, 256>>>(pvs, pvc);
    scatter_all_kernel<<<120000, 256>>>(pV, inv, pvs, pvc);
    {
        dim3 grid(GTC, 4);
        proj_mma_kernel<<<grid, 256>>>(pV, inv, pvs, pvc, pWp,
                                       proj_b, proj_s, proj_bb, pms);
    }
    attn_mma_kernel<<<GTC, 256>>>(pms, pWa, attn_b, attn_s, attn_bb, fused);
    gemm_n20_kernel<<<938, 256>>>(fused, head_w, head_b, logits);
}

// round 14
// speedup vs baseline: 1.6366x; 1.0484x over previous
#include <cuda_runtime.h>
#include <cuda_fp16.h>
#include <math.h>
#include <stdint.h>

#define MP 120000
#define GTC 938     // ceil(MP / 128)

// ---------------- scratch (static device globals; no runtime allocs) ----------
__device__ float  g_V[MP * 64];
__device__ __half g_H16[MP * 64];
__device__ float  g_acc[MP * 64];        // conv fp32 accumulator
__device__ __half g_W1a16[4 * 4096];
__device__ __half g_W1b16[4 * 4096];
__device__ __half g_Wp16[4 * 4096];
__device__ __half g_Wa16[4 * 4096];
__device__ __half g_W13t[4 * 4096];      // tap-13 weights transposed [d][c] fp16
__device__ __half g_W3n[4 * 27 * 4096];  // conv weights original [c][d] fp16
__device__ int2   g_ent[26 * MP];        // valid (m, src) pairs per non-self tap
__device__ int    g_ecnt[26];
__device__ float  g_ms[4 * MP * 64];
__device__ float  g_vsum4[4 * MP * 64];
__device__ float  g_vcnt4[4 * MP];

__device__ __forceinline__ float lrelu(float x, float a) { return x > 0.f ? x : a * x; }

__device__ __forceinline__ uint32_t smem_u32(const void* p) {
    uint32_t a;
    asm("{ .reg .u64 t; cvta.to.shared.u64 t, %1; cvt.u32.u64 %0, t; }" : "=r"(a) : "l"(p));
    return a;
}

__device__ __forceinline__ void ldm4(uint32_t r[4], uint32_t addr) {
    asm volatile("ldmatrix.sync.aligned.m8n8.x4.shared.b16 {%0,%1,%2,%3}, [%4];"
                 : "=r"(r[0]), "=r"(r[1]), "=r"(r[2]), "=r"(r[3]) : "r"(addr));
}

__device__ __forceinline__ void mma16816(float c[4], const uint32_t a[4],
                                         uint32_t b0, uint32_t b1) {
    asm volatile(
        "mma.sync.aligned.m16n8k16.row.col.f32.f16.f16.f32 "
        "{%0,%1,%2,%3},{%4,%5,%6,%7},{%8,%9},{%0,%1,%2,%3};"
        : "+f"(c[0]), "+f"(c[1]), "+f"(c[2]), "+f"(c[3])
        : "r"(a[0]), "r"(a[1]), "r"(a[2]), "r"(a[3]), "r"(b0), "r"(b1));
}

#define CP16(dst, src) \
    asm volatile("cp.async.cg.shared.global [%0], [%1], 16;" :: "r"(dst), "l"(src))
#define CP_COMMIT() asm volatile("cp.async.commit_group;" ::: "memory")
#define CP_WAIT(n)  asm volatile("cp.async.wait_group %0;" :: "n"(n) : "memory")
#define STS_ZERO(dst) do { uint32_t _z = 0; \
    asm volatile("st.shared.v4.b32 [%0], {%1,%1,%1,%1};" :: "r"(dst), "r"(_z)); } while (0)

// ========== MMA core (M-tile 128): A(128x64) x W(64x64)^T, 8 warps ============
__device__ __forceinline__ void mma_tile_64(uint32_t a_s, uint32_t w_s,
                                            int lane, int wm, int wn,
                                            float acc[2][4][4]) {
#pragma unroll
    for (int kb = 0; kb < 4; kb++) {
        uint32_t a[2][4], wh[2][4];
#pragma unroll
        for (int mt = 0; mt < 2; mt++) {
            int r = wm + mt * 16 + (lane & 15);
            int lc = kb * 2 + (lane >> 4);
            ldm4(a[mt], a_s + r * 128 + ((lc ^ (r & 7)) << 4));
        }
#pragma unroll
        for (int np = 0; np < 2; np++) {
            int r = wn + np * 16 + (lane & 7) + ((lane & 16) ? 8 : 0);
            int lc = kb * 2 + ((lane >> 3) & 1);
            ldm4(wh[np], w_s + r * 128 + ((lc ^ (r & 7)) << 4));
        }
#pragma unroll
        for (int mt = 0; mt < 2; mt++)
#pragma unroll
            for (int nt = 0; nt < 4; nt++) {
                int np = nt >> 1, q = (nt & 1) * 2;
                mma16816(acc[mt][nt], a[mt], wh[np][q], wh[np][q + 1]);
            }
    }
}

// epi helper: write fp16 lrelu result into swizzled smem tile
__device__ __forceinline__ void epi_to_smem(char* sm, int lr0, int lr1, int col,
                                            float v0, float v1, float v2, float v3) {
    __half2 h0 = __float22half2_rn(make_float2(v0, v1));
    __half2 h1 = __float22half2_rn(make_float2(v2, v3));
    uint32_t d0 = lr0 * 128 + (((col >> 3) ^ (lr0 & 7)) << 4) + ((col * 2) & 15);
    uint32_t d1 = lr1 * 128 + (((col >> 3) ^ (lr1 & 7)) << 4) + ((col * 2) & 15);
    *(__half2*)(sm + d0) = h0;
    *(__half2*)(sm + d1) = h1;
}

// ====== weight prep: transpose+fp16 for 1x1/proj/attn/W13t; zero ecnt =========
__global__ void wprep_kernel(const float* __restrict__ w1a, const float* __restrict__ w1b,
                             const float* __restrict__ wp, const float* __restrict__ wa,
                             const float* __restrict__ w3,
                             __half* __restrict__ o1a, __half* __restrict__ o1b,
                             __half* __restrict__ op, __half* __restrict__ oa,
                             __half* __restrict__ o13, int* __restrict__ ecnt) {
    int g = blockIdx.x * 256 + threadIdx.x;
    if (g < 26) ecnt[g] = 0;
    if (g >= 20 * 4096) return;
    int t = g >> 12;
    int rc = g & 4095;
    int d = rc >> 6, c = rc & 63;
    if (t < 4)
        o1a[(size_t)t * 4096 + d * 64 + c] = __float2half_rn(w1a[(size_t)t * 4096 + c * 64 + d]);
    else if (t < 8)
        o1b[(size_t)(t - 4) * 4096 + d * 64 + c] = __float2half_rn(w1b[(size_t)(t - 4) * 4096 + c * 64 + d]);
    else if (t < 12)
        op[(size_t)(t - 8) * 4096 + d * 64 + c] = __float2half_rn(wp[(size_t)(t - 8) * 4096 + c * 64 + d]);
    else if (t < 16)
        oa[(size_t)(t - 12) * 4096 + d * 64 + c] = __float2half_rn(wa[(size_t)(t - 12) * 4096 + c * 64 + d]);
    else {
        int lt = t - 16;
        o13[(size_t)lt * 4096 + d * 64 + c] =
            __float2half_rn(w3[((size_t)lt * 27 + 13) * 4096 + c * 64 + d]);
    }
}

__global__ void w3n_kernel(const float* __restrict__ w3, __half* __restrict__ o) {
    int g = blockIdx.x * 256 + threadIdx.x;
    if (g >= 4 * 27 * 4096) return;
    o[g] = __float2half_rn(w3[g]);
}

__global__ void entprep_kernel(const int* __restrict__ nbr,
                               int2* __restrict__ ent, int* __restrict__ ecnt) {
    int m = blockIdx.x * 256 + threadIdx.x;
    if (m >= MP) return;
#pragma unroll
    for (int k = 0; k < 27; k++) {
        if (k == 13) continue;
        int src = nbr[(size_t)m * 27 + k];
        if (src >= 0) {
            int idx = (k < 13) ? k : k - 1;
            int pos = atomicAdd(&ecnt[idx], 1);
            ent[(size_t)idx * MP + pos] = make_int2(m, src);
        }
    }
}

// ==== first layer fused: fp32 feats -> w1a epi -> H16 out; H @ W13 -> acc =====
__global__ __launch_bounds__(256) void gemm64hf2_kernel(
    const float* __restrict__ Xf, const __half* __restrict__ W,
    const float* __restrict__ s, const float* __restrict__ b,
    const __half* __restrict__ W13,
    __half* __restrict__ outh, float* __restrict__ accout) {
    __shared__ __align__(16) char smA[16384];
    __shared__ __align__(16) char smB[16384];
    __shared__ __align__(16) char smW[8192];
    __shared__ __align__(16) char smW13[8192];
    const uint32_t a_s = smem_u32(smA);
    const uint32_t b_s = smem_u32(smB);
    const uint32_t w_s = smem_u32(smW);
    const uint32_t w13_s = smem_u32(smW13);
    const int tid = threadIdx.x;
    const int lane = tid & 31, wid = tid >> 5;
    const int m0 = blockIdx.x * 128;

#pragma unroll
    for (int j = 0; j < 2; j++) {
        int f = tid + j * 256;
        int r = f >> 3, c = f & 7;
        CP16(w_s + r * 128 + ((c ^ (r & 7)) << 4), W + (size_t)r * 64 + c * 8);
        CP16(w13_s + r * 128 + ((c ^ (r & 7)) << 4), W13 + (size_t)r * 64 + c * 8);
    }
    CP_COMMIT();
#pragma unroll
    for (int j = 0; j < 4; j++) {
        int f = tid + j * 256;
        int r = f >> 3, c = f & 7;
        uint32_t dst = a_s + r * 128 + ((c ^ (r & 7)) << 4);
        int m = m0 + r;
        if (m < MP) {
            float4 v0 = *(const float4*)&Xf[(size_t)m * 64 + c * 8];
            float4 v1 = *(const float4*)&Xf[(size_t)m * 64 + c * 8 + 4];
            __half2 h0 = __float22half2_rn(make_float2(v0.x, v0.y));
            __half2 h1 = __float22half2_rn(make_float2(v0.z, v0.w));
            __half2 h2 = __float22half2_rn(make_float2(v1.x, v1.y));
            __half2 h3 = __float22half2_rn(make_float2(v1.z, v1.w));
            uint32_t q0 = *(uint32_t*)&h0, q1 = *(uint32_t*)&h1;
            uint32_t q2 = *(uint32_t*)&h2, q3 = *(uint32_t*)&h3;
            asm volatile("st.shared.v4.b32 [%0], {%1,%2,%3,%4};"
                         :: "r"(dst), "r"(q0), "r"(q1), "r"(q2), "r"(q3));
        } else {
            STS_ZERO(dst);
        }
    }
    CP_WAIT(0);
    __syncthreads();

    const int wm = (wid >> 1) * 32;
    const int wn = (wid & 1) * 32;
    const int qr = lane >> 2, qc = lane & 3;

    float acc[2][4][4] = {};
    mma_tile_64(a_s, w_s, lane, wm, wn, acc);

#pragma unroll
    for (int mt = 0; mt < 2; mt++)
#pragma unroll
        for (int nt = 0; nt < 4; nt++) {
            int col = wn + nt * 8 + qc * 2;
            float2 s2 = *(const float2*)&s[col];
            float2 b2 = *(const float2*)&b[col];
            int lr0 = wm + mt * 16 + qr;
            int lr1 = lr0 + 8;
            int r0 = m0 + lr0, r1 = m0 + lr1;
            float v0 = lrelu(acc[mt][nt][0] * s2.x + b2.x, 0.01f);
            float v1 = lrelu(acc[mt][nt][1] * s2.y + b2.y, 0.01f);
            float v2 = lrelu(acc[mt][nt][2] * s2.x + b2.x, 0.01f);
            float v3 = lrelu(acc[mt][nt][3] * s2.y + b2.y, 0.01f);
            epi_to_smem(smB, lr0, lr1, col, v0, v1, v2, v3);
            if (r0 < MP) *(__half2*)&outh[(size_t)r0 * 64 + col] =
                __float22half2_rn(make_float2(v0, v1));
            if (r1 < MP) *(__half2*)&outh[(size_t)r1 * 64 + col] =
                __float22half2_rn(make_float2(v2, v3));
        }
    __syncthreads();

    float acc2[2][4][4] = {};
    mma_tile_64(b_s, w13_s, lane, wm, wn, acc2);

#pragma unroll
    for (int mt = 0; mt < 2; mt++)
#pragma unroll
        for (int nt = 0; nt < 4; nt++) {
            int col = wn + nt * 8 + qc * 2;
            int r0 = m0 + wm + mt * 16 + qr;
            int r1 = r0 + 8;
            if (r0 < MP) *(float2*)&accout[(size_t)r0 * 64 + col] =
                make_float2(acc2[mt][nt][0], acc2[mt][nt][1]);
            if (r1 < MP) *(float2*)&accout[(size_t)r1 * 64 + col] =
                make_float2(acc2[mt][nt][2], acc2[mt][nt][3]);
        }
}

// ======= sparse conv: acc[m] += H[src] @ W3[tap], chunk-stride grid ===========
__global__ __launch_bounds__(256) void sparse_conv_kernel(
    const __half* __restrict__ H, const __half* __restrict__ W3n,
    const int2* __restrict__ ent, const int* __restrict__ ecnt,
    float* __restrict__ acc) {
    const int kk = blockIdx.y;             // 0..25
    const int cnt = ecnt[kk];
    if ((int)(blockIdx.x * 64) >= cnt) return;
    const int tap = (kk < 13) ? kk : kk + 1;

    __shared__ __align__(16) __half Ws[64 * 64];   // [c][j]
    __shared__ __align__(16) __half Hs[64][64];
    __shared__ int2 es[64];
    const int tid = threadIdx.x;

    const uint4* wsrc = (const uint4*)(W3n + (size_t)tap * 4096);
#pragma unroll
    for (int j = 0; j < 2; j++)
        ((uint4*)Ws)[tid + j * 256] = wsrc[tid + j * 256];

    const int wrp = tid >> 5, lane = tid & 31;

    for (int base = blockIdx.x * 64; base < cnt; base += gridDim.x * 64) {
        __syncthreads();
        if (tid < 64) {
            int e = base + tid;
            es[tid] = (e < cnt) ? ent[(size_t)kk * MP + e] : make_int2(-1, -1);
        }
        __syncthreads();
        {
            int e = tid >> 2, q = tid & 3;
            int src = es[e].y;
            if (src >= 0) {
                *(uint4*)&Hs[e][q * 8]      = *(const uint4*)&H[(size_t)src * 64 + q * 8];
                *(uint4*)&Hs[e][32 + q * 8] = *(const uint4*)&H[(size_t)src * 64 + 32 + q * 8];
            }
        }
        __syncthreads();

#pragma unroll
        for (int ei = 0; ei < 8; ei++) {
            int e = wrp * 8 + ei;
            int m = es[e].x;
            if (m < 0) continue;
            float v0 = 0.f, v1 = 0.f;
#pragma unroll
            for (int d = 0; d < 64; d++) {
                float h = __half2float(Hs[e][d]);
                float2 wf = __half22float2(*(const __half2*)&Ws[d * 64 + lane * 2]);
                v0 += h * wf.x;
                v1 += h * wf.y;
            }
            atomicAdd(&acc[(size_t)m * 64 + lane * 2], v0);
            atomicAdd(&acc[(size_t)m * 64 + lane * 2 + 1], v1);
        }
    }
}

// === fused triple (DYNAMIC smem 56KB): conv-epi(acc) -> @W1b -> epi ->
//     @W1a_next -> epi -> H16; then H @ W13_next -> accout =====================
// dyn smem layout: A 16384 | B 16384 | W1 8192 | W2 8192 | W13 8192 = 57344
#define T3_A    0
#define T3_B    16384
#define T3_W1   32768
#define T3_W2   40960
#define T3_W13  49152
#define T3_TOT  57344

__global__ __launch_bounds__(256) void gemm64h3f_kernel(
    const float* __restrict__ accin, const float* __restrict__ cs, const float* __restrict__ cb,
    const __half* __restrict__ W1, const float* __restrict__ s1, const float* __restrict__ b1,
    const __half* __restrict__ W2, const float* __restrict__ s2, const float* __restrict__ b2,
    const __half* __restrict__ W13,
    __half* __restrict__ outh, float* __restrict__ accout) {
    extern __shared__ __align__(16) char smd[];
    char* smA = smd + T3_A;
    char* smB = smd + T3_B;
    const uint32_t a_s = smem_u32(smd) + T3_A;
    const uint32_t b_s = smem_u32(smd) + T3_B;
    const uint32_t w1_s = smem_u32(smd) + T3_W1;
    const uint32_t w2_s = smem_u32(smd) + T3_W2;
    const uint32_t w13_s = smem_u32(smd) + T3_W13;
    const int tid = threadIdx.x;
    const int lane = tid & 31, wid = tid >> 5;
    const int m0 = blockIdx.x * 128;

#pragma unroll
    for (int j = 0; j < 2; j++) {
        int f = tid + j * 256;
        int r = f >> 3, c = f & 7;
        CP16(w1_s + r * 128 + ((c ^ (r & 7)) << 4), W1 + (size_t)r * 64 + c * 8);
        CP16(w2_s + r * 128 + ((c ^ (r & 7)) << 4), W2 + (size_t)r * 64 + c * 8);
        CP16(w13_s + r * 128 + ((c ^ (r & 7)) << 4), W13 + (size_t)r * 64 + c * 8);
    }
    CP_COMMIT();
#pragma unroll
    for (int j = 0; j < 4; j++) {
        int f = tid + j * 256;
        int r = f >> 3, c = f & 7;
        uint32_t dst = a_s + r * 128 + ((c ^ (r & 7)) << 4);
        int m = m0 + r;
        if (m < MP) {
            float4 v0 = *(const float4*)&accin[(size_t)m * 64 + c * 8];
            float4 v1 = *(const float4*)&accin[(size_t)m * 64 + c * 8 + 4];
            float4 s0 = *(const float4*)&cs[c * 8];
            float4 s1v = *(const float4*)&cs[c * 8 + 4];
            float4 b0 = *(const float4*)&cb[c * 8];
            float4 b1v = *(const float4*)&cb[c * 8 + 4];
            __half2 h0 = __float22half2_rn(make_float2(lrelu(v0.x * s0.x + b0.x, 0.01f),
                                                       lrelu(v0.y * s0.y + b0.y, 0.01f)));
            __half2 h1 = __float22half2_rn(make_float2(lrelu(v0.z * s0.z + b0.z, 0.01f),
                                                       lrelu(v0.w * s0.w + b0.w, 0.01f)));
            __half2 h2 = __float22half2_rn(make_float2(lrelu(v1.x * s1v.x + b1v.x, 0.01f),
                                                       lrelu(v1.y * s1v.y + b1v.y, 0.01f)));
            __half2 h3 = __float22half2_rn(make_float2(lrelu(v1.z * s1v.z + b1v.z, 0.01f),
                                                       lrelu(v1.w * s1v.w + b1v.w, 0.01f)));
            uint32_t q0 = *(uint32_t*)&h0, q1 = *(uint32_t*)&h1;
            uint32_t q2 = *(uint32_t*)&h2, q3 = *(uint32_t*)&h3;
            asm volatile("st.shared.v4.b32 [%0], {%1,%2,%3,%4};"
                         :: "r"(dst), "r"(q0), "r"(q1), "r"(q2), "r"(q3));
        } else {
            STS_ZERO(dst);
        }
    }
    CP_WAIT(0);
    __syncthreads();

    const int wm = (wid >> 1) * 32;
    const int wn = (wid & 1) * 32;
    const int qr = lane >> 2, qc = lane & 3;

    float acc[2][4][4] = {};
    mma_tile_64(a_s, w1_s, lane, wm, wn, acc);

#pragma unroll
    for (int mt = 0; mt < 2; mt++)
#pragma unroll
        for (int nt = 0; nt < 4; nt++) {
            int col = wn + nt * 8 + qc * 2;
            float2 sv = *(const float2*)&s1[col];
            float2 bv = *(const float2*)&b1[col];
            int lr0 = wm + mt * 16 + qr;
            int lr1 = lr0 + 8;
            epi_to_smem(smB, lr0, lr1, col,
                        lrelu(acc[mt][nt][0] * sv.x + bv.x, 0.01f),
                        lrelu(acc[mt][nt][1] * sv.y + bv.y, 0.01f),
                        lrelu(acc[mt][nt][2] * sv.x + bv.x, 0.01f),
                        lrelu(acc[mt][nt][3] * sv.y + bv.y, 0.01f));
        }
    __syncthreads();

    float acc2[2][4][4] = {};
    mma_tile_64(b_s, w2_s, lane, wm, wn, acc2);
    __syncthreads();   // all reads of smA (GEMM1) and smB (GEMM2) complete

#pragma unroll
    for (int mt = 0; mt < 2; mt++)
#pragma unroll
        for (int nt = 0; nt < 4; nt++) {
            int col = wn + nt * 8 + qc * 2;
            float2 sv = *(const float2*)&s2[col];
            float2 bv = *(const float2*)&b2[col];
            int lr0 = wm + mt * 16 + qr;
            int lr1 = lr0 + 8;
            int r0 = m0 + lr0, r1 = m0 + lr1;
            float v0 = lrelu(acc2[mt][nt][0] * sv.x + bv.x, 0.01f);
            float v1 = lrelu(acc2[mt][nt][1] * sv.y + bv.y, 0.01f);
            float v2 = lrelu(acc2[mt][nt][2] * sv.x + bv.x, 0.01f);
            float v3 = lrelu(acc2[mt][nt][3] * sv.y + bv.y, 0.01f);
            epi_to_smem(smA, lr0, lr1, col, v0, v1, v2, v3);   // reuse smA for H tile
            if (r0 < MP) *(__half2*)&outh[(size_t)r0 * 64 + col] =
                __float22half2_rn(make_float2(v0, v1));
            if (r1 < MP) *(__half2*)&outh[(size_t)r1 * 64 + col] =
                __float22half2_rn(make_float2(v2, v3));
        }
    __syncthreads();

    float acc3[2][4][4] = {};
    mma_tile_64(a_s, w13_s, lane, wm, wn, acc3);

#pragma unroll
    for (int mt = 0; mt < 2; mt++)
#pragma unroll
        for (int nt = 0; nt < 4; nt++) {
            int col = wn + nt * 8 + qc * 2;
            int r0 = m0 + wm + mt * 16 + qr;
            int r1 = r0 + 8;
            if (r0 < MP) *(float2*)&accout[(size_t)r0 * 64 + col] =
                make_float2(acc3[mt][nt][0], acc3[mt][nt][1]);
            if (r1 < MP) *(float2*)&accout[(size_t)r1 * 64 + col] =
                make_float2(acc3[mt][nt][2], acc3[mt][nt][3]);
        }
}

// === fused last: conv-epilogue(acc) -> GEMM w1b -> epi + residual -> V fp32 ===
__global__ __launch_bounds__(256) void gemm64h_resf_kernel(
    const float* __restrict__ accin, const float* __restrict__ cs, const float* __restrict__ cb,
    const __half* __restrict__ W, const float* __restrict__ s, const float* __restrict__ b,
    float* __restrict__ outf, const float* __restrict__ feats) {
    __shared__ __align__(16) char smA[16384];
    __shared__ __align__(16) char smW[8192];
    const uint32_t a_s = smem_u32(smA);
    const uint32_t w_s = smem_u32(smW);
    const int tid = threadIdx.x;
    const int lane = tid & 31, wid = tid >> 5;
    const int m0 = blockIdx.x * 128;

#pragma unroll
    for (int j = 0; j < 2; j++) {
        int f = tid + j * 256;
        int r = f >> 3, c = f & 7;
        CP16(w_s + r * 128 + ((c ^ (r & 7)) << 4), W + (size_t)r * 64 + c * 8);
    }
    CP_COMMIT();
#pragma unroll
    for (int j = 0; j < 4; j++) {
        int f = tid + j * 256;
        int r = f >> 3, c = f & 7;
        uint32_t dst = a_s + r * 128 + ((c ^ (r & 7)) << 4);
        int m = m0 + r;
        if (m < MP) {
            float4 v0 = *(const float4*)&accin[(size_t)m * 64 + c * 8];
            float4 v1 = *(const float4*)&accin[(size_t)m * 64 + c * 8 + 4];
            float4 s0 = *(const float4*)&cs[c * 8];
            float4 s1v = *(const float4*)&cs[c * 8 + 4];
            float4 b0 = *(const float4*)&cb[c * 8];
            float4 b1v = *(const float4*)&cb[c * 8 + 4];
            __half2 h0 = __float22half2_rn(make_float2(lrelu(v0.x * s0.x + b0.x, 0.01f),
                                                       lrelu(v0.y * s0.y + b0.y, 0.01f)));
            __half2 h1 = __float22half2_rn(make_float2(lrelu(v0.z * s0.z + b0.z, 0.01f),
                                                       lrelu(v0.w * s0.w + b0.w, 0.01f)));
            __half2 h2 = __float22half2_rn(make_float2(lrelu(v1.x * s1v.x + b1v.x, 0.01f),
                                                       lrelu(v1.y * s1v.y + b1v.y, 0.01f)));
            __half2 h3 = __float22half2_rn(make_float2(lrelu(v1.z * s1v.z + b1v.z, 0.01f),
                                                       lrelu(v1.w * s1v.w + b1v.w, 0.01f)));
            uint32_t q0 = *(uint32_t*)&h0, q1 = *(uint32_t*)&h1;
            uint32_t q2 = *(uint32_t*)&h2, q3 = *(uint32_t*)&h3;
            asm volatile("st.shared.v4.b32 [%0], {%1,%2,%3,%4};"
                         :: "r"(dst), "r"(q0), "r"(q1), "r"(q2), "r"(q3));
        } else {
            STS_ZERO(dst);
        }
    }
    CP_WAIT(0);
    __syncthreads();

    const int wm = (wid >> 1) * 32;
    const int wn = (wid & 1) * 32;
    float acc[2][4][4] = {};
    mma_tile_64(a_s, w_s, lane, wm, wn, acc);

    const int qr = lane >> 2, qc = lane & 3;
#pragma unroll
    for (int mt = 0; mt < 2; mt++)
#pragma unroll
        for (int nt = 0; nt < 4; nt++) {
            int col = wn + nt * 8 + qc * 2;
            float2 sv = *(const float2*)&s[col];
            float2 bv = *(const float2*)&b[col];
            int r0 = m0 + wm + mt * 16 + qr;
            int r1 = r0 + 8;
            if (r0 < MP) {
                float2 fr = *(const float2*)&feats[(size_t)r0 * 64 + col];
                *(float2*)&outf[(size_t)r0 * 64 + col] = make_float2(
                    lrelu(lrelu(acc[mt][nt][0] * sv.x + bv.x, 0.01f) + fr.x, 0.1f),
                    lrelu(lrelu(acc[mt][nt][1] * sv.y + bv.y, 0.01f) + fr.y, 0.1f));
            }
            if (r1 < MP) {
                float2 fr = *(const float2*)&feats[(size_t)r1 * 64 + col];
                *(float2*)&outf[(size_t)r1 * 64 + col] = make_float2(
                    lrelu(lrelu(acc[mt][nt][2] * sv.x + bv.x, 0.01f) + fr.x, 0.1f),
                    lrelu(lrelu(acc[mt][nt][3] * sv.y + bv.y, 0.01f) + fr.y, 0.1f));
            }
        }
}

// =================== batched scatter-mean over all 4 scales ===================
__global__ void zero_all_kernel(float* __restrict__ vsum4, float* __restrict__ vcnt4) {
    int gid = blockIdx.x * 256 + threadIdx.x;
    if (gid < 4 * MP * 16) ((float4*)vsum4)[gid] = make_float4(0.f, 0.f, 0.f, 0.f);
    if (gid < 4 * MP) vcnt4[gid] = 0.f;
}

__global__ void scatter_all_kernel(const float* __restrict__ V, const int* __restrict__ inv,
                                   float* __restrict__ vsum4, float* __restrict__ vcnt4) {
    int gid = blockIdx.x * 256 + threadIdx.x;
    if (gid >= 4 * MP * 64) return;
    int si = gid / (MP * 64);
    int rem = gid - si * (MP * 64);
    int m = rem >> 6, c = rem & 63;
    int sg = inv[si * MP + m];
    atomicAdd(&vsum4[(size_t)si * MP * 64 + sg * 64 + c], V[rem]);
    if (c == 0) atomicAdd(&vcnt4[si * MP + sg], 1.0f);
}

// ============ tensorized proj: Os=(V-mean)*V (fp16) @ proj_w, grid (GTC,4) ====
__global__ __launch_bounds__(256) void proj_mma_kernel(
    const float* __restrict__ V, const int* __restrict__ inv,
    const float* __restrict__ vsum4, const float* __restrict__ vcnt4,
    const __half* __restrict__ Wp, const float* __restrict__ pb,
    const float* __restrict__ ps, const float* __restrict__ pbb,
    float* __restrict__ ms) {
    __shared__ __align__(16) char smA[16384];
    __shared__ __align__(16) char smW[8192];
    const uint32_t a_s = smem_u32(smA);
    const uint32_t w_s = smem_u32(smW);
    const int tid = threadIdx.x;
    const int lane = tid & 31, wid = tid >> 5;
    const int m0 = blockIdx.x * 128;
    const int si = blockIdx.y;
    const int* seg = inv + (size_t)si * MP;
    const float* vsum = vsum4 + (size_t)si * MP * 64;
    const float* vcnt = vcnt4 + (size_t)si * MP;
    float* msO = ms + (size_t)si * MP * 64;

#pragma unroll
    for (int j = 0; j < 2; j++) {
        int f = tid + j * 256;
        int r = f >> 3, c = f & 7;
        CP16(w_s + r * 128 + ((c ^ (r & 7)) << 4),
             Wp + (size_t)si * 4096 + r * 64 + c * 8);
    }
    CP_COMMIT();
#pragma unroll
    for (int j = 0; j < 4; j++) {
        int f = tid + j * 256;
        int r = f >> 3, c = f & 7;
        uint32_t dst = a_s + r * 128 + ((c ^ (r & 7)) << 4);
        int m = m0 + r;
        if (m < MP) {
            int sg = seg[m];
            float rc = 1.0f / fmaxf(vcnt[sg], 1.0f);
            float4 v0 = *(const float4*)&V[(size_t)m * 64 + c * 8];
            float4 v1 = *(const float4*)&V[(size_t)m * 64 + c * 8 + 4];
            float4 u0 = *(const float4*)&vsum[(size_t)sg * 64 + c * 8];
            float4 u1 = *(const float4*)&vsum[(size_t)sg * 64 + c * 8 + 4];
            __half2 h0 = __float22half2_rn(make_float2((v0.x - u0.x * rc) * v0.x,
                                                       (v0.y - u0.y * rc) * v0.y));
            __half2 h1 = __float22half2_rn(make_float2((v0.z - u0.z * rc) * v0.z,
                                                       (v0.w - u0.w * rc) * v0.w));
            __half2 h2 = __float22half2_rn(make_float2((v1.x - u1.x * rc) * v1.x,
                                                       (v1.y - u1.y * rc) * v1.y));
            __half2 h3 = __float22half2_rn(make_float2((v1.z - u1.z * rc) * v1.z,
                                                       (v1.w - u1.w * rc) * v1.w));
            uint32_t q0 = *(uint32_t*)&h0, q1 = *(uint32_t*)&h1;
            uint32_t q2 = *(uint32_t*)&h2, q3 = *(uint32_t*)&h3;
            asm volatile("st.shared.v4.b32 [%0], {%1,%2,%3,%4};"
                         :: "r"(dst), "r"(q0), "r"(q1), "r"(q2), "r"(q3));
        } else {
            STS_ZERO(dst);
        }
    }
    CP_WAIT(0);
    __syncthreads();

    const int wm = (wid >> 1) * 32;
    const int wn = (wid & 1) * 32;
    float acc[2][4][4] = {};
    mma_tile_64(a_s, w_s, lane, wm, wn, acc);

    const int qr = lane >> 2, qc = lane & 3;
#pragma unroll
    for (int mt = 0; mt < 2; mt++)
#pragma unroll
        for (int nt = 0; nt < 4; nt++) {
            int col = wn + nt * 8 + qc * 2;
            float2 bv = *(const float2*)&pb[si * 64 + col];
            float2 sv = *(const float2*)&ps[si * 64 + col];
            float2 b2 = *(const float2*)&pbb[si * 64 + col];
            int r0 = m0 + wm + mt * 16 + qr;
            int r1 = r0 + 8;
            if (r0 < MP) *(float2*)&msO[(size_t)r0 * 64 + col] = make_float2(
                lrelu((acc[mt][nt][0] + bv.x) * sv.x + b2.x, 0.01f),
                lrelu((acc[mt][nt][1] + bv.y) * sv.y + b2.y, 0.01f));
            if (r1 < MP) *(float2*)&msO[(size_t)r1 * 64 + col] = make_float2(
                lrelu((acc[mt][nt][2] + bv.x) * sv.x + b2.x, 0.01f),
                lrelu((acc[mt][nt][3] + bv.y) * sv.y + b2.y, 0.01f));
        }
}

// ===== tensorized attn: sumx built in-kernel (fp16), 4 GEMMs, fused output ====
__global__ __launch_bounds__(256) void attn_mma_kernel(
    const float* __restrict__ ms, const __half* __restrict__ Wa,
    const float* __restrict__ ab, const float* __restrict__ as_,
    const float* __restrict__ abb, float* __restrict__ fused) {
    __shared__ __align__(16) char smA[16384];
    __shared__ __align__(16) char smW[8192];
    const uint32_t a_s = smem_u32(smA);
    const uint32_t w_s = smem_u32(smW);
    const int tid = threadIdx.x;
    const int lane = tid & 31, wid = tid >> 5;
    const int m0 = blockIdx.x * 128;

#pragma unroll
    for (int j = 0; j < 4; j++) {
        int f = tid + j * 256;
        int r = f >> 3, c = f & 7;
        uint32_t dst = a_s + r * 128 + ((c ^ (r & 7)) << 4);
        int m = m0 + r;
        if (m < MP) {
            float sx[8] = {};
#pragma unroll
            for (int i = 0; i < 4; i++) {
                float4 v0 = *(const float4*)&ms[((size_t)i * MP + m) * 64 + c * 8];
                float4 v1 = *(const float4*)&ms[((size_t)i * MP + m) * 64 + c * 8 + 4];
                sx[0] += v0.x; sx[1] += v0.y; sx[2] += v0.z; sx[3] += v0.w;
                sx[4] += v1.x; sx[5] += v1.y; sx[6] += v1.z; sx[7] += v1.w;
            }
            __half2 h0 = __float22half2_rn(make_float2(sx[0], sx[1]));
            __half2 h1 = __float22half2_rn(make_float2(sx[2], sx[3]));
            __half2 h2 = __float22half2_rn(make_float2(sx[4], sx[5]));
            __half2 h3 = __float22half2_rn(make_float2(sx[6], sx[7]));
            uint32_t q0 = *(uint32_t*)&h0, q1 = *(uint32_t*)&h1;
            uint32_t q2 = *(uint32_t*)&h2, q3 = *(uint32_t*)&h3;
            asm volatile("st.shared.v4.b32 [%0], {%1,%2,%3,%4};"
                         :: "r"(dst), "r"(q0), "r"(q1), "r"(q2), "r"(q3));
        } else {
            STS_ZERO(dst);
        }
    }

    const int wm = (wid >> 1) * 32;
    const int wn = (wid & 1) * 32;
    const int qr = lane >> 2, qc = lane & 3;
    float fac[2][4][4] = {};

    for (int i = 0; i < 4; i++) {
        __syncthreads();
#pragma unroll
        for (int j = 0; j < 2; j++) {
            int f = tid + j * 256;
            int r = f >> 3, c = f & 7;
            CP16(w_s + r * 128 + ((c ^ (r & 7)) << 4),
                 Wa + (size_t)i * 4096 + r * 64 + c * 8);
        }
        CP_COMMIT();
        CP_WAIT(0);
        __syncthreads();

        float acc[2][4][4] = {};
        mma_tile_64(a_s, w_s, lane, wm, wn, acc);

#pragma unroll
        for (int mt = 0; mt < 2; mt++)
#pragma unroll
            for (int nt = 0; nt < 4; nt++) {
                int col = wn + nt * 8 + qc * 2;
                float2 bv = *(const float2*)&ab[i * 64 + col];
                float2 sv = *(const float2*)&as_[i * 64 + col];
                float2 b2 = *(const float2*)&abb[i * 64 + col];
                int r0 = m0 + wm + mt * 16 + qr;
                int r1 = r0 + 8;
                if (r0 < MP) {
                    float2 mv = *(const float2*)&ms[((size_t)i * MP + r0) * 64 + col];
                    float a0 = 1.0f / (1.0f + __expf(-((acc[mt][nt][0] + bv.x) * sv.x + b2.x)));
                    float a1 = 1.0f / (1.0f + __expf(-((acc[mt][nt][1] + bv.y) * sv.y + b2.y)));
                    fac[mt][nt][0] += a0 * mv.x;
                    fac[mt][nt][1] += a1 * mv.y;
                }
                if (r1 < MP) {
                    float2 mv = *(const float2*)&ms[((size_t)i * MP + r1) * 64 + col];
                    float a2 = 1.0f / (1.0f + __expf(-((acc[mt][nt][2] + bv.x) * sv.x + b2.x)));
                    float a3 = 1.0f / (1.0f + __expf(-((acc[mt][nt][3] + bv.y) * sv.y + b2.y)));
                    fac[mt][nt][2] += a2 * mv.x;
                    fac[mt][nt][3] += a3 * mv.y;
                }
            }
    }

#pragma unroll
    for (int mt = 0; mt < 2; mt++)
#pragma unroll
        for (int nt = 0; nt < 4; nt++) {
            int col = wn + nt * 8 + qc * 2;
            int r0 = m0 + wm + mt * 16 + qr;
            int r1 = r0 + 8;
            if (r0 < MP) *(float2*)&fused[(size_t)r0 * 64 + col] =
                make_float2(fac[mt][nt][0], fac[mt][nt][1]);
            if (r1 < MP) *(float2*)&fused[(size_t)r1 * 64 + col] =
                make_float2(fac[mt][nt][2], fac[mt][nt][3]);
        }
}

// ================================ N=20 heads ==================================
__global__ __launch_bounds__(256) void gemm_n20_kernel(
    const float* __restrict__ X, const float* __restrict__ W,
    const float* __restrict__ b, float* __restrict__ out) {
    __shared__ float Xs[128 * 68];
    __shared__ float Ws[64 * 20];
    __shared__ float bs[20];
    const int tid = threadIdx.x;
    const int m0 = blockIdx.x * 128;
#pragma unroll
    for (int j = 0; j < 8; j++) {
        int f = tid + 256 * j;
        int r = f >> 4, c4 = f & 15;
        int m = m0 + r;
        float4 v = make_float4(0.f, 0.f, 0.f, 0.f);
        if (m < MP) v = *(const float4*)&X[(size_t)m * 64 + c4 * 4];
        *(float4*)&Xs[r * 68 + c4 * 4] = v;
    }
    for (int f = tid; f < 64 * 20; f += 256) Ws[f] = W[f];
    if (tid < 20) bs[tid] = b[tid];
    __syncthreads();
    int r = tid >> 1, half = tid & 1, n0 = half * 10;
    int m = m0 + r;
    if (m < MP) {
        float acc[10];
#pragma unroll
        for (int j = 0; j < 10; j++) acc[j] = bs[n0 + j];
#pragma unroll 8
        for (int c = 0; c < 64; c++) {
            float x = Xs[r * 68 + c];
#pragma unroll
            for (int j = 0; j < 10; j++) acc[j] += x * Ws[c * 20 + n0 + j];
        }
#pragma unroll
        for (int j = 0; j < 10; j++) out[(size_t)m * 20 + n0 + j] = acc[j];
    }
}

// ==============================================================================
extern "C" void kernel_launch(void* const* d_in, const int* in_sizes, int n_in,
                              void* d_out, int out_size) {
    const float* feats   = (const float*)d_in[0];
    const float* w1a     = (const float*)d_in[1];
    const float* s1a     = (const float*)d_in[2];
    const float* b1a     = (const float*)d_in[3];
    const float* w3      = (const float*)d_in[4];
    const float* s3      = (const float*)d_in[5];
    const float* b3      = (const float*)d_in[6];
    const float* w1b     = (const float*)d_in[7];
    const float* s1b     = (const float*)d_in[8];
    const float* b1b     = (const float*)d_in[9];
    const float* aux_w   = (const float*)d_in[10];
    const float* aux_b   = (const float*)d_in[11];
    const float* proj_w  = (const float*)d_in[12];
    const float* proj_b  = (const float*)d_in[13];
    const float* proj_s  = (const float*)d_in[14];
    const float* proj_bb = (const float*)d_in[15];
    const float* attn_w  = (const float*)d_in[16];
    const float* attn_b  = (const float*)d_in[17];
    const float* attn_s  = (const float*)d_in[18];
    const float* attn_bb = (const float*)d_in[19];
    const float* head_w  = (const float*)d_in[20];
    const float* head_b  = (const float*)d_in[21];
    const int*   nbr     = (const int*)d_in[22];
    const int*   inv     = (const int*)d_in[23];

    float* out    = (float*)d_out;
    float* fused  = out;
    float* logits = out + (size_t)MP * 64;
    float* aux    = out + (size_t)MP * 84;

    float *pV, *pms, *pvs, *pvc, *pacc;
    __half *pH16, *pW1a, *pW1b, *pWp, *pWa, *pW13, *pW3n;
    int2 *pent; int *pecnt;
    cudaGetSymbolAddress((void**)&pV, g_V);
    cudaGetSymbolAddress((void**)&pms, g_ms);
    cudaGetSymbolAddress((void**)&pvs, g_vsum4);
    cudaGetSymbolAddress((void**)&pvc, g_vcnt4);
    cudaGetSymbolAddress((void**)&pacc, g_acc);
    cudaGetSymbolAddress((void**)&pH16, g_H16);
    cudaGetSymbolAddress((void**)&pW1a, g_W1a16);
    cudaGetSymbolAddress((void**)&pW1b, g_W1b16);
    cudaGetSymbolAddress((void**)&pWp, g_Wp16);
    cudaGetSymbolAddress((void**)&pWa, g_Wa16);
    cudaGetSymbolAddress((void**)&pW13, g_W13t);
    cudaGetSymbolAddress((void**)&pW3n, g_W3n);
    cudaGetSymbolAddress((void**)&pent, g_ent);
    cudaGetSymbolAddress((void**)&pecnt, g_ecnt);

    cudaFuncSetAttribute(gemm64h3f_kernel, cudaFuncAttributeMaxDynamicSharedMemorySize, T3_TOT);

    wprep_kernel<<<320, 256>>>(w1a, w1b, proj_w, attn_w, w3,
                               pW1a, pW1b, pWp, pWa, pW13, pecnt);
    w3n_kernel<<<1728, 256>>>(w3, pW3n);
    entprep_kernel<<<469, 256>>>(nbr, pent, pecnt);

    // layer 0 input: feats (fp32) -> H (fp16) and acc init (self tap)
    gemm64hf2_kernel<<<GTC, 256>>>(feats, pW1a, s1a, b1a, pW13, pH16, pacc);
    for (int i = 0; i < 4; i++) {
        {
            dim3 grid(128, 26);
            sparse_conv_kernel<<<grid, 256>>>(pH16, pW3n + (size_t)i * 27 * 4096,
                                              pent, pecnt, pacc);
        }
        if (i < 3) {
            gemm64h3f_kernel<<<GTC, 256, T3_TOT>>>(pacc, s3 + i * 64, b3 + i * 64,
                                           pW1b + (size_t)i * 4096, s1b + i * 64, b1b + i * 64,
                                           pW1a + (size_t)(i + 1) * 4096, s1a + (i + 1) * 64,
                                           b1a + (i + 1) * 64,
                                           pW13 + (size_t)(i + 1) * 4096,
                                           pH16, pacc);
        } else {
            gemm64h_resf_kernel<<<GTC, 256>>>(pacc, s3 + i * 64, b3 + i * 64,
                                              pW1b + (size_t)i * 4096, s1b + i * 64,
                                              b1b + i * 64, pV, feats);
        }
    }

    gemm_n20_kernel<<<938, 256>>>(pV, aux_w, aux_b, aux);

    zero_all_kernel<<<30000, 256>>>(pvs, pvc);
    scatter_all_kernel<<<120000, 256>>>(pV, inv, pvs, pvc);
    {
        dim3 grid(GTC, 4);
        proj_mma_kernel<<<grid, 256>>>(pV, inv, pvs, pvc, pWp,
                                       proj_b, proj_s, proj_bb, pms);
    }
    attn_mma_kernel<<<GTC, 256>>>(pms, pWa, attn_b, attn_s, attn_bb, fused);
    gemm_n20_kernel<<<938, 256>>>(fused, head_w, head_b, logits);
}

// round 15
// speedup vs baseline: 1.6760x; 1.0241x over previous
#include <cuda_runtime.h>
#include <cuda_fp16.h>
#include <math.h>
#include <stdint.h>

#define MP 120000
#define GTC 938     // ceil(MP / 128)

// ---------------- scratch (static device globals; no runtime allocs) ----------
__device__ float  g_V[MP * 64];
__device__ __half g_H16[MP * 64];
__device__ float  g_acc[MP * 64];        // conv fp32 accumulator
__device__ __half g_W1a16[4 * 4096];
__device__ __half g_W1b16[4 * 4096];
__device__ __half g_Wp16[4 * 4096];
__device__ __half g_Wa16[4 * 4096];
__device__ __half g_W13t[4 * 4096];      // tap-13 weights transposed [d][c] fp16
__device__ __half g_W3n[4 * 27 * 4096];  // conv weights original [c][d] fp16
__device__ int2   g_ent[26 * MP];        // valid (m, src) pairs per non-self tap
__device__ int    g_ecnt[26];
__device__ __half g_ms16[4 * MP * 64];   // multi-scale features (fp16)
__device__ float  g_vsum4[4 * MP * 64];
__device__ float  g_vcnt4[4 * MP];

__device__ __forceinline__ float lrelu(float x, float a) { return x > 0.f ? x : a * x; }

__device__ __forceinline__ uint32_t smem_u32(const void* p) {
    uint32_t a;
    asm("{ .reg .u64 t; cvta.to.shared.u64 t, %1; cvt.u32.u64 %0, t; }" : "=r"(a) : "l"(p));
    return a;
}

__device__ __forceinline__ void ldm4(uint32_t r[4], uint32_t addr) {
    asm volatile("ldmatrix.sync.aligned.m8n8.x4.shared.b16 {%0,%1,%2,%3}, [%4];"
                 : "=r"(r[0]), "=r"(r[1]), "=r"(r[2]), "=r"(r[3]) : "r"(addr));
}

__device__ __forceinline__ void mma16816(float c[4], const uint32_t a[4],
                                         uint32_t b0, uint32_t b1) {
    asm volatile(
        "mma.sync.aligned.m16n8k16.row.col.f32.f16.f16.f32 "
        "{%0,%1,%2,%3},{%4,%5,%6,%7},{%8,%9},{%0,%1,%2,%3};"
        : "+f"(c[0]), "+f"(c[1]), "+f"(c[2]), "+f"(c[3])
        : "r"(a[0]), "r"(a[1]), "r"(a[2]), "r"(a[3]), "r"(b0), "r"(b1));
}

#define CP16(dst, src) \
    asm volatile("cp.async.cg.shared.global [%0], [%1], 16;" :: "r"(dst), "l"(src))
#define CP_COMMIT() asm volatile("cp.async.commit_group;" ::: "memory")
#define CP_WAIT(n)  asm volatile("cp.async.wait_group %0;" :: "n"(n) : "memory")
#define STS_ZERO(dst) do { uint32_t _z = 0; \
    asm volatile("st.shared.v4.b32 [%0], {%1,%1,%1,%1};" :: "r"(dst), "r"(_z)); } while (0)

// ========== MMA core (M-tile 128): A(128x64) x W(64x64)^T, 8 warps ============
__device__ __forceinline__ void mma_tile_64(uint32_t a_s, uint32_t w_s,
                                            int lane, int wm, int wn,
                                            float acc[2][4][4]) {
#pragma unroll
    for (int kb = 0; kb < 4; kb++) {
        uint32_t a[2][4], wh[2][4];
#pragma unroll
        for (int mt = 0; mt < 2; mt++) {
            int r = wm + mt * 16 + (lane & 15);
            int lc = kb * 2 + (lane >> 4);
            ldm4(a[mt], a_s + r * 128 + ((lc ^ (r & 7)) << 4));
        }
#pragma unroll
        for (int np = 0; np < 2; np++) {
            int r = wn + np * 16 + (lane & 7) + ((lane & 16) ? 8 : 0);
            int lc = kb * 2 + ((lane >> 3) & 1);
            ldm4(wh[np], w_s + r * 128 + ((lc ^ (r & 7)) << 4));
        }
#pragma unroll
        for (int mt = 0; mt < 2; mt++)
#pragma unroll
            for (int nt = 0; nt < 4; nt++) {
                int np = nt >> 1, q = (nt & 1) * 2;
                mma16816(acc[mt][nt], a[mt], wh[np][q], wh[np][q + 1]);
            }
    }
}

// epi helper: write fp16 lrelu result into swizzled smem tile
__device__ __forceinline__ void epi_to_smem(char* sm, int lr0, int lr1, int col,
                                            float v0, float v1, float v2, float v3) {
    __half2 h0 = __float22half2_rn(make_float2(v0, v1));
    __half2 h1 = __float22half2_rn(make_float2(v2, v3));
    uint32_t d0 = lr0 * 128 + (((col >> 3) ^ (lr0 & 7)) << 4) + ((col * 2) & 15);
    uint32_t d1 = lr1 * 128 + (((col >> 3) ^ (lr1 & 7)) << 4) + ((col * 2) & 15);
    *(__half2*)(sm + d0) = h0;
    *(__half2*)(sm + d1) = h1;
}

// read one fp16 value from swizzled smem tile
__device__ __forceinline__ float smem_h(const char* sm, int r, int c) {
    uint32_t off = r * 128 + (((c >> 3) ^ (r & 7)) << 4) + ((c & 7) * 2);
    return __half2float(*(const __half*)(sm + off));
}

// ====== weight prep: transpose+fp16 for 1x1/proj/attn/W13t; zero ecnt =========
__global__ void wprep_kernel(const float* __restrict__ w1a, const float* __restrict__ w1b,
                             const float* __restrict__ wp, const float* __restrict__ wa,
                             const float* __restrict__ w3,
                             __half* __restrict__ o1a, __half* __restrict__ o1b,
                             __half* __restrict__ op, __half* __restrict__ oa,
                             __half* __restrict__ o13, int* __restrict__ ecnt) {
    int g = blockIdx.x * 256 + threadIdx.x;
    if (g < 26) ecnt[g] = 0;
    if (g >= 20 * 4096) return;
    int t = g >> 12;
    int rc = g & 4095;
    int d = rc >> 6, c = rc & 63;
    if (t < 4)
        o1a[(size_t)t * 4096 + d * 64 + c] = __float2half_rn(w1a[(size_t)t * 4096 + c * 64 + d]);
    else if (t < 8)
        o1b[(size_t)(t - 4) * 4096 + d * 64 + c] = __float2half_rn(w1b[(size_t)(t - 4) * 4096 + c * 64 + d]);
    else if (t < 12)
        op[(size_t)(t - 8) * 4096 + d * 64 + c] = __float2half_rn(wp[(size_t)(t - 8) * 4096 + c * 64 + d]);
    else if (t < 16)
        oa[(size_t)(t - 12) * 4096 + d * 64 + c] = __float2half_rn(wa[(size_t)(t - 12) * 4096 + c * 64 + d]);
    else {
        int lt = t - 16;
        o13[(size_t)lt * 4096 + d * 64 + c] =
            __float2half_rn(w3[((size_t)lt * 27 + 13) * 4096 + c * 64 + d]);
    }
}

__global__ void w3n_kernel(const float* __restrict__ w3, __half* __restrict__ o) {
    int g = blockIdx.x * 256 + threadIdx.x;
    if (g >= 4 * 27 * 4096) return;
    o[g] = __float2half_rn(w3[g]);
}

__global__ void entprep_kernel(const int* __restrict__ nbr,
                               int2* __restrict__ ent, int* __restrict__ ecnt) {
    int m = blockIdx.x * 256 + threadIdx.x;
    if (m >= MP) return;
#pragma unroll
    for (int k = 0; k < 27; k++) {
        if (k == 13) continue;
        int src = nbr[(size_t)m * 27 + k];
        if (src >= 0) {
            int idx = (k < 13) ? k : k - 1;
            int pos = atomicAdd(&ecnt[idx], 1);
            ent[(size_t)idx * MP + pos] = make_int2(m, src);
        }
    }
}

// ==== first layer fused: fp32 feats -> w1a epi -> H16 out; H @ W13 -> acc =====
__global__ __launch_bounds__(256) void gemm64hf2_kernel(
    const float* __restrict__ Xf, const __half* __restrict__ W,
    const float* __restrict__ s, const float* __restrict__ b,
    const __half* __restrict__ W13,
    __half* __restrict__ outh, float* __restrict__ accout) {
    __shared__ __align__(16) char smA[16384];
    __shared__ __align__(16) char smB[16384];
    __shared__ __align__(16) char smW[8192];
    __shared__ __align__(16) char smW13[8192];
    const uint32_t a_s = smem_u32(smA);
    const uint32_t b_s = smem_u32(smB);
    const uint32_t w_s = smem_u32(smW);
    const uint32_t w13_s = smem_u32(smW13);
    const int tid = threadIdx.x;
    const int lane = tid & 31, wid = tid >> 5;
    const int m0 = blockIdx.x * 128;

#pragma unroll
    for (int j = 0; j < 2; j++) {
        int f = tid + j * 256;
        int r = f >> 3, c = f & 7;
        CP16(w_s + r * 128 + ((c ^ (r & 7)) << 4), W + (size_t)r * 64 + c * 8);
        CP16(w13_s + r * 128 + ((c ^ (r & 7)) << 4), W13 + (size_t)r * 64 + c * 8);
    }
    CP_COMMIT();
#pragma unroll
    for (int j = 0; j < 4; j++) {
        int f = tid + j * 256;
        int r = f >> 3, c = f & 7;
        uint32_t dst = a_s + r * 128 + ((c ^ (r & 7)) << 4);
        int m = m0 + r;
        if (m < MP) {
            float4 v0 = *(const float4*)&Xf[(size_t)m * 64 + c * 8];
            float4 v1 = *(const float4*)&Xf[(size_t)m * 64 + c * 8 + 4];
            __half2 h0 = __float22half2_rn(make_float2(v0.x, v0.y));
            __half2 h1 = __float22half2_rn(make_float2(v0.z, v0.w));
            __half2 h2 = __float22half2_rn(make_float2(v1.x, v1.y));
            __half2 h3 = __float22half2_rn(make_float2(v1.z, v1.w));
            uint32_t q0 = *(uint32_t*)&h0, q1 = *(uint32_t*)&h1;
            uint32_t q2 = *(uint32_t*)&h2, q3 = *(uint32_t*)&h3;
            asm volatile("st.shared.v4.b32 [%0], {%1,%2,%3,%4};"
                         :: "r"(dst), "r"(q0), "r"(q1), "r"(q2), "r"(q3));
        } else {
            STS_ZERO(dst);
        }
    }
    CP_WAIT(0);
    __syncthreads();

    const int wm = (wid >> 1) * 32;
    const int wn = (wid & 1) * 32;
    const int qr = lane >> 2, qc = lane & 3;

    float acc[2][4][4] = {};
    mma_tile_64(a_s, w_s, lane, wm, wn, acc);

#pragma unroll
    for (int mt = 0; mt < 2; mt++)
#pragma unroll
        for (int nt = 0; nt < 4; nt++) {
            int col = wn + nt * 8 + qc * 2;
            float2 s2 = *(const float2*)&s[col];
            float2 b2 = *(const float2*)&b[col];
            int lr0 = wm + mt * 16 + qr;
            int lr1 = lr0 + 8;
            int r0 = m0 + lr0, r1 = m0 + lr1;
            float v0 = lrelu(acc[mt][nt][0] * s2.x + b2.x, 0.01f);
            float v1 = lrelu(acc[mt][nt][1] * s2.y + b2.y, 0.01f);
            float v2 = lrelu(acc[mt][nt][2] * s2.x + b2.x, 0.01f);
            float v3 = lrelu(acc[mt][nt][3] * s2.y + b2.y, 0.01f);
            epi_to_smem(smB, lr0, lr1, col, v0, v1, v2, v3);
            if (r0 < MP) *(__half2*)&outh[(size_t)r0 * 64 + col] =
                __float22half2_rn(make_float2(v0, v1));
            if (r1 < MP) *(__half2*)&outh[(size_t)r1 * 64 + col] =
                __float22half2_rn(make_float2(v2, v3));
        }
    __syncthreads();

    float acc2[2][4][4] = {};
    mma_tile_64(b_s, w13_s, lane, wm, wn, acc2);

#pragma unroll
    for (int mt = 0; mt < 2; mt++)
#pragma unroll
        for (int nt = 0; nt < 4; nt++) {
            int col = wn + nt * 8 + qc * 2;
            int r0 = m0 + wm + mt * 16 + qr;
            int r1 = r0 + 8;
            if (r0 < MP) *(float2*)&accout[(size_t)r0 * 64 + col] =
                make_float2(acc2[mt][nt][0], acc2[mt][nt][1]);
            if (r1 < MP) *(float2*)&accout[(size_t)r1 * 64 + col] =
                make_float2(acc2[mt][nt][2], acc2[mt][nt][3]);
        }
}

// ======= sparse conv: acc[m] += H[src] @ W3[tap], chunk-stride grid ===========
__global__ __launch_bounds__(256) void sparse_conv_kernel(
    const __half* __restrict__ H, const __half* __restrict__ W3n,
    const int2* __restrict__ ent, const int* __restrict__ ecnt,
    float* __restrict__ acc) {
    const int kk = blockIdx.y;             // 0..25
    const int cnt = ecnt[kk];
    if ((int)(blockIdx.x * 64) >= cnt) return;
    const int tap = (kk < 13) ? kk : kk + 1;

    __shared__ __align__(16) __half Ws[64 * 64];   // [c][j]
    __shared__ __align__(16) __half Hs[64][64];
    __shared__ int2 es[64];
    const int tid = threadIdx.x;

    const uint4* wsrc = (const uint4*)(W3n + (size_t)tap * 4096);
#pragma unroll
    for (int j = 0; j < 2; j++)
        ((uint4*)Ws)[tid + j * 256] = wsrc[tid + j * 256];

    const int wrp = tid >> 5, lane = tid & 31;

    for (int base = blockIdx.x * 64; base < cnt; base += gridDim.x * 64) {
        __syncthreads();
        if (tid < 64) {
            int e = base + tid;
            es[tid] = (e < cnt) ? ent[(size_t)kk * MP + e] : make_int2(-1, -1);
        }
        __syncthreads();
        {
            int e = tid >> 2, q = tid & 3;
            int src = es[e].y;
            if (src >= 0) {
                *(uint4*)&Hs[e][q * 8]      = *(const uint4*)&H[(size_t)src * 64 + q * 8];
                *(uint4*)&Hs[e][32 + q * 8] = *(const uint4*)&H[(size_t)src * 64 + 32 + q * 8];
            }
        }
        __syncthreads();

#pragma unroll
        for (int ei = 0; ei < 8; ei++) {
            int e = wrp * 8 + ei;
            int m = es[e].x;
            if (m < 0) continue;
            float v0 = 0.f, v1 = 0.f;
#pragma unroll
            for (int d = 0; d < 64; d++) {
                float h = __half2float(Hs[e][d]);
                float2 wf = __half22float2(*(const __half2*)&Ws[d * 64 + lane * 2]);
                v0 += h * wf.x;
                v1 += h * wf.y;
            }
            atomicAdd(&acc[(size_t)m * 64 + lane * 2], v0);
            atomicAdd(&acc[(size_t)m * 64 + lane * 2 + 1], v1);
        }
    }
}

// === fused triple (DYNAMIC smem 56KB): conv-epi(acc) -> @W1b -> epi ->
//     @W1a_next -> epi -> H16; then H @ W13_next -> accout =====================
#define T3_A    0
#define T3_B    16384
#define T3_W1   32768
#define T3_W2   40960
#define T3_W13  49152
#define T3_TOT  57344

__global__ __launch_bounds__(256) void gemm64h3f_kernel(
    const float* __restrict__ accin, const float* __restrict__ cs, const float* __restrict__ cb,
    const __half* __restrict__ W1, const float* __restrict__ s1, const float* __restrict__ b1,
    const __half* __restrict__ W2, const float* __restrict__ s2, const float* __restrict__ b2,
    const __half* __restrict__ W13,
    __half* __restrict__ outh, float* __restrict__ accout) {
    extern __shared__ __align__(16) char smd[];
    char* smA = smd + T3_A;
    char* smB = smd + T3_B;
    const uint32_t a_s = smem_u32(smd) + T3_A;
    const uint32_t b_s = smem_u32(smd) + T3_B;
    const uint32_t w1_s = smem_u32(smd) + T3_W1;
    const uint32_t w2_s = smem_u32(smd) + T3_W2;
    const uint32_t w13_s = smem_u32(smd) + T3_W13;
    const int tid = threadIdx.x;
    const int lane = tid & 31, wid = tid >> 5;
    const int m0 = blockIdx.x * 128;

#pragma unroll
    for (int j = 0; j < 2; j++) {
        int f = tid + j * 256;
        int r = f >> 3, c = f & 7;
        CP16(w1_s + r * 128 + ((c ^ (r & 7)) << 4), W1 + (size_t)r * 64 + c * 8);
        CP16(w2_s + r * 128 + ((c ^ (r & 7)) << 4), W2 + (size_t)r * 64 + c * 8);
        CP16(w13_s + r * 128 + ((c ^ (r & 7)) << 4), W13 + (size_t)r * 64 + c * 8);
    }
    CP_COMMIT();
#pragma unroll
    for (int j = 0; j < 4; j++) {
        int f = tid + j * 256;
        int r = f >> 3, c = f & 7;
        uint32_t dst = a_s + r * 128 + ((c ^ (r & 7)) << 4);
        int m = m0 + r;
        if (m < MP) {
            float4 v0 = *(const float4*)&accin[(size_t)m * 64 + c * 8];
            float4 v1 = *(const float4*)&accin[(size_t)m * 64 + c * 8 + 4];
            float4 s0 = *(const float4*)&cs[c * 8];
            float4 s1v = *(const float4*)&cs[c * 8 + 4];
            float4 b0 = *(const float4*)&cb[c * 8];
            float4 b1v = *(const float4*)&cb[c * 8 + 4];
            __half2 h0 = __float22half2_rn(make_float2(lrelu(v0.x * s0.x + b0.x, 0.01f),
                                                       lrelu(v0.y * s0.y + b0.y, 0.01f)));
            __half2 h1 = __float22half2_rn(make_float2(lrelu(v0.z * s0.z + b0.z, 0.01f),
                                                       lrelu(v0.w * s0.w + b0.w, 0.01f)));
            __half2 h2 = __float22half2_rn(make_float2(lrelu(v1.x * s1v.x + b1v.x, 0.01f),
                                                       lrelu(v1.y * s1v.y + b1v.y, 0.01f)));
            __half2 h3 = __float22half2_rn(make_float2(lrelu(v1.z * s1v.z + b1v.z, 0.01f),
                                                       lrelu(v1.w * s1v.w + b1v.w, 0.01f)));
            uint32_t q0 = *(uint32_t*)&h0, q1 = *(uint32_t*)&h1;
            uint32_t q2 = *(uint32_t*)&h2, q3 = *(uint32_t*)&h3;
            asm volatile("st.shared.v4.b32 [%0], {%1,%2,%3,%4};"
                         :: "r"(dst), "r"(q0), "r"(q1), "r"(q2), "r"(q3));
        } else {
            STS_ZERO(dst);
        }
    }
    CP_WAIT(0);
    __syncthreads();

    const int wm = (wid >> 1) * 32;
    const int wn = (wid & 1) * 32;
    const int qr = lane >> 2, qc = lane & 3;

    float acc[2][4][4] = {};
    mma_tile_64(a_s, w1_s, lane, wm, wn, acc);

#pragma unroll
    for (int mt = 0; mt < 2; mt++)
#pragma unroll
        for (int nt = 0; nt < 4; nt++) {
            int col = wn + nt * 8 + qc * 2;
            float2 sv = *(const float2*)&s1[col];
            float2 bv = *(const float2*)&b1[col];
            int lr0 = wm + mt * 16 + qr;
            int lr1 = lr0 + 8;
            epi_to_smem(smB, lr0, lr1, col,
                        lrelu(acc[mt][nt][0] * sv.x + bv.x, 0.01f),
                        lrelu(acc[mt][nt][1] * sv.y + bv.y, 0.01f),
                        lrelu(acc[mt][nt][2] * sv.x + bv.x, 0.01f),
                        lrelu(acc[mt][nt][3] * sv.y + bv.y, 0.01f));
        }
    __syncthreads();

    float acc2[2][4][4] = {};
    mma_tile_64(b_s, w2_s, lane, wm, wn, acc2);
    __syncthreads();

#pragma unroll
    for (int mt = 0; mt < 2; mt++)
#pragma unroll
        for (int nt = 0; nt < 4; nt++) {
            int col = wn + nt * 8 + qc * 2;
            float2 sv = *(const float2*)&s2[col];
            float2 bv = *(const float2*)&b2[col];
            int lr0 = wm + mt * 16 + qr;
            int lr1 = lr0 + 8;
            int r0 = m0 + lr0, r1 = m0 + lr1;
            float v0 = lrelu(acc2[mt][nt][0] * sv.x + bv.x, 0.01f);
            float v1 = lrelu(acc2[mt][nt][1] * sv.y + bv.y, 0.01f);
            float v2 = lrelu(acc2[mt][nt][2] * sv.x + bv.x, 0.01f);
            float v3 = lrelu(acc2[mt][nt][3] * sv.y + bv.y, 0.01f);
            epi_to_smem(smA, lr0, lr1, col, v0, v1, v2, v3);
            if (r0 < MP) *(__half2*)&outh[(size_t)r0 * 64 + col] =
                __float22half2_rn(make_float2(v0, v1));
            if (r1 < MP) *(__half2*)&outh[(size_t)r1 * 64 + col] =
                __float22half2_rn(make_float2(v2, v3));
        }
    __syncthreads();

    float acc3[2][4][4] = {};
    mma_tile_64(a_s, w13_s, lane, wm, wn, acc3);

#pragma unroll
    for (int mt = 0; mt < 2; mt++)
#pragma unroll
        for (int nt = 0; nt < 4; nt++) {
            int col = wn + nt * 8 + qc * 2;
            int r0 = m0 + wm + mt * 16 + qr;
            int r1 = r0 + 8;
            if (r0 < MP) *(float2*)&accout[(size_t)r0 * 64 + col] =
                make_float2(acc3[mt][nt][0], acc3[mt][nt][1]);
            if (r1 < MP) *(float2*)&accout[(size_t)r1 * 64 + col] =
                make_float2(acc3[mt][nt][2], acc3[mt][nt][3]);
        }
}

// === fused last: conv-epi(acc) -> @W1b -> epi + residual -> V fp32
//     + aux head: aux = V @ aux_w + aux_b (V staged fp16 in smem) ==============
__global__ __launch_bounds__(256) void gemm64h_resf_kernel(
    const float* __restrict__ accin, const float* __restrict__ cs, const float* __restrict__ cb,
    const __half* __restrict__ W, const float* __restrict__ s, const float* __restrict__ b,
    float* __restrict__ outf, const float* __restrict__ feats,
    const float* __restrict__ aux_w, const float* __restrict__ aux_b,
    float* __restrict__ aux) {
    __shared__ __align__(16) char smA[16384];
    __shared__ __align__(16) char smW[8192];
    __shared__ float Ws20[64 * 20];
    __shared__ float bs20[20];
    const uint32_t a_s = smem_u32(smA);
    const uint32_t w_s = smem_u32(smW);
    const int tid = threadIdx.x;
    const int lane = tid & 31, wid = tid >> 5;
    const int m0 = blockIdx.x * 128;

#pragma unroll
    for (int j = 0; j < 2; j++) {
        int f = tid + j * 256;
        int r = f >> 3, c = f & 7;
        CP16(w_s + r * 128 + ((c ^ (r & 7)) << 4), W + (size_t)r * 64 + c * 8);
    }
    CP_COMMIT();
    for (int f = tid; f < 64 * 20; f += 256) Ws20[f] = aux_w[f];
    if (tid < 20) bs20[tid] = aux_b[tid];
#pragma unroll
    for (int j = 0; j < 4; j++) {
        int f = tid + j * 256;
        int r = f >> 3, c = f & 7;
        uint32_t dst = a_s + r * 128 + ((c ^ (r & 7)) << 4);
        int m = m0 + r;
        if (m < MP) {
            float4 v0 = *(const float4*)&accin[(size_t)m * 64 + c * 8];
            float4 v1 = *(const float4*)&accin[(size_t)m * 64 + c * 8 + 4];
            float4 s0 = *(const float4*)&cs[c * 8];
            float4 s1v = *(const float4*)&cs[c * 8 + 4];
            float4 b0 = *(const float4*)&cb[c * 8];
            float4 b1v = *(const float4*)&cb[c * 8 + 4];
            __half2 h0 = __float22half2_rn(make_float2(lrelu(v0.x * s0.x + b0.x, 0.01f),
                                                       lrelu(v0.y * s0.y + b0.y, 0.01f)));
            __half2 h1 = __float22half2_rn(make_float2(lrelu(v0.z * s0.z + b0.z, 0.01f),
                                                       lrelu(v0.w * s0.w + b0.w, 0.01f)));
            __half2 h2 = __float22half2_rn(make_float2(lrelu(v1.x * s1v.x + b1v.x, 0.01f),
                                                       lrelu(v1.y * s1v.y + b1v.y, 0.01f)));
            __half2 h3 = __float22half2_rn(make_float2(lrelu(v1.z * s1v.z + b1v.z, 0.01f),
                                                       lrelu(v1.w * s1v.w + b1v.w, 0.01f)));
            uint32_t q0 = *(uint32_t*)&h0, q1 = *(uint32_t*)&h1;
            uint32_t q2 = *(uint32_t*)&h2, q3 = *(uint32_t*)&h3;
            asm volatile("st.shared.v4.b32 [%0], {%1,%2,%3,%4};"
                         :: "r"(dst), "r"(q0), "r"(q1), "r"(q2), "r"(q3));
        } else {
            STS_ZERO(dst);
        }
    }
    CP_WAIT(0);
    __syncthreads();

    const int wm = (wid >> 1) * 32;
    const int wn = (wid & 1) * 32;
    float acc[2][4][4] = {};
    mma_tile_64(a_s, w_s, lane, wm, wn, acc);
    __syncthreads();   // all warps done reading smA before V staging

    const int qr = lane >> 2, qc = lane & 3;
#pragma unroll
    for (int mt = 0; mt < 2; mt++)
#pragma unroll
        for (int nt = 0; nt < 4; nt++) {
            int col = wn + nt * 8 + qc * 2;
            float2 sv = *(const float2*)&s[col];
            float2 bv = *(const float2*)&b[col];
            int lr0 = wm + mt * 16 + qr;
            int lr1 = lr0 + 8;
            int r0 = m0 + lr0, r1 = m0 + lr1;
            float v0 = 0.f, v1 = 0.f, v2 = 0.f, v3 = 0.f;
            if (r0 < MP) {
                float2 fr = *(const float2*)&feats[(size_t)r0 * 64 + col];
                v0 = lrelu(lrelu(acc[mt][nt][0] * sv.x + bv.x, 0.01f) + fr.x, 0.1f);
                v1 = lrelu(lrelu(acc[mt][nt][1] * sv.y + bv.y, 0.01f) + fr.y, 0.1f);
                *(float2*)&outf[(size_t)r0 * 64 + col] = make_float2(v0, v1);
            }
            if (r1 < MP) {
                float2 fr = *(const float2*)&feats[(size_t)r1 * 64 + col];
                v2 = lrelu(lrelu(acc[mt][nt][2] * sv.x + bv.x, 0.01f) + fr.x, 0.1f);
                v3 = lrelu(lrelu(acc[mt][nt][3] * sv.y + bv.y, 0.01f) + fr.y, 0.1f);
                *(float2*)&outf[(size_t)r1 * 64 + col] = make_float2(v2, v3);
            }
            epi_to_smem(smA, lr0, lr1, col, v0, v1, v2, v3);
        }
    __syncthreads();

    // aux head: 128 rows, 2 threads/row (10 cols each)
    {
        int r = tid >> 1, n0 = (tid & 1) * 10;
        int m = m0 + r;
        if (m < MP) {
            float accn[10];
#pragma unroll
            for (int j = 0; j < 10; j++) accn[j] = bs20[n0 + j];
#pragma unroll 8
            for (int c = 0; c < 64; c++) {
                float x = smem_h(smA, r, c);
#pragma unroll
                for (int j = 0; j < 10; j++) accn[j] += x * Ws20[c * 20 + n0 + j];
            }
#pragma unroll
            for (int j = 0; j < 10; j++) aux[(size_t)m * 20 + n0 + j] = accn[j];
        }
    }
}

// =================== batched scatter-mean over all 4 scales ===================
__global__ void zero_all_kernel(float* __restrict__ vsum4, float* __restrict__ vcnt4) {
    int gid = blockIdx.x * 256 + threadIdx.x;
    if (gid < 4 * MP * 16) ((float4*)vsum4)[gid] = make_float4(0.f, 0.f, 0.f, 0.f);
    if (gid < 4 * MP) vcnt4[gid] = 0.f;
}

__global__ void scatter_all_kernel(const float* __restrict__ V, const int* __restrict__ inv,
                                   float* __restrict__ vsum4, float* __restrict__ vcnt4) {
    int gid = blockIdx.x * 256 + threadIdx.x;
    if (gid >= 4 * MP * 64) return;
    int si = gid / (MP * 64);
    int rem = gid - si * (MP * 64);
    int m = rem >> 6, c = rem & 63;
    int sg = inv[si * MP + m];
    atomicAdd(&vsum4[(size_t)si * MP * 64 + sg * 64 + c], V[rem]);
    if (c == 0) atomicAdd(&vcnt4[si * MP + sg], 1.0f);
}

// ============ tensorized proj: Os=(V-mean)*V (fp16) @ proj_w -> ms fp16 =======
__global__ __launch_bounds__(256) void proj_mma_kernel(
    const float* __restrict__ V, const int* __restrict__ inv,
    const float* __restrict__ vsum4, const float* __restrict__ vcnt4,
    const __half* __restrict__ Wp, const float* __restrict__ pb,
    const float* __restrict__ ps, const float* __restrict__ pbb,
    __half* __restrict__ ms) {
    __shared__ __align__(16) char smA[16384];
    __shared__ __align__(16) char smW[8192];
    const uint32_t a_s = smem_u32(smA);
    const uint32_t w_s = smem_u32(smW);
    const int tid = threadIdx.x;
    const int lane = tid & 31, wid = tid >> 5;
    const int m0 = blockIdx.x * 128;
    const int si = blockIdx.y;
    const int* seg = inv + (size_t)si * MP;
    const float* vsum = vsum4 + (size_t)si * MP * 64;
    const float* vcnt = vcnt4 + (size_t)si * MP;
    __half* msO = ms + (size_t)si * MP * 64;

#pragma unroll
    for (int j = 0; j < 2; j++) {
        int f = tid + j * 256;
        int r = f >> 3, c = f & 7;
        CP16(w_s + r * 128 + ((c ^ (r & 7)) << 4),
             Wp + (size_t)si * 4096 + r * 64 + c * 8);
    }
    CP_COMMIT();
#pragma unroll
    for (int j = 0; j < 4; j++) {
        int f = tid + j * 256;
        int r = f >> 3, c = f & 7;
        uint32_t dst = a_s + r * 128 + ((c ^ (r & 7)) << 4);
        int m = m0 + r;
        if (m < MP) {
            int sg = seg[m];
            float rc = 1.0f / fmaxf(vcnt[sg], 1.0f);
            float4 v0 = *(const float4*)&V[(size_t)m * 64 + c * 8];
            float4 v1 = *(const float4*)&V[(size_t)m * 64 + c * 8 + 4];
            float4 u0 = *(const float4*)&vsum[(size_t)sg * 64 + c * 8];
            float4 u1 = *(const float4*)&vsum[(size_t)sg * 64 + c * 8 + 4];
            __half2 h0 = __float22half2_rn(make_float2((v0.x - u0.x * rc) * v0.x,
                                                       (v0.y - u0.y * rc) * v0.y));
            __half2 h1 = __float22half2_rn(make_float2((v0.z - u0.z * rc) * v0.z,
                                                       (v0.w - u0.w * rc) * v0.w));
            __half2 h2 = __float22half2_rn(make_float2((v1.x - u1.x * rc) * v1.x,
                                                       (v1.y - u1.y * rc) * v1.y));
            __half2 h3 = __float22half2_rn(make_float2((v1.z - u1.z * rc) * v1.z,
                                                       (v1.w - u1.w * rc) * v1.w));
            uint32_t q0 = *(uint32_t*)&h0, q1 = *(uint32_t*)&h1;
            uint32_t q2 = *(uint32_t*)&h2, q3 = *(uint32_t*)&h3;
            asm volatile("st.shared.v4.b32 [%0], {%1,%2,%3,%4};"
                         :: "r"(dst), "r"(q0), "r"(q1), "r"(q2), "r"(q3));
        } else {
            STS_ZERO(dst);
        }
    }
    CP_WAIT(0);
    __syncthreads();

    const int wm = (wid >> 1) * 32;
    const int wn = (wid & 1) * 32;
    float acc[2][4][4] = {};
    mma_tile_64(a_s, w_s, lane, wm, wn, acc);

    const int qr = lane >> 2, qc = lane & 3;
#pragma unroll
    for (int mt = 0; mt < 2; mt++)
#pragma unroll
        for (int nt = 0; nt < 4; nt++) {
            int col = wn + nt * 8 + qc * 2;
            float2 bv = *(const float2*)&pb[si * 64 + col];
            float2 sv = *(const float2*)&ps[si * 64 + col];
            float2 b2 = *(const float2*)&pbb[si * 64 + col];
            int r0 = m0 + wm + mt * 16 + qr;
            int r1 = r0 + 8;
            if (r0 < MP) *(__half2*)&msO[(size_t)r0 * 64 + col] = __float22half2_rn(
                make_float2(lrelu((acc[mt][nt][0] + bv.x) * sv.x + b2.x, 0.01f),
                            lrelu((acc[mt][nt][1] + bv.y) * sv.y + b2.y, 0.01f)));
            if (r1 < MP) *(__half2*)&msO[(size_t)r1 * 64 + col] = __float22half2_rn(
                make_float2(lrelu((acc[mt][nt][2] + bv.x) * sv.x + b2.x, 0.01f),
                            lrelu((acc[mt][nt][3] + bv.y) * sv.y + b2.y, 0.01f)));
        }
}

// ===== attn: sumx in-kernel (fp16 ms), 4 GEMMs, fused out + head logits =======
__global__ __launch_bounds__(256) void attn_mma_kernel(
    const __half* __restrict__ ms, const __half* __restrict__ Wa,
    const float* __restrict__ ab, const float* __restrict__ as_,
    const float* __restrict__ abb, float* __restrict__ fused,
    const float* __restrict__ head_w, const float* __restrict__ head_b,
    float* __restrict__ logits) {
    __shared__ __align__(16) char smA[16384];
    __shared__ __align__(16) char smW[8192];
    __shared__ float Ws20[64 * 20];
    __shared__ float bs20[20];
    const uint32_t a_s = smem_u32(smA);
    const uint32_t w_s = smem_u32(smW);
    const int tid = threadIdx.x;
    const int lane = tid & 31, wid = tid >> 5;
    const int m0 = blockIdx.x * 128;

    for (int f = tid; f < 64 * 20; f += 256) Ws20[f] = head_w[f];
    if (tid < 20) bs20[tid] = head_b[tid];

#pragma unroll
    for (int j = 0; j < 4; j++) {
        int f = tid + j * 256;
        int r = f >> 3, c = f & 7;
        uint32_t dst = a_s + r * 128 + ((c ^ (r & 7)) << 4);
        int m = m0 + r;
        if (m < MP) {
            float sx[8] = {};
#pragma unroll
            for (int i = 0; i < 4; i++) {
                uint4 q = *(const uint4*)&ms[((size_t)i * MP + m) * 64 + c * 8];
                const __half2* hp = (const __half2*)&q;
#pragma unroll
                for (int t = 0; t < 4; t++) {
                    float2 fv = __half22float2(hp[t]);
                    sx[t * 2] += fv.x;
                    sx[t * 2 + 1] += fv.y;
                }
            }
            __half2 h0 = __float22half2_rn(make_float2(sx[0], sx[1]));
            __half2 h1 = __float22half2_rn(make_float2(sx[2], sx[3]));
            __half2 h2 = __float22half2_rn(make_float2(sx[4], sx[5]));
            __half2 h3 = __float22half2_rn(make_float2(sx[6], sx[7]));
            uint32_t q0 = *(uint32_t*)&h0, q1 = *(uint32_t*)&h1;
            uint32_t q2 = *(uint32_t*)&h2, q3 = *(uint32_t*)&h3;
            asm volatile("st.shared.v4.b32 [%0], {%1,%2,%3,%4};"
                         :: "r"(dst), "r"(q0), "r"(q1), "r"(q2), "r"(q3));
        } else {
            STS_ZERO(dst);
        }
    }

    const int wm = (wid >> 1) * 32;
    const int wn = (wid & 1) * 32;
    const int qr = lane >> 2, qc = lane & 3;
    float fac[2][4][4] = {};

    for (int i = 0; i < 4; i++) {
        __syncthreads();
#pragma unroll
        for (int j = 0; j < 2; j++) {
            int f = tid + j * 256;
            int r = f >> 3, c = f & 7;
            CP16(w_s + r * 128 + ((c ^ (r & 7)) << 4),
                 Wa + (size_t)i * 4096 + r * 64 + c * 8);
        }
        CP_COMMIT();
        CP_WAIT(0);
        __syncthreads();

        float acc[2][4][4] = {};
        mma_tile_64(a_s, w_s, lane, wm, wn, acc);

#pragma unroll
        for (int mt = 0; mt < 2; mt++)
#pragma unroll
            for (int nt = 0; nt < 4; nt++) {
                int col = wn + nt * 8 + qc * 2;
                float2 bv = *(const float2*)&ab[i * 64 + col];
                float2 sv = *(const float2*)&as_[i * 64 + col];
                float2 b2 = *(const float2*)&abb[i * 64 + col];
                int r0 = m0 + wm + mt * 16 + qr;
                int r1 = r0 + 8;
                if (r0 < MP) {
                    float2 mv = __half22float2(*(const __half2*)&ms[((size_t)i * MP + r0) * 64 + col]);
                    float a0 = 1.0f / (1.0f + __expf(-((acc[mt][nt][0] + bv.x) * sv.x + b2.x)));
                    float a1 = 1.0f / (1.0f + __expf(-((acc[mt][nt][1] + bv.y) * sv.y + b2.y)));
                    fac[mt][nt][0] += a0 * mv.x;
                    fac[mt][nt][1] += a1 * mv.y;
                }
                if (r1 < MP) {
                    float2 mv = __half22float2(*(const __half2*)&ms[((size_t)i * MP + r1) * 64 + col]);
                    float a2 = 1.0f / (1.0f + __expf(-((acc[mt][nt][2] + bv.x) * sv.x + b2.x)));
                    float a3 = 1.0f / (1.0f + __expf(-((acc[mt][nt][3] + bv.y) * sv.y + b2.y)));
                    fac[mt][nt][2] += a2 * mv.x;
                    fac[mt][nt][3] += a3 * mv.y;
                }
            }
    }
    __syncthreads();   // all warps done reading sumx tile before fused staging

#pragma unroll
    for (int mt = 0; mt < 2; mt++)
#pragma unroll
        for (int nt = 0; nt < 4; nt++) {
            int col = wn + nt * 8 + qc * 2;
            int lr0 = wm + mt * 16 + qr;
            int lr1 = lr0 + 8;
            int r0 = m0 + lr0, r1 = m0 + lr1;
            if (r0 < MP) *(float2*)&fused[(size_t)r0 * 64 + col] =
                make_float2(fac[mt][nt][0], fac[mt][nt][1]);
            if (r1 < MP) *(float2*)&fused[(size_t)r1 * 64 + col] =
                make_float2(fac[mt][nt][2], fac[mt][nt][3]);
            epi_to_smem(smA, lr0, lr1, col,
                        fac[mt][nt][0], fac[mt][nt][1], fac[mt][nt][2], fac[mt][nt][3]);
        }
    __syncthreads();

    // head logits: 128 rows, 2 threads/row (10 cols each), fused staged fp16
    {
        int r = tid >> 1, n0 = (tid & 1) * 10;
        int m = m0 + r;
        if (m < MP) {
            float accn[10];
#pragma unroll
            for (int j = 0; j < 10; j++) accn[j] = bs20[n0 + j];
#pragma unroll 8
            for (int c = 0; c < 64; c++) {
                float x = smem_h(smA, r, c);
#pragma unroll
                for (int j = 0; j < 10; j++) accn[j] += x * Ws20[c * 20 + n0 + j];
            }
#pragma unroll
            for (int j = 0; j < 10; j++) logits[(size_t)m * 20 + n0 + j] = accn[j];
        }
    }
}

// ==============================================================================
extern "C" void kernel_launch(void* const* d_in, const int* in_sizes, int n_in,
                              void* d_out, int out_size) {
    const float* feats   = (const float*)d_in[0];
    const float* w1a     = (const float*)d_in[1];
    const float* s1a     = (const float*)d_in[2];
    const float* b1a     = (const float*)d_in[3];
    const float* w3      = (const float*)d_in[4];
    const float* s3      = (const float*)d_in[5];
    const float* b3      = (const float*)d_in[6];
    const float* w1b     = (const float*)d_in[7];
    const float* s1b     = (const float*)d_in[8];
    const float* b1b     = (const float*)d_in[9];
    const float* aux_w   = (const float*)d_in[10];
    const float* aux_b   = (const float*)d_in[11];
    const float* proj_w  = (const float*)d_in[12];
    const float* proj_b  = (const float*)d_in[13];
    const float* proj_s  = (const float*)d_in[14];
    const float* proj_bb = (const float*)d_in[15];
    const float* attn_w  = (const float*)d_in[16];
    const float* attn_b  = (const float*)d_in[17];
    const float* attn_s  = (const float*)d_in[18];
    const float* attn_bb = (const float*)d_in[19];
    const float* head_w  = (const float*)d_in[20];
    const float* head_b  = (const float*)d_in[21];
    const int*   nbr     = (const int*)d_in[22];
    const int*   inv     = (const int*)d_in[23];

    float* out    = (float*)d_out;
    float* fused  = out;
    float* logits = out + (size_t)MP * 64;
    float* aux    = out + (size_t)MP * 84;

    float *pV, *pvs, *pvc, *pacc;
    __half *pH16, *pW1a, *pW1b, *pWp, *pWa, *pW13, *pW3n, *pms;
    int2 *pent; int *pecnt;
    cudaGetSymbolAddress((void**)&pV, g_V);
    cudaGetSymbolAddress((void**)&pms, g_ms16);
    cudaGetSymbolAddress((void**)&pvs, g_vsum4);
    cudaGetSymbolAddress((void**)&pvc, g_vcnt4);
    cudaGetSymbolAddress((void**)&pacc, g_acc);
    cudaGetSymbolAddress((void**)&pH16, g_H16);
    cudaGetSymbolAddress((void**)&pW1a, g_W1a16);
    cudaGetSymbolAddress((void**)&pW1b, g_W1b16);
    cudaGetSymbolAddress((void**)&pWp, g_Wp16);
    cudaGetSymbolAddress((void**)&pWa, g_Wa16);
    cudaGetSymbolAddress((void**)&pW13, g_W13t);
    cudaGetSymbolAddress((void**)&pW3n, g_W3n);
    cudaGetSymbolAddress((void**)&pent, g_ent);
    cudaGetSymbolAddress((void**)&pecnt, g_ecnt);

    cudaFuncSetAttribute(gemm64h3f_kernel, cudaFuncAttributeMaxDynamicSharedMemorySize, T3_TOT);

    wprep_kernel<<<320, 256>>>(w1a, w1b, proj_w, attn_w, w3,
                               pW1a, pW1b, pWp, pWa, pW13, pecnt);
    w3n_kernel<<<1728, 256>>>(w3, pW3n);
    entprep_kernel<<<469, 256>>>(nbr, pent, pecnt);

    gemm64hf2_kernel<<<GTC, 256>>>(feats, pW1a, s1a, b1a, pW13, pH16, pacc);
    for (int i = 0; i < 4; i++) {
        {
            dim3 grid(128, 26);
            sparse_conv_kernel<<<grid, 256>>>(pH16, pW3n + (size_t)i * 27 * 4096,
                                              pent, pecnt, pacc);
        }
        if (i < 3) {
            gemm64h3f_kernel<<<GTC, 256, T3_TOT>>>(pacc, s3 + i * 64, b3 + i * 64,
                                           pW1b + (size_t)i * 4096, s1b + i * 64, b1b + i * 64,
                                           pW1a + (size_t)(i + 1) * 4096, s1a + (i + 1) * 64,
                                           b1a + (i + 1) * 64,
                                           pW13 + (size_t)(i + 1) * 4096,
                                           pH16, pacc);
        } else {
            gemm64h_resf_kernel<<<GTC, 256>>>(pacc, s3 + i * 64, b3 + i * 64,
                                              pW1b + (size_t)i * 4096, s1b + i * 64,
                                              b1b + i * 64, pV, feats,
                                              aux_w, aux_b, aux);
        }
    }

    zero_all_kernel<<<30000, 256>>>(pvs, pvc);
    scatter_all_kernel<<<120000, 256>>>(pV, inv, pvs, pvc);
    {
        dim3 grid(GTC, 4);
        proj_mma_kernel<<<grid, 256>>>(pV, inv, pvs, pvc, pWp,
                                       proj_b, proj_s, proj_bb, pms);
    }
    attn_mma_kernel<<<GTC, 256>>>(pms, pWa, attn_b, attn_s, attn_bb, fused,
                                  head_w, head_b, logits);
}

// round 16
// speedup vs baseline: 1.7321x; 1.0334x over previous
#include <cuda_runtime.h>
#include <cuda_fp16.h>
#include <math.h>
#include <stdint.h>

#define MP 120000
#define GTC 938     // ceil(MP / 128)

// ---------------- scratch (static device globals; no runtime allocs) ----------
__device__ float  g_V[MP * 64];
__device__ __half g_H16[MP * 64];
__device__ float  g_acc[MP * 64];        // conv fp32 accumulator
__device__ __half g_W1a16[4 * 4096];
__device__ __half g_W1b16[4 * 4096];
__device__ __half g_Wp16[4 * 4096];
__device__ __half g_Wa16[4 * 4096];
__device__ __half g_W13t[4 * 4096];      // tap-13 weights transposed [d][c] fp16
__device__ __half g_W3n[4 * 27 * 4096];  // conv weights original [c][d] fp16
__device__ int2   g_ent[26 * MP];        // valid (m, src) pairs per non-self tap
__device__ int    g_ecnt[26];
__device__ int    g_nseg4[4];            // max segment id per scale
__device__ __half g_ms16[4 * MP * 64];   // multi-scale features (fp16)
__device__ float  g_vsum4[4 * MP * 64];
__device__ float  g_vcnt4[4 * MP];

__device__ __forceinline__ float lrelu(float x, float a) { return x > 0.f ? x : a * x; }

__device__ __forceinline__ uint32_t smem_u32(const void* p) {
    uint32_t a;
    asm("{ .reg .u64 t; cvta.to.shared.u64 t, %1; cvt.u32.u64 %0, t; }" : "=r"(a) : "l"(p));
    return a;
}

__device__ __forceinline__ void ldm4(uint32_t r[4], uint32_t addr) {
    asm volatile("ldmatrix.sync.aligned.m8n8.x4.shared.b16 {%0,%1,%2,%3}, [%4];"
                 : "=r"(r[0]), "=r"(r[1]), "=r"(r[2]), "=r"(r[3]) : "r"(addr));
}

__device__ __forceinline__ void mma16816(float c[4], const uint32_t a[4],
                                         uint32_t b0, uint32_t b1) {
    asm volatile(
        "mma.sync.aligned.m16n8k16.row.col.f32.f16.f16.f32 "
        "{%0,%1,%2,%3},{%4,%5,%6,%7},{%8,%9},{%0,%1,%2,%3};"
        : "+f"(c[0]), "+f"(c[1]), "+f"(c[2]), "+f"(c[3])
        : "r"(a[0]), "r"(a[1]), "r"(a[2]), "r"(a[3]), "r"(b0), "r"(b1));
}

#define CP16(dst, src) \
    asm volatile("cp.async.cg.shared.global [%0], [%1], 16;" :: "r"(dst), "l"(src))
#define CP_COMMIT() asm volatile("cp.async.commit_group;" ::: "memory")
#define CP_WAIT(n)  asm volatile("cp.async.wait_group %0;" :: "n"(n) : "memory")
#define STS_ZERO(dst) do { uint32_t _z = 0; \
    asm volatile("st.shared.v4.b32 [%0], {%1,%1,%1,%1};" :: "r"(dst), "r"(_z)); } while (0)

// ========== MMA core (M-tile 128): A(128x64) x W(64x64)^T, 8 warps ============
__device__ __forceinline__ void mma_tile_64(uint32_t a_s, uint32_t w_s,
                                            int lane, int wm, int wn,
                                            float acc[2][4][4]) {
#pragma unroll
    for (int kb = 0; kb < 4; kb++) {
        uint32_t a[2][4], wh[2][4];
#pragma unroll
        for (int mt = 0; mt < 2; mt++) {
            int r = wm + mt * 16 + (lane & 15);
            int lc = kb * 2 + (lane >> 4);
            ldm4(a[mt], a_s + r * 128 + ((lc ^ (r & 7)) << 4));
        }
#pragma unroll
        for (int np = 0; np < 2; np++) {
            int r = wn + np * 16 + (lane & 7) + ((lane & 16) ? 8 : 0);
            int lc = kb * 2 + ((lane >> 3) & 1);
            ldm4(wh[np], w_s + r * 128 + ((lc ^ (r & 7)) << 4));
        }
#pragma unroll
        for (int mt = 0; mt < 2; mt++)
#pragma unroll
            for (int nt = 0; nt < 4; nt++) {
                int np = nt >> 1, q = (nt & 1) * 2;
                mma16816(acc[mt][nt], a[mt], wh[np][q], wh[np][q + 1]);
            }
    }
}

// epi helper: write fp16 lrelu result into swizzled smem tile
__device__ __forceinline__ void epi_to_smem(char* sm, int lr0, int lr1, int col,
                                            float v0, float v1, float v2, float v3) {
    __half2 h0 = __float22half2_rn(make_float2(v0, v1));
    __half2 h1 = __float22half2_rn(make_float2(v2, v3));
    uint32_t d0 = lr0 * 128 + (((col >> 3) ^ (lr0 & 7)) << 4) + ((col * 2) & 15);
    uint32_t d1 = lr1 * 128 + (((col >> 3) ^ (lr1 & 7)) << 4) + ((col * 2) & 15);
    *(__half2*)(sm + d0) = h0;
    *(__half2*)(sm + d1) = h1;
}

__device__ __forceinline__ float smem_h(const char* sm, int r, int c) {
    uint32_t off = r * 128 + (((c >> 3) ^ (r & 7)) << 4) + ((c & 7) * 2);
    return __half2float(*(const __half*)(sm + off));
}

__device__ __forceinline__ float2 smem_h2(const char* sm, int r, int c) {
    uint32_t off = r * 128 + (((c >> 3) ^ (r & 7)) << 4) + ((c & 7) * 2);
    return __half22float2(*(const __half2*)(sm + off));
}

// ====== weight prep: transpose+fp16; zero ecnt + nseg =========================
__global__ void wprep_kernel(const float* __restrict__ w1a, const float* __restrict__ w1b,
                             const float* __restrict__ wp, const float* __restrict__ wa,
                             const float* __restrict__ w3,
                             __half* __restrict__ o1a, __half* __restrict__ o1b,
                             __half* __restrict__ op, __half* __restrict__ oa,
                             __half* __restrict__ o13, int* __restrict__ ecnt,
                             int* __restrict__ nseg4) {
    int g = blockIdx.x * 256 + threadIdx.x;
    if (g < 26) ecnt[g] = 0;
    if (g < 4) nseg4[g] = 0;
    if (g >= 20 * 4096) return;
    int t = g >> 12;
    int rc = g & 4095;
    int d = rc >> 6, c = rc & 63;
    if (t < 4)
        o1a[(size_t)t * 4096 + d * 64 + c] = __float2half_rn(w1a[(size_t)t * 4096 + c * 64 + d]);
    else if (t < 8)
        o1b[(size_t)(t - 4) * 4096 + d * 64 + c] = __float2half_rn(w1b[(size_t)(t - 4) * 4096 + c * 64 + d]);
    else if (t < 12)
        op[(size_t)(t - 8) * 4096 + d * 64 + c] = __float2half_rn(wp[(size_t)(t - 8) * 4096 + c * 64 + d]);
    else if (t < 16)
        oa[(size_t)(t - 12) * 4096 + d * 64 + c] = __float2half_rn(wa[(size_t)(t - 12) * 4096 + c * 64 + d]);
    else {
        int lt = t - 16;
        o13[(size_t)lt * 4096 + d * 64 + c] =
            __float2half_rn(w3[((size_t)lt * 27 + 13) * 4096 + c * 64 + d]);
    }
}

__global__ void w3n_kernel(const float* __restrict__ w3, __half* __restrict__ o) {
    int g = blockIdx.x * 256 + threadIdx.x;
    if (g >= 4 * 27 * 4096) return;
    o[g] = __float2half_rn(w3[g]);
}

__global__ void entprep_kernel(const int* __restrict__ nbr, const int* __restrict__ inv,
                               int2* __restrict__ ent, int* __restrict__ ecnt,
                               int* __restrict__ nseg4) {
    __shared__ int bmax[4];
    const int tid = threadIdx.x;
    if (tid < 4) bmax[tid] = 0;
    __syncthreads();
    int m = blockIdx.x * 256 + tid;
    if (m < MP) {
#pragma unroll
        for (int k = 0; k < 27; k++) {
            if (k == 13) continue;
            int src = nbr[(size_t)m * 27 + k];
            if (src >= 0) {
                int idx = (k < 13) ? k : k - 1;
                int pos = atomicAdd(&ecnt[idx], 1);
                ent[(size_t)idx * MP + pos] = make_int2(m, src);
            }
        }
#pragma unroll
        for (int si = 0; si < 4; si++)
            atomicMax(&bmax[si], inv[(size_t)si * MP + m]);
    }
    __syncthreads();
    if (tid < 4) atomicMax(&nseg4[tid], bmax[tid]);
}

// ==== first layer fused: fp32 feats -> w1a epi -> H16 out; H @ W13 -> acc =====
__global__ __launch_bounds__(256) void gemm64hf2_kernel(
    const float* __restrict__ Xf, const __half* __restrict__ W,
    const float* __restrict__ s, const float* __restrict__ b,
    const __half* __restrict__ W13,
    __half* __restrict__ outh, float* __restrict__ accout) {
    __shared__ __align__(16) char smA[16384];
    __shared__ __align__(16) char smB[16384];
    __shared__ __align__(16) char smW[8192];
    __shared__ __align__(16) char smW13[8192];
    const uint32_t a_s = smem_u32(smA);
    const uint32_t b_s = smem_u32(smB);
    const uint32_t w_s = smem_u32(smW);
    const uint32_t w13_s = smem_u32(smW13);
    const int tid = threadIdx.x;
    const int lane = tid & 31, wid = tid >> 5;
    const int m0 = blockIdx.x * 128;

#pragma unroll
    for (int j = 0; j < 2; j++) {
        int f = tid + j * 256;
        int r = f >> 3, c = f & 7;
        CP16(w_s + r * 128 + ((c ^ (r & 7)) << 4), W + (size_t)r * 64 + c * 8);
        CP16(w13_s + r * 128 + ((c ^ (r & 7)) << 4), W13 + (size_t)r * 64 + c * 8);
    }
    CP_COMMIT();
#pragma unroll
    for (int j = 0; j < 4; j++) {
        int f = tid + j * 256;
        int r = f >> 3, c = f & 7;
        uint32_t dst = a_s + r * 128 + ((c ^ (r & 7)) << 4);
        int m = m0 + r;
        if (m < MP) {
            float4 v0 = *(const float4*)&Xf[(size_t)m * 64 + c * 8];
            float4 v1 = *(const float4*)&Xf[(size_t)m * 64 + c * 8 + 4];
            __half2 h0 = __float22half2_rn(make_float2(v0.x, v0.y));
            __half2 h1 = __float22half2_rn(make_float2(v0.z, v0.w));
            __half2 h2 = __float22half2_rn(make_float2(v1.x, v1.y));
            __half2 h3 = __float22half2_rn(make_float2(v1.z, v1.w));
            uint32_t q0 = *(uint32_t*)&h0, q1 = *(uint32_t*)&h1;
            uint32_t q2 = *(uint32_t*)&h2, q3 = *(uint32_t*)&h3;
            asm volatile("st.shared.v4.b32 [%0], {%1,%2,%3,%4};"
                         :: "r"(dst), "r"(q0), "r"(q1), "r"(q2), "r"(q3));
        } else {
            STS_ZERO(dst);
        }
    }
    CP_WAIT(0);
    __syncthreads();

    const int wm = (wid >> 1) * 32;
    const int wn = (wid & 1) * 32;
    const int qr = lane >> 2, qc = lane & 3;

    float acc[2][4][4] = {};
    mma_tile_64(a_s, w_s, lane, wm, wn, acc);

#pragma unroll
    for (int mt = 0; mt < 2; mt++)
#pragma unroll
        for (int nt = 0; nt < 4; nt++) {
            int col = wn + nt * 8 + qc * 2;
            float2 s2 = *(const float2*)&s[col];
            float2 b2 = *(const float2*)&b[col];
            int lr0 = wm + mt * 16 + qr;
            int lr1 = lr0 + 8;
            int r0 = m0 + lr0, r1 = m0 + lr1;
            float v0 = lrelu(acc[mt][nt][0] * s2.x + b2.x, 0.01f);
            float v1 = lrelu(acc[mt][nt][1] * s2.y + b2.y, 0.01f);
            float v2 = lrelu(acc[mt][nt][2] * s2.x + b2.x, 0.01f);
            float v3 = lrelu(acc[mt][nt][3] * s2.y + b2.y, 0.01f);
            epi_to_smem(smB, lr0, lr1, col, v0, v1, v2, v3);
            if (r0 < MP) *(__half2*)&outh[(size_t)r0 * 64 + col] =
                __float22half2_rn(make_float2(v0, v1));
            if (r1 < MP) *(__half2*)&outh[(size_t)r1 * 64 + col] =
                __float22half2_rn(make_float2(v2, v3));
        }
    __syncthreads();

    float acc2[2][4][4] = {};
    mma_tile_64(b_s, w13_s, lane, wm, wn, acc2);

#pragma unroll
    for (int mt = 0; mt < 2; mt++)
#pragma unroll
        for (int nt = 0; nt < 4; nt++) {
            int col = wn + nt * 8 + qc * 2;
            int r0 = m0 + wm + mt * 16 + qr;
            int r1 = r0 + 8;
            if (r0 < MP) *(float2*)&accout[(size_t)r0 * 64 + col] =
                make_float2(acc2[mt][nt][0], acc2[mt][nt][1]);
            if (r1 < MP) *(float2*)&accout[(size_t)r1 * 64 + col] =
                make_float2(acc2[mt][nt][2], acc2[mt][nt][3]);
        }
}

// ======= sparse conv: acc[m] += H[src] @ W3[tap], chunk-stride grid ===========
__global__ __launch_bounds__(256) void sparse_conv_kernel(
    const __half* __restrict__ H, const __half* __restrict__ W3n,
    const int2* __restrict__ ent, const int* __restrict__ ecnt,
    float* __restrict__ acc) {
    const int kk = blockIdx.y;             // 0..25
    const int cnt = ecnt[kk];
    if ((int)(blockIdx.x * 64) >= cnt) return;
    const int tap = (kk < 13) ? kk : kk + 1;

    __shared__ __align__(16) __half Ws[64 * 64];   // [c][j]
    __shared__ __align__(16) __half Hs[64][64];
    __shared__ int2 es[64];
    const int tid = threadIdx.x;

    const uint4* wsrc = (const uint4*)(W3n + (size_t)tap * 4096);
#pragma unroll
    for (int j = 0; j < 2; j++)
        ((uint4*)Ws)[tid + j * 256] = wsrc[tid + j * 256];

    const int wrp = tid >> 5, lane = tid & 31;

    for (int base = blockIdx.x * 64; base < cnt; base += gridDim.x * 64) {
        __syncthreads();
        if (tid < 64) {
            int e = base + tid;
            es[tid] = (e < cnt) ? ent[(size_t)kk * MP + e] : make_int2(-1, -1);
        }
        __syncthreads();
        {
            int e = tid >> 2, q = tid & 3;
            int src = es[e].y;
            if (src >= 0) {
                *(uint4*)&Hs[e][q * 8]      = *(const uint4*)&H[(size_t)src * 64 + q * 8];
                *(uint4*)&Hs[e][32 + q * 8] = *(const uint4*)&H[(size_t)src * 64 + 32 + q * 8];
            }
        }
        __syncthreads();

#pragma unroll
        for (int ei = 0; ei < 8; ei++) {
            int e = wrp * 8 + ei;
            int m = es[e].x;
            if (m < 0) continue;
            float v0 = 0.f, v1 = 0.f;
#pragma unroll
            for (int d = 0; d < 64; d++) {
                float h = __half2float(Hs[e][d]);
                float2 wf = __half22float2(*(const __half2*)&Ws[d * 64 + lane * 2]);
                v0 += h * wf.x;
                v1 += h * wf.y;
            }
            atomicAdd(&acc[(size_t)m * 64 + lane * 2], v0);
            atomicAdd(&acc[(size_t)m * 64 + lane * 2 + 1], v1);
        }
    }
}

// === fused triple (DYNAMIC smem 56KB) =========================================
#define T3_A    0
#define T3_B    16384
#define T3_W1   32768
#define T3_W2   40960
#define T3_W13  49152
#define T3_TOT  57344

__global__ __launch_bounds__(256) void gemm64h3f_kernel(
    const float* __restrict__ accin, const float* __restrict__ cs, const float* __restrict__ cb,
    const __half* __restrict__ W1, const float* __restrict__ s1, const float* __restrict__ b1,
    const __half* __restrict__ W2, const float* __restrict__ s2, const float* __restrict__ b2,
    const __half* __restrict__ W13,
    __half* __restrict__ outh, float* __restrict__ accout) {
    extern __shared__ __align__(16) char smd[];
    char* smA = smd + T3_A;
    char* smB = smd + T3_B;
    const uint32_t a_s = smem_u32(smd) + T3_A;
    const uint32_t b_s = smem_u32(smd) + T3_B;
    const uint32_t w1_s = smem_u32(smd) + T3_W1;
    const uint32_t w2_s = smem_u32(smd) + T3_W2;
    const uint32_t w13_s = smem_u32(smd) + T3_W13;
    const int tid = threadIdx.x;
    const int lane = tid & 31, wid = tid >> 5;
    const int m0 = blockIdx.x * 128;

#pragma unroll
    for (int j = 0; j < 2; j++) {
        int f = tid + j * 256;
        int r = f >> 3, c = f & 7;
        CP16(w1_s + r * 128 + ((c ^ (r & 7)) << 4), W1 + (size_t)r * 64 + c * 8);
        CP16(w2_s + r * 128 + ((c ^ (r & 7)) << 4), W2 + (size_t)r * 64 + c * 8);
        CP16(w13_s + r * 128 + ((c ^ (r & 7)) << 4), W13 + (size_t)r * 64 + c * 8);
    }
    CP_COMMIT();
#pragma unroll
    for (int j = 0; j < 4; j++) {
        int f = tid + j * 256;
        int r = f >> 3, c = f & 7;
        uint32_t dst = a_s + r * 128 + ((c ^ (r & 7)) << 4);
        int m = m0 + r;
        if (m < MP) {
            float4 v0 = *(const float4*)&accin[(size_t)m * 64 + c * 8];
            float4 v1 = *(const float4*)&accin[(size_t)m * 64 + c * 8 + 4];
            float4 s0 = *(const float4*)&cs[c * 8];
            float4 s1v = *(const float4*)&cs[c * 8 + 4];
            float4 b0 = *(const float4*)&cb[c * 8];
            float4 b1v = *(const float4*)&cb[c * 8 + 4];
            __half2 h0 = __float22half2_rn(make_float2(lrelu(v0.x * s0.x + b0.x, 0.01f),
                                                       lrelu(v0.y * s0.y + b0.y, 0.01f)));
            __half2 h1 = __float22half2_rn(make_float2(lrelu(v0.z * s0.z + b0.z, 0.01f),
                                                       lrelu(v0.w * s0.w + b0.w, 0.01f)));
            __half2 h2 = __float22half2_rn(make_float2(lrelu(v1.x * s1v.x + b1v.x, 0.01f),
                                                       lrelu(v1.y * s1v.y + b1v.y, 0.01f)));
            __half2 h3 = __float22half2_rn(make_float2(lrelu(v1.z * s1v.z + b1v.z, 0.01f),
                                                       lrelu(v1.w * s1v.w + b1v.w, 0.01f)));
            uint32_t q0 = *(uint32_t*)&h0, q1 = *(uint32_t*)&h1;
            uint32_t q2 = *(uint32_t*)&h2, q3 = *(uint32_t*)&h3;
            asm volatile("st.shared.v4.b32 [%0], {%1,%2,%3,%4};"
                         :: "r"(dst), "r"(q0), "r"(q1), "r"(q2), "r"(q3));
        } else {
            STS_ZERO(dst);
        }
    }
    CP_WAIT(0);
    __syncthreads();

    const int wm = (wid >> 1) * 32;
    const int wn = (wid & 1) * 32;
    const int qr = lane >> 2, qc = lane & 3;

    float acc[2][4][4] = {};
    mma_tile_64(a_s, w1_s, lane, wm, wn, acc);

#pragma unroll
    for (int mt = 0; mt < 2; mt++)
#pragma unroll
        for (int nt = 0; nt < 4; nt++) {
            int col = wn + nt * 8 + qc * 2;
            float2 sv = *(const float2*)&s1[col];
            float2 bv = *(const float2*)&b1[col];
            int lr0 = wm + mt * 16 + qr;
            int lr1 = lr0 + 8;
            epi_to_smem(smB, lr0, lr1, col,
                        lrelu(acc[mt][nt][0] * sv.x + bv.x, 0.01f),
                        lrelu(acc[mt][nt][1] * sv.y + bv.y, 0.01f),
                        lrelu(acc[mt][nt][2] * sv.x + bv.x, 0.01f),
                        lrelu(acc[mt][nt][3] * sv.y + bv.y, 0.01f));
        }
    __syncthreads();

    float acc2[2][4][4] = {};
    mma_tile_64(b_s, w2_s, lane, wm, wn, acc2);
    __syncthreads();

#pragma unroll
    for (int mt = 0; mt < 2; mt++)
#pragma unroll
        for (int nt = 0; nt < 4; nt++) {
            int col = wn + nt * 8 + qc * 2;
            float2 sv = *(const float2*)&s2[col];
            float2 bv = *(const float2*)&b2[col];
            int lr0 = wm + mt * 16 + qr;
            int lr1 = lr0 + 8;
            int r0 = m0 + lr0, r1 = m0 + lr1;
            float v0 = lrelu(acc2[mt][nt][0] * sv.x + bv.x, 0.01f);
            float v1 = lrelu(acc2[mt][nt][1] * sv.y + bv.y, 0.01f);
            float v2 = lrelu(acc2[mt][nt][2] * sv.x + bv.x, 0.01f);
            float v3 = lrelu(acc2[mt][nt][3] * sv.y + bv.y, 0.01f);
            epi_to_smem(smA, lr0, lr1, col, v0, v1, v2, v3);
            if (r0 < MP) *(__half2*)&outh[(size_t)r0 * 64 + col] =
                __float22half2_rn(make_float2(v0, v1));
            if (r1 < MP) *(__half2*)&outh[(size_t)r1 * 64 + col] =
                __float22half2_rn(make_float2(v2, v3));
        }
    __syncthreads();

    float acc3[2][4][4] = {};
    mma_tile_64(a_s, w13_s, lane, wm, wn, acc3);

#pragma unroll
    for (int mt = 0; mt < 2; mt++)
#pragma unroll
        for (int nt = 0; nt < 4; nt++) {
            int col = wn + nt * 8 + qc * 2;
            int r0 = m0 + wm + mt * 16 + qr;
            int r1 = r0 + 8;
            if (r0 < MP) *(float2*)&accout[(size_t)r0 * 64 + col] =
                make_float2(acc3[mt][nt][0], acc3[mt][nt][1]);
            if (r1 < MP) *(float2*)&accout[(size_t)r1 * 64 + col] =
                make_float2(acc3[mt][nt][2], acc3[mt][nt][3]);
        }
}

// === fused last: conv-epi(acc) -> @W1b -> epi + residual -> V fp32 + aux head =
__global__ __launch_bounds__(256) void gemm64h_resf_kernel(
    const float* __restrict__ accin, const float* __restrict__ cs, const float* __restrict__ cb,
    const __half* __restrict__ W, const float* __restrict__ s, const float* __restrict__ b,
    float* __restrict__ outf, const float* __restrict__ feats,
    const float* __restrict__ aux_w, const float* __restrict__ aux_b,
    float* __restrict__ aux) {
    __shared__ __align__(16) char smA[16384];
    __shared__ __align__(16) char smW[8192];
    __shared__ float Ws20[64 * 20];
    __shared__ float bs20[20];
    const uint32_t a_s = smem_u32(smA);
    const uint32_t w_s = smem_u32(smW);
    const int tid = threadIdx.x;
    const int lane = tid & 31, wid = tid >> 5;
    const int m0 = blockIdx.x * 128;

#pragma unroll
    for (int j = 0; j < 2; j++) {
        int f = tid + j * 256;
        int r = f >> 3, c = f & 7;
        CP16(w_s + r * 128 + ((c ^ (r & 7)) << 4), W + (size_t)r * 64 + c * 8);
    }
    CP_COMMIT();
    for (int f = tid; f < 64 * 20; f += 256) Ws20[f] = aux_w[f];
    if (tid < 20) bs20[tid] = aux_b[tid];
#pragma unroll
    for (int j = 0; j < 4; j++) {
        int f = tid + j * 256;
        int r = f >> 3, c = f & 7;
        uint32_t dst = a_s + r * 128 + ((c ^ (r & 7)) << 4);
        int m = m0 + r;
        if (m < MP) {
            float4 v0 = *(const float4*)&accin[(size_t)m * 64 + c * 8];
            float4 v1 = *(const float4*)&accin[(size_t)m * 64 + c * 8 + 4];
            float4 s0 = *(const float4*)&cs[c * 8];
            float4 s1v = *(const float4*)&cs[c * 8 + 4];
            float4 b0 = *(const float4*)&cb[c * 8];
            float4 b1v = *(const float4*)&cb[c * 8 + 4];
            __half2 h0 = __float22half2_rn(make_float2(lrelu(v0.x * s0.x + b0.x, 0.01f),
                                                       lrelu(v0.y * s0.y + b0.y, 0.01f)));
            __half2 h1 = __float22half2_rn(make_float2(lrelu(v0.z * s0.z + b0.z, 0.01f),
                                                       lrelu(v0.w * s0.w + b0.w, 0.01f)));
            __half2 h2 = __float22half2_rn(make_float2(lrelu(v1.x * s1v.x + b1v.x, 0.01f),
                                                       lrelu(v1.y * s1v.y + b1v.y, 0.01f)));
            __half2 h3 = __float22half2_rn(make_float2(lrelu(v1.z * s1v.z + b1v.z, 0.01f),
                                                       lrelu(v1.w * s1v.w + b1v.w, 0.01f)));
            uint32_t q0 = *(uint32_t*)&h0, q1 = *(uint32_t*)&h1;
            uint32_t q2 = *(uint32_t*)&h2, q3 = *(uint32_t*)&h3;
            asm volatile("st.shared.v4.b32 [%0], {%1,%2,%3,%4};"
                         :: "r"(dst), "r"(q0), "r"(q1), "r"(q2), "r"(q3));
        } else {
            STS_ZERO(dst);
        }
    }
    CP_WAIT(0);
    __syncthreads();

    const int wm = (wid >> 1) * 32;
    const int wn = (wid & 1) * 32;
    float acc[2][4][4] = {};
    mma_tile_64(a_s, w_s, lane, wm, wn, acc);
    __syncthreads();

    const int qr = lane >> 2, qc = lane & 3;
#pragma unroll
    for (int mt = 0; mt < 2; mt++)
#pragma unroll
        for (int nt = 0; nt < 4; nt++) {
            int col = wn + nt * 8 + qc * 2;
            float2 sv = *(const float2*)&s[col];
            float2 bv = *(const float2*)&b[col];
            int lr0 = wm + mt * 16 + qr;
            int lr1 = lr0 + 8;
            int r0 = m0 + lr0, r1 = m0 + lr1;
            float v0 = 0.f, v1 = 0.f, v2 = 0.f, v3 = 0.f;
            if (r0 < MP) {
                float2 fr = *(const float2*)&feats[(size_t)r0 * 64 + col];
                v0 = lrelu(lrelu(acc[mt][nt][0] * sv.x + bv.x, 0.01f) + fr.x, 0.1f);
                v1 = lrelu(lrelu(acc[mt][nt][1] * sv.y + bv.y, 0.01f) + fr.y, 0.1f);
                *(float2*)&outf[(size_t)r0 * 64 + col] = make_float2(v0, v1);
            }
            if (r1 < MP) {
                float2 fr = *(const float2*)&feats[(size_t)r1 * 64 + col];
                v2 = lrelu(lrelu(acc[mt][nt][2] * sv.x + bv.x, 0.01f) + fr.x, 0.1f);
                v3 = lrelu(lrelu(acc[mt][nt][3] * sv.y + bv.y, 0.01f) + fr.y, 0.1f);
                *(float2*)&outf[(size_t)r1 * 64 + col] = make_float2(v2, v3);
            }
            epi_to_smem(smA, lr0, lr1, col, v0, v1, v2, v3);
        }
    __syncthreads();

    {
        int r = tid >> 1, n0 = (tid & 1) * 10;
        int m = m0 + r;
        if (m < MP) {
            float accn[10];
#pragma unroll
            for (int j = 0; j < 10; j++) accn[j] = bs20[n0 + j];
#pragma unroll 8
            for (int c = 0; c < 64; c++) {
                float x = smem_h(smA, r, c);
#pragma unroll
                for (int j = 0; j < 10; j++) accn[j] += x * Ws20[c * 20 + n0 + j];
            }
#pragma unroll
            for (int j = 0; j < 10; j++) aux[(size_t)m * 20 + n0 + j] = accn[j];
        }
    }
}

// ============== bounded zero: only rows [0, nseg+1) per scale =================
__global__ void zero_all_kernel(float* __restrict__ vsum4, float* __restrict__ vcnt4,
                                const int* __restrict__ nseg4) {
    const int si = blockIdx.y;
    const int cap = nseg4[si] + 1;
    const int nf4 = cap * 16;   // 64 floats per row = 16 float4
    float4* dst = (float4*)(vsum4 + (size_t)si * MP * 64);
    for (int i = blockIdx.x * 256 + threadIdx.x; i < nf4; i += gridDim.x * 256)
        dst[i] = make_float4(0.f, 0.f, 0.f, 0.f);
    float* cdst = vcnt4 + (size_t)si * MP;
    for (int i = blockIdx.x * 256 + threadIdx.x; i < cap; i += gridDim.x * 256)
        cdst[i] = 0.f;
}

// =============== scatter: read V once, 4 scales inner loop ====================
__global__ void scatter_all_kernel(const float* __restrict__ V, const int* __restrict__ inv,
                                   float* __restrict__ vsum4, float* __restrict__ vcnt4) {
    int gid = blockIdx.x * 256 + threadIdx.x;
    if (gid >= MP * 64) return;
    int m = gid >> 6, c = gid & 63;
    float v = V[gid];
#pragma unroll
    for (int si = 0; si < 4; si++) {
        int sg = inv[(size_t)si * MP + m];
        atomicAdd(&vsum4[(size_t)si * MP * 64 + sg * 64 + c], v);
        if (c == 0) atomicAdd(&vcnt4[(size_t)si * MP + sg], 1.0f);
    }
}

// ====== proj 4-in-1: V staged in smem, per scale Os build + GEMM -> ms ========
#define P4_V   0        // 32768 fp32 V tile [128][64]
#define P4_A   32768    // 16384
#define P4_W   49152    // 8192
#define P4_TOT 57344

__global__ __launch_bounds__(256) void proj4_mma_kernel(
    const float* __restrict__ V, const int* __restrict__ inv,
    const float* __restrict__ vsum4, const float* __restrict__ vcnt4,
    const __half* __restrict__ Wp, const float* __restrict__ pb,
    const float* __restrict__ ps, const float* __restrict__ pbb,
    __half* __restrict__ ms) {
    extern __shared__ __align__(16) char smd[];
    float* Vs = (float*)(smd + P4_V);
    const uint32_t a_s = smem_u32(smd) + P4_A;
    const uint32_t w_s = smem_u32(smd) + P4_W;
    const int tid = threadIdx.x;
    const int lane = tid & 31, wid = tid >> 5;
    const int m0 = blockIdx.x * 128;

    // stage V tile (fp32, plain layout)
#pragma unroll
    for (int j = 0; j < 8; j++) {
        int idx = tid + j * 256;                 // float4 id, 2048 total
        int r = idx >> 4, c4 = idx & 15;
        int m = m0 + r;
        float4 v = make_float4(0.f, 0.f, 0.f, 0.f);
        if (m < MP) v = *(const float4*)&V[(size_t)m * 64 + c4 * 4];
        *(float4*)&Vs[r * 64 + c4 * 4] = v;
    }
    __syncthreads();

    const int wm = (wid >> 1) * 32;
    const int wn = (wid & 1) * 32;
    const int qr = lane >> 2, qc = lane & 3;

    for (int si = 0; si < 4; si++) {
        const int* seg = inv + (size_t)si * MP;
        const float* vsum = vsum4 + (size_t)si * MP * 64;
        const float* vcnt = vcnt4 + (size_t)si * MP;
        __half* msO = ms + (size_t)si * MP * 64;

#pragma unroll
        for (int j = 0; j < 2; j++) {
            int f = tid + j * 256;
            int r = f >> 3, c = f & 7;
            CP16(w_s + r * 128 + ((c ^ (r & 7)) << 4),
                 Wp + (size_t)si * 4096 + r * 64 + c * 8);
        }
        CP_COMMIT();

#pragma unroll
        for (int j = 0; j < 4; j++) {
            int f = tid + j * 256;
            int r = f >> 3, c = f & 7;
            uint32_t dst = a_s + r * 128 + ((c ^ (r & 7)) << 4);
            int m = m0 + r;
            if (m < MP) {
                int sg = seg[m];
                float rc = 1.0f / fmaxf(vcnt[sg], 1.0f);
                float4 v0 = *(const float4*)&Vs[r * 64 + c * 8];
                float4 v1 = *(const float4*)&Vs[r * 64 + c * 8 + 4];
                float4 u0 = *(const float4*)&vsum[(size_t)sg * 64 + c * 8];
                float4 u1 = *(const float4*)&vsum[(size_t)sg * 64 + c * 8 + 4];
                __half2 h0 = __float22half2_rn(make_float2((v0.x - u0.x * rc) * v0.x,
                                                           (v0.y - u0.y * rc) * v0.y));
                __half2 h1 = __float22half2_rn(make_float2((v0.z - u0.z * rc) * v0.z,
                                                           (v0.w - u0.w * rc) * v0.w));
                __half2 h2 = __float22half2_rn(make_float2((v1.x - u1.x * rc) * v1.x,
                                                           (v1.y - u1.y * rc) * v1.y));
                __half2 h3 = __float22half2_rn(make_float2((v1.z - u1.z * rc) * v1.z,
                                                           (v1.w - u1.w * rc) * v1.w));
                uint32_t q0 = *(uint32_t*)&h0, q1 = *(uint32_t*)&h1;
                uint32_t q2 = *(uint32_t*)&h2, q3 = *(uint32_t*)&h3;
                asm volatile("st.shared.v4.b32 [%0], {%1,%2,%3,%4};"
                             :: "r"(dst), "r"(q0), "r"(q1), "r"(q2), "r"(q3));
            } else {
                STS_ZERO(dst);
            }
        }
        CP_WAIT(0);
        __syncthreads();

        float acc[2][4][4] = {};
        mma_tile_64(a_s, w_s, lane, wm, wn, acc);

#pragma unroll
        for (int mt = 0; mt < 2; mt++)
#pragma unroll
            for (int nt = 0; nt < 4; nt++) {
                int col = wn + nt * 8 + qc * 2;
                float2 bv = *(const float2*)&pb[si * 64 + col];
                float2 sv = *(const float2*)&ps[si * 64 + col];
                float2 b2 = *(const float2*)&pbb[si * 64 + col];
                int r0 = m0 + wm + mt * 16 + qr;
                int r1 = r0 + 8;
                if (r0 < MP) *(__half2*)&msO[(size_t)r0 * 64 + col] = __float22half2_rn(
                    make_float2(lrelu((acc[mt][nt][0] + bv.x) * sv.x + b2.x, 0.01f),
                                lrelu((acc[mt][nt][1] + bv.y) * sv.y + b2.y, 0.01f)));
                if (r1 < MP) *(__half2*)&msO[(size_t)r1 * 64 + col] = __float22half2_rn(
                    make_float2(lrelu((acc[mt][nt][2] + bv.x) * sv.x + b2.x, 0.01f),
                                lrelu((acc[mt][nt][3] + bv.y) * sv.y + b2.y, 0.01f)));
            }
        __syncthreads();   // A/W reads done before next scale overwrites
    }
}

// ===== attn: ms tiles staged in smem, 4 GEMMs, fused out + head logits ========
#define AT_A   0        // 16384
#define AT_W   16384    // 8192
#define AT_MS  24576    // 4 x 16384 = 65536
#define AT_TOT 90112

__global__ __launch_bounds__(256) void attn_mma_kernel(
    const __half* __restrict__ ms, const __half* __restrict__ Wa,
    const float* __restrict__ ab, const float* __restrict__ as_,
    const float* __restrict__ abb, float* __restrict__ fused,
    const float* __restrict__ head_w, const float* __restrict__ head_b,
    float* __restrict__ logits) {
    extern __shared__ __align__(16) char smd[];
    char* smA = smd + AT_A;
    char* msS = smd + AT_MS;
    const uint32_t a_s = smem_u32(smd) + AT_A;
    const uint32_t w_s = smem_u32(smd) + AT_W;
    __shared__ float Ws20[64 * 20];
    __shared__ float bs20[20];
    const int tid = threadIdx.x;
    const int lane = tid & 31, wid = tid >> 5;
    const int m0 = blockIdx.x * 128;

    for (int f = tid; f < 64 * 20; f += 256) Ws20[f] = head_w[f];
    if (tid < 20) bs20[tid] = head_b[tid];

    // stage 4 ms tiles + build sumx tile (single pass over global ms)
#pragma unroll
    for (int j = 0; j < 4; j++) {
        int f = tid + j * 256;
        int r = f >> 3, c = f & 7;
        uint32_t dstoff = r * 128 + ((c ^ (r & 7)) << 4);
        int m = m0 + r;
        if (m < MP) {
            float sx[8] = {};
#pragma unroll
            for (int i = 0; i < 4; i++) {
                uint4 q = *(const uint4*)&ms[((size_t)i * MP + m) * 64 + c * 8];
                *(uint4*)(msS + i * 16384 + dstoff) = q;
                const __half2* hp = (const __half2*)&q;
#pragma unroll
                for (int t = 0; t < 4; t++) {
                    float2 fv = __half22float2(hp[t]);
                    sx[t * 2] += fv.x;
                    sx[t * 2 + 1] += fv.y;
                }
            }
            __half2 h0 = __float22half2_rn(make_float2(sx[0], sx[1]));
            __half2 h1 = __float22half2_rn(make_float2(sx[2], sx[3]));
            __half2 h2 = __float22half2_rn(make_float2(sx[4], sx[5]));
            __half2 h3 = __float22half2_rn(make_float2(sx[6], sx[7]));
            uint32_t q0 = *(uint32_t*)&h0, q1 = *(uint32_t*)&h1;
            uint32_t q2 = *(uint32_t*)&h2, q3 = *(uint32_t*)&h3;
            asm volatile("st.shared.v4.b32 [%0], {%1,%2,%3,%4};"
                         :: "r"(a_s + dstoff), "r"(q0), "r"(q1), "r"(q2), "r"(q3));
        } else {
            STS_ZERO(a_s + dstoff);
            uint4 z = make_uint4(0, 0, 0, 0);
#pragma unroll
            for (int i = 0; i < 4; i++)
                *(uint4*)(msS + i * 16384 + dstoff) = z;
        }
    }

    const int wm = (wid >> 1) * 32;
    const int wn = (wid & 1) * 32;
    const int qr = lane >> 2, qc = lane & 3;
    float fac[2][4][4] = {};

    for (int i = 0; i < 4; i++) {
        __syncthreads();
#pragma unroll
        for (int j = 0; j < 2; j++) {
            int f = tid + j * 256;
            int r = f >> 3, c = f & 7;
            CP16(w_s + r * 128 + ((c ^ (r & 7)) << 4),
                 Wa + (size_t)i * 4096 + r * 64 + c * 8);
        }
        CP_COMMIT();
        CP_WAIT(0);
        __syncthreads();

        float acc[2][4][4] = {};
        mma_tile_64(a_s, w_s, lane, wm, wn, acc);

        const char* msT = msS + i * 16384;
#pragma unroll
        for (int mt = 0; mt < 2; mt++)
#pragma unroll
            for (int nt = 0; nt < 4; nt++) {
                int col = wn + nt * 8 + qc * 2;
                float2 bv = *(const float2*)&ab[i * 64 + col];
                float2 sv = *(const float2*)&as_[i * 64 + col];
                float2 b2 = *(const float2*)&abb[i * 64 + col];
                int lr0 = wm + mt * 16 + qr;
                int lr1 = lr0 + 8;
                {
                    float2 mv = smem_h2(msT, lr0, col);
                    float a0 = 1.0f / (1.0f + __expf(-((acc[mt][nt][0] + bv.x) * sv.x + b2.x)));
                    float a1 = 1.0f / (1.0f + __expf(-((acc[mt][nt][1] + bv.y) * sv.y + b2.y)));
                    fac[mt][nt][0] += a0 * mv.x;
                    fac[mt][nt][1] += a1 * mv.y;
                }
                {
                    float2 mv = smem_h2(msT, lr1, col);
                    float a2 = 1.0f / (1.0f + __expf(-((acc[mt][nt][2] + bv.x) * sv.x + b2.x)));
                    float a3 = 1.0f / (1.0f + __expf(-((acc[mt][nt][3] + bv.y) * sv.y + b2.y)));
                    fac[mt][nt][2] += a2 * mv.x;
                    fac[mt][nt][3] += a3 * mv.y;
                }
            }
    }
    __syncthreads();

#pragma unroll
    for (int mt = 0; mt < 2; mt++)
#pragma unroll
        for (int nt = 0; nt < 4; nt++) {
            int col = wn + nt * 8 + qc * 2;
            int lr0 = wm + mt * 16 + qr;
            int lr1 = lr0 + 8;
            int r0 = m0 + lr0, r1 = m0 + lr1;
            if (r0 < MP) *(float2*)&fused[(size_t)r0 * 64 + col] =
                make_float2(fac[mt][nt][0], fac[mt][nt][1]);
            if (r1 < MP) *(float2*)&fused[(size_t)r1 * 64 + col] =
                make_float2(fac[mt][nt][2], fac[mt][nt][3]);
            epi_to_smem(smA, lr0, lr1, col,
                        fac[mt][nt][0], fac[mt][nt][1], fac[mt][nt][2], fac[mt][nt][3]);
        }
    __syncthreads();

    {
        int r = tid >> 1, n0 = (tid & 1) * 10;
        int m = m0 + r;
        if (m < MP) {
            float accn[10];
#pragma unroll
            for (int j = 0; j < 10; j++) accn[j] = bs20[n0 + j];
#pragma unroll 8
            for (int c = 0; c < 64; c++) {
                float x = smem_h(smA, r, c);
#pragma unroll
                for (int j = 0; j < 10; j++) accn[j] += x * Ws20[c * 20 + n0 + j];
            }
#pragma unroll
            for (int j = 0; j < 10; j++) logits[(size_t)m * 20 + n0 + j] = accn[j];
        }
    }
}

// ==============================================================================
extern "C" void kernel_launch(void* const* d_in, const int* in_sizes, int n_in,
                              void* d_out, int out_size) {
    const float* feats   = (const float*)d_in[0];
    const float* w1a     = (const float*)d_in[1];
    const float* s1a     = (const float*)d_in[2];
    const float* b1a     = (const float*)d_in[3];
    const float* w3      = (const float*)d_in[4];
    const float* s3      = (const float*)d_in[5];
    const float* b3      = (const float*)d_in[6];
    const float* w1b     = (const float*)d_in[7];
    const float* s1b     = (const float*)d_in[8];
    const float* b1b     = (const float*)d_in[9];
    const float* aux_w   = (const float*)d_in[10];
    const float* aux_b   = (const float*)d_in[11];
    const float* proj_w  = (const float*)d_in[12];
    const float* proj_b  = (const float*)d_in[13];
    const float* proj_s  = (const float*)d_in[14];
    const float* proj_bb = (const float*)d_in[15];
    const float* attn_w  = (const float*)d_in[16];
    const float* attn_b  = (const float*)d_in[17];
    const float* attn_s  = (const float*)d_in[18];
    const float* attn_bb = (const float*)d_in[19];
    const float* head_w  = (const float*)d_in[20];
    const float* head_b  = (const float*)d_in[21];
    const int*   nbr     = (const int*)d_in[22];
    const int*   inv     = (const int*)d_in[23];

    float* out    = (float*)d_out;
    float* fused  = out;
    float* logits = out + (size_t)MP * 64;
    float* aux    = out + (size_t)MP * 84;

    float *pV, *pvs, *pvc, *pacc;
    __half *pH16, *pW1a, *pW1b, *pWp, *pWa, *pW13, *pW3n, *pms;
    int2 *pent; int *pecnt, *pnseg;
    cudaGetSymbolAddress((void**)&pV, g_V);
    cudaGetSymbolAddress((void**)&pms, g_ms16);
    cudaGetSymbolAddress((void**)&pvs, g_vsum4);
    cudaGetSymbolAddress((void**)&pvc, g_vcnt4);
    cudaGetSymbolAddress((void**)&pacc, g_acc);
    cudaGetSymbolAddress((void**)&pH16, g_H16);
    cudaGetSymbolAddress((void**)&pW1a, g_W1a16);
    cudaGetSymbolAddress((void**)&pW1b, g_W1b16);
    cudaGetSymbolAddress((void**)&pWp, g_Wp16);
    cudaGetSymbolAddress((void**)&pWa, g_Wa16);
    cudaGetSymbolAddress((void**)&pW13, g_W13t);
    cudaGetSymbolAddress((void**)&pW3n, g_W3n);
    cudaGetSymbolAddress((void**)&pent, g_ent);
    cudaGetSymbolAddress((void**)&pecnt, g_ecnt);
    cudaGetSymbolAddress((void**)&pnseg, g_nseg4);

    cudaFuncSetAttribute(gemm64h3f_kernel, cudaFuncAttributeMaxDynamicSharedMemorySize, T3_TOT);
    cudaFuncSetAttribute(proj4_mma_kernel, cudaFuncAttributeMaxDynamicSharedMemorySize, P4_TOT);
    cudaFuncSetAttribute(attn_mma_kernel, cudaFuncAttributeMaxDynamicSharedMemorySize, AT_TOT);

    wprep_kernel<<<320, 256>>>(w1a, w1b, proj_w, attn_w, w3,
                               pW1a, pW1b, pWp, pWa, pW13, pecnt, pnseg);
    w3n_kernel<<<1728, 256>>>(w3, pW3n);
    entprep_kernel<<<469, 256>>>(nbr, inv, pent, pecnt, pnseg);

    gemm64hf2_kernel<<<GTC, 256>>>(feats, pW1a, s1a, b1a, pW13, pH16, pacc);
    for (int i = 0; i < 4; i++) {
        {
            dim3 grid(128, 26);
            sparse_conv_kernel<<<grid, 256>>>(pH16, pW3n + (size_t)i * 27 * 4096,
                                              pent, pecnt, pacc);
        }
        if (i < 3) {
            gemm64h3f_kernel<<<GTC, 256, T3_TOT>>>(pacc, s3 + i * 64, b3 + i * 64,
                                           pW1b + (size_t)i * 4096, s1b + i * 64, b1b + i * 64,
                                           pW1a + (size_t)(i + 1) * 4096, s1a + (i + 1) * 64,
                                           b1a + (i + 1) * 64,
                                           pW13 + (size_t)(i + 1) * 4096,
                                           pH16, pacc);
        } else {
            gemm64h_resf_kernel<<<GTC, 256>>>(pacc, s3 + i * 64, b3 + i * 64,
                                              pW1b + (size_t)i * 4096, s1b + i * 64,
                                              b1b + i * 64, pV, feats,
                                              aux_w, aux_b, aux);
        }
    }

    {
        dim3 zgrid(469, 4);
        zero_all_kernel<<<zgrid, 256>>>(pvs, pvc, pnseg);
    }
    scatter_all_kernel<<<30000, 256>>>(pV, inv, pvs, pvc);
    proj4_mma_kernel<<<GTC, 256, P4_TOT>>>(pV, inv, pvs, pvc, pWp,
                                           proj_b, proj_s, proj_bb, pms);
    attn_mma_kernel<<<GTC, 256, AT_TOT>>>(pms, pWa, attn_b, attn_s, attn_bb, fused,
                                          head_w, head_b, logits);
}

// round 17
// speedup vs baseline: 1.7638x; 1.0183x over previous
#include <cuda_runtime.h>
#include <cuda_fp16.h>
#include <math.h>
#include <stdint.h>

#define MP 120000
#define GTC 938     // ceil(MP / 128)

// ---------------- scratch (static device globals; no runtime allocs) ----------
__device__ float  g_V[MP * 64];
__device__ __half g_H16[MP * 64];
__device__ __half g_acc16[MP * 64];      // conv accumulator (fp16, half2 atomics)
__device__ __half g_W1a16[4 * 4096];
__device__ __half g_W1b16[4 * 4096];
__device__ __half g_Wp16[4 * 4096];
__device__ __half g_Wa16[4 * 4096];
__device__ __half g_W13t[4 * 4096];      // tap-13 weights transposed [d][c] fp16
__device__ __half g_W3n[4 * 27 * 4096];  // conv weights original [c][d] fp16
__device__ int2   g_ent[26 * MP];        // valid (m, src) pairs per non-self tap
__device__ int    g_ecnt[26];
__device__ int    g_nseg4[4];            // max segment id per scale
__device__ __half g_ms16[4 * MP * 64];   // multi-scale features (fp16)
__device__ float  g_vsum4[4 * MP * 64];
__device__ float  g_vcnt4[4 * MP];

__device__ __forceinline__ float lrelu(float x, float a) { return x > 0.f ? x : a * x; }

__device__ __forceinline__ uint32_t smem_u32(const void* p) {
    uint32_t a;
    asm("{ .reg .u64 t; cvta.to.shared.u64 t, %1; cvt.u32.u64 %0, t; }" : "=r"(a) : "l"(p));
    return a;
}

__device__ __forceinline__ void ldm4(uint32_t r[4], uint32_t addr) {
    asm volatile("ldmatrix.sync.aligned.m8n8.x4.shared.b16 {%0,%1,%2,%3}, [%4];"
                 : "=r"(r[0]), "=r"(r[1]), "=r"(r[2]), "=r"(r[3]) : "r"(addr));
}

__device__ __forceinline__ void mma16816(float c[4], const uint32_t a[4],
                                         uint32_t b0, uint32_t b1) {
    asm volatile(
        "mma.sync.aligned.m16n8k16.row.col.f32.f16.f16.f32 "
        "{%0,%1,%2,%3},{%4,%5,%6,%7},{%8,%9},{%0,%1,%2,%3};"
        : "+f"(c[0]), "+f"(c[1]), "+f"(c[2]), "+f"(c[3])
        : "r"(a[0]), "r"(a[1]), "r"(a[2]), "r"(a[3]), "r"(b0), "r"(b1));
}

#define CP16(dst, src) \
    asm volatile("cp.async.cg.shared.global [%0], [%1], 16;" :: "r"(dst), "l"(src))
#define CP_COMMIT() asm volatile("cp.async.commit_group;" ::: "memory")
#define CP_WAIT(n)  asm volatile("cp.async.wait_group %0;" :: "n"(n) : "memory")
#define STS_ZERO(dst) do { uint32_t _z = 0; \
    asm volatile("st.shared.v4.b32 [%0], {%1,%1,%1,%1};" :: "r"(dst), "r"(_z)); } while (0)

// ========== MMA core (M-tile 128): A(128x64) x W(64x64)^T, 8 warps ============
__device__ __forceinline__ void mma_tile_64(uint32_t a_s, uint32_t w_s,
                                            int lane, int wm, int wn,
                                            float acc[2][4][4]) {
#pragma unroll
    for (int kb = 0; kb < 4; kb++) {
        uint32_t a[2][4], wh[2][4];
#pragma unroll
        for (int mt = 0; mt < 2; mt++) {
            int r = wm + mt * 16 + (lane & 15);
            int lc = kb * 2 + (lane >> 4);
            ldm4(a[mt], a_s + r * 128 + ((lc ^ (r & 7)) << 4));
        }
#pragma unroll
        for (int np = 0; np < 2; np++) {
            int r = wn + np * 16 + (lane & 7) + ((lane & 16) ? 8 : 0);
            int lc = kb * 2 + ((lane >> 3) & 1);
            ldm4(wh[np], w_s + r * 128 + ((lc ^ (r & 7)) << 4));
        }
#pragma unroll
        for (int mt = 0; mt < 2; mt++)
#pragma unroll
            for (int nt = 0; nt < 4; nt++) {
                int np = nt >> 1, q = (nt & 1) * 2;
                mma16816(acc[mt][nt], a[mt], wh[np][q], wh[np][q + 1]);
            }
    }
}

// epi helper: write fp16 lrelu result into swizzled smem tile
__device__ __forceinline__ void epi_to_smem(char* sm, int lr0, int lr1, int col,
                                            float v0, float v1, float v2, float v3) {
    __half2 h0 = __float22half2_rn(make_float2(v0, v1));
    __half2 h1 = __float22half2_rn(make_float2(v2, v3));
    uint32_t d0 = lr0 * 128 + (((col >> 3) ^ (lr0 & 7)) << 4) + ((col * 2) & 15);
    uint32_t d1 = lr1 * 128 + (((col >> 3) ^ (lr1 & 7)) << 4) + ((col * 2) & 15);
    *(__half2*)(sm + d0) = h0;
    *(__half2*)(sm + d1) = h1;
}

__device__ __forceinline__ float smem_h(const char* sm, int r, int c) {
    uint32_t off = r * 128 + (((c >> 3) ^ (r & 7)) << 4) + ((c & 7) * 2);
    return __half2float(*(const __half*)(sm + off));
}

__device__ __forceinline__ float2 smem_h2(const char* sm, int r, int c) {
    uint32_t off = r * 128 + (((c >> 3) ^ (r & 7)) << 4) + ((c & 7) * 2);
    return __half22float2(*(const __half2*)(sm + off));
}

// conv-epi: load 8 fp16 acc values, apply s3/b3 + lrelu, stage fp16 into smem
__device__ __forceinline__ void convepi_to_smem(uint32_t dst, const __half* accin,
                                                size_t base, int c,
                                                const float* cs, const float* cb) {
    uint4 q = *(const uint4*)&accin[base + c * 8];
    const __half2* ap = (const __half2*)&q;
    float2 a0 = __half22float2(ap[0]);
    float2 a1 = __half22float2(ap[1]);
    float2 a2 = __half22float2(ap[2]);
    float2 a3 = __half22float2(ap[3]);
    float4 s0 = *(const float4*)&cs[c * 8];
    float4 s1v = *(const float4*)&cs[c * 8 + 4];
    float4 b0 = *(const float4*)&cb[c * 8];
    float4 b1v = *(const float4*)&cb[c * 8 + 4];
    __half2 h0 = __float22half2_rn(make_float2(lrelu(a0.x * s0.x + b0.x, 0.01f),
                                               lrelu(a0.y * s0.y + b0.y, 0.01f)));
    __half2 h1 = __float22half2_rn(make_float2(lrelu(a1.x * s0.z + b0.z, 0.01f),
                                               lrelu(a1.y * s0.w + b0.w, 0.01f)));
    __half2 h2 = __float22half2_rn(make_float2(lrelu(a2.x * s1v.x + b1v.x, 0.01f),
                                               lrelu(a2.y * s1v.y + b1v.y, 0.01f)));
    __half2 h3 = __float22half2_rn(make_float2(lrelu(a3.x * s1v.z + b1v.z, 0.01f),
                                               lrelu(a3.y * s1v.w + b1v.w, 0.01f)));
    uint32_t q0 = *(uint32_t*)&h0, q1 = *(uint32_t*)&h1;
    uint32_t q2 = *(uint32_t*)&h2, q3 = *(uint32_t*)&h3;
    asm volatile("st.shared.v4.b32 [%0], {%1,%2,%3,%4};"
                 :: "r"(dst), "r"(q0), "r"(q1), "r"(q2), "r"(q3));
}

// ====== weight prep: transpose+fp16; zero ecnt + nseg =========================
__global__ void wprep_kernel(const float* __restrict__ w1a, const float* __restrict__ w1b,
                             const float* __restrict__ wp, const float* __restrict__ wa,
                             const float* __restrict__ w3,
                             __half* __restrict__ o1a, __half* __restrict__ o1b,
                             __half* __restrict__ op, __half* __restrict__ oa,
                             __half* __restrict__ o13, int* __restrict__ ecnt,
                             int* __restrict__ nseg4) {
    int g = blockIdx.x * 256 + threadIdx.x;
    if (g < 26) ecnt[g] = 0;
    if (g < 4) nseg4[g] = 0;
    if (g >= 20 * 4096) return;
    int t = g >> 12;
    int rc = g & 4095;
    int d = rc >> 6, c = rc & 63;
    if (t < 4)
        o1a[(size_t)t * 4096 + d * 64 + c] = __float2half_rn(w1a[(size_t)t * 4096 + c * 64 + d]);
    else if (t < 8)
        o1b[(size_t)(t - 4) * 4096 + d * 64 + c] = __float2half_rn(w1b[(size_t)(t - 4) * 4096 + c * 64 + d]);
    else if (t < 12)
        op[(size_t)(t - 8) * 4096 + d * 64 + c] = __float2half_rn(wp[(size_t)(t - 8) * 4096 + c * 64 + d]);
    else if (t < 16)
        oa[(size_t)(t - 12) * 4096 + d * 64 + c] = __float2half_rn(wa[(size_t)(t - 12) * 4096 + c * 64 + d]);
    else {
        int lt = t - 16;
        o13[(size_t)lt * 4096 + d * 64 + c] =
            __float2half_rn(w3[((size_t)lt * 27 + 13) * 4096 + c * 64 + d]);
    }
}

__global__ void w3n_kernel(const float* __restrict__ w3, __half* __restrict__ o) {
    int g = blockIdx.x * 256 + threadIdx.x;
    if (g >= 4 * 27 * 4096) return;
    o[g] = __float2half_rn(w3[g]);
}

__global__ void entprep_kernel(const int* __restrict__ nbr, const int* __restrict__ inv,
                               int2* __restrict__ ent, int* __restrict__ ecnt,
                               int* __restrict__ nseg4) {
    __shared__ int bmax[4];
    const int tid = threadIdx.x;
    if (tid < 4) bmax[tid] = 0;
    __syncthreads();
    int m = blockIdx.x * 256 + tid;
    if (m < MP) {
#pragma unroll
        for (int k = 0; k < 27; k++) {
            if (k == 13) continue;
            int src = nbr[(size_t)m * 27 + k];
            if (src >= 0) {
                int idx = (k < 13) ? k : k - 1;
                int pos = atomicAdd(&ecnt[idx], 1);
                ent[(size_t)idx * MP + pos] = make_int2(m, src);
            }
        }
#pragma unroll
        for (int si = 0; si < 4; si++)
            atomicMax(&bmax[si], inv[(size_t)si * MP + m]);
    }
    __syncthreads();
    if (tid < 4) atomicMax(&nseg4[tid], bmax[tid]);
}

// ==== first layer fused: fp32 feats -> w1a epi -> H16 out; H @ W13 -> acc16 ===
__global__ __launch_bounds__(256) void gemm64hf2_kernel(
    const float* __restrict__ Xf, const __half* __restrict__ W,
    const float* __restrict__ s, const float* __restrict__ b,
    const __half* __restrict__ W13,
    __half* __restrict__ outh, __half* __restrict__ accout) {
    __shared__ __align__(16) char smA[16384];
    __shared__ __align__(16) char smB[16384];
    __shared__ __align__(16) char smW[8192];
    __shared__ __align__(16) char smW13[8192];
    const uint32_t a_s = smem_u32(smA);
    const uint32_t b_s = smem_u32(smB);
    const uint32_t w_s = smem_u32(smW);
    const uint32_t w13_s = smem_u32(smW13);
    const int tid = threadIdx.x;
    const int lane = tid & 31, wid = tid >> 5;
    const int m0 = blockIdx.x * 128;

#pragma unroll
    for (int j = 0; j < 2; j++) {
        int f = tid + j * 256;
        int r = f >> 3, c = f & 7;
        CP16(w_s + r * 128 + ((c ^ (r & 7)) << 4), W + (size_t)r * 64 + c * 8);
        CP16(w13_s + r * 128 + ((c ^ (r & 7)) << 4), W13 + (size_t)r * 64 + c * 8);
    }
    CP_COMMIT();
#pragma unroll
    for (int j = 0; j < 4; j++) {
        int f = tid + j * 256;
        int r = f >> 3, c = f & 7;
        uint32_t dst = a_s + r * 128 + ((c ^ (r & 7)) << 4);
        int m = m0 + r;
        if (m < MP) {
            float4 v0 = *(const float4*)&Xf[(size_t)m * 64 + c * 8];
            float4 v1 = *(const float4*)&Xf[(size_t)m * 64 + c * 8 + 4];
            __half2 h0 = __float22half2_rn(make_float2(v0.x, v0.y));
            __half2 h1 = __float22half2_rn(make_float2(v0.z, v0.w));
            __half2 h2 = __float22half2_rn(make_float2(v1.x, v1.y));
            __half2 h3 = __float22half2_rn(make_float2(v1.z, v1.w));
            uint32_t q0 = *(uint32_t*)&h0, q1 = *(uint32_t*)&h1;
            uint32_t q2 = *(uint32_t*)&h2, q3 = *(uint32_t*)&h3;
            asm volatile("st.shared.v4.b32 [%0], {%1,%2,%3,%4};"
                         :: "r"(dst), "r"(q0), "r"(q1), "r"(q2), "r"(q3));
        } else {
            STS_ZERO(dst);
        }
    }
    CP_WAIT(0);
    __syncthreads();

    const int wm = (wid >> 1) * 32;
    const int wn = (wid & 1) * 32;
    const int qr = lane >> 2, qc = lane & 3;

    float acc[2][4][4] = {};
    mma_tile_64(a_s, w_s, lane, wm, wn, acc);

#pragma unroll
    for (int mt = 0; mt < 2; mt++)
#pragma unroll
        for (int nt = 0; nt < 4; nt++) {
            int col = wn + nt * 8 + qc * 2;
            float2 s2 = *(const float2*)&s[col];
            float2 b2 = *(const float2*)&b[col];
            int lr0 = wm + mt * 16 + qr;
            int lr1 = lr0 + 8;
            int r0 = m0 + lr0, r1 = m0 + lr1;
            float v0 = lrelu(acc[mt][nt][0] * s2.x + b2.x, 0.01f);
            float v1 = lrelu(acc[mt][nt][1] * s2.y + b2.y, 0.01f);
            float v2 = lrelu(acc[mt][nt][2] * s2.x + b2.x, 0.01f);
            float v3 = lrelu(acc[mt][nt][3] * s2.y + b2.y, 0.01f);
            epi_to_smem(smB, lr0, lr1, col, v0, v1, v2, v3);
            if (r0 < MP) *(__half2*)&outh[(size_t)r0 * 64 + col] =
                __float22half2_rn(make_float2(v0, v1));
            if (r1 < MP) *(__half2*)&outh[(size_t)r1 * 64 + col] =
                __float22half2_rn(make_float2(v2, v3));
        }
    __syncthreads();

    float acc2[2][4][4] = {};
    mma_tile_64(b_s, w13_s, lane, wm, wn, acc2);

#pragma unroll
    for (int mt = 0; mt < 2; mt++)
#pragma unroll
        for (int nt = 0; nt < 4; nt++) {
            int col = wn + nt * 8 + qc * 2;
            int r0 = m0 + wm + mt * 16 + qr;
            int r1 = r0 + 8;
            if (r0 < MP) *(__half2*)&accout[(size_t)r0 * 64 + col] =
                __float22half2_rn(make_float2(acc2[mt][nt][0], acc2[mt][nt][1]));
            if (r1 < MP) *(__half2*)&accout[(size_t)r1 * 64 + col] =
                __float22half2_rn(make_float2(acc2[mt][nt][2], acc2[mt][nt][3]));
        }
}

// ======= sparse conv: acc16[m] += H[src] @ W3[tap]  (half2 atomics) ===========
__global__ __launch_bounds__(256) void sparse_conv_kernel(
    const __half* __restrict__ H, const __half* __restrict__ W3n,
    const int2* __restrict__ ent, const int* __restrict__ ecnt,
    __half* __restrict__ acc) {
    const int kk = blockIdx.y;             // 0..25
    const int cnt = ecnt[kk];
    if ((int)(blockIdx.x * 64) >= cnt) return;
    const int tap = (kk < 13) ? kk : kk + 1;

    __shared__ __align__(16) __half Ws[64 * 64];   // [c][j]
    __shared__ __align__(16) __half Hs[64][64];
    __shared__ int2 es[64];
    const int tid = threadIdx.x;

    const uint4* wsrc = (const uint4*)(W3n + (size_t)tap * 4096);
#pragma unroll
    for (int j = 0; j < 2; j++)
        ((uint4*)Ws)[tid + j * 256] = wsrc[tid + j * 256];

    const int wrp = tid >> 5, lane = tid & 31;

    for (int base = blockIdx.x * 64; base < cnt; base += gridDim.x * 64) {
        __syncthreads();
        if (tid < 64) {
            int e = base + tid;
            es[tid] = (e < cnt) ? ent[(size_t)kk * MP + e] : make_int2(-1, -1);
        }
        __syncthreads();
        {
            int e = tid >> 2, q = tid & 3;
            int src = es[e].y;
            if (src >= 0) {
                *(uint4*)&Hs[e][q * 8]      = *(const uint4*)&H[(size_t)src * 64 + q * 8];
                *(uint4*)&Hs[e][32 + q * 8] = *(const uint4*)&H[(size_t)src * 64 + 32 + q * 8];
            }
        }
        __syncthreads();

#pragma unroll
        for (int ei = 0; ei < 8; ei++) {
            int e = wrp * 8 + ei;
            int m = es[e].x;
            if (m < 0) continue;
            float v0 = 0.f, v1 = 0.f;
#pragma unroll
            for (int d = 0; d < 64; d++) {
                float h = __half2float(Hs[e][d]);
                float2 wf = __half22float2(*(const __half2*)&Ws[d * 64 + lane * 2]);
                v0 += h * wf.x;
                v1 += h * wf.y;
            }
            atomicAdd((__half2*)&acc[(size_t)m * 64 + lane * 2],
                      __float22half2_rn(make_float2(v0, v1)));
        }
    }
}

// === fused triple (DYNAMIC smem 56KB) =========================================
#define T3_A    0
#define T3_B    16384
#define T3_W1   32768
#define T3_W2   40960
#define T3_W13  49152
#define T3_TOT  57344

__global__ __launch_bounds__(256) void gemm64h3f_kernel(
    const __half* __restrict__ accin, const float* __restrict__ cs, const float* __restrict__ cb,
    const __half* __restrict__ W1, const float* __restrict__ s1, const float* __restrict__ b1,
    const __half* __restrict__ W2, const float* __restrict__ s2, const float* __restrict__ b2,
    const __half* __restrict__ W13,
    __half* __restrict__ outh, __half* __restrict__ accout) {
    extern __shared__ __align__(16) char smd[];
    char* smA = smd + T3_A;
    char* smB = smd + T3_B;
    const uint32_t a_s = smem_u32(smd) + T3_A;
    const uint32_t b_s = smem_u32(smd) + T3_B;
    const uint32_t w1_s = smem_u32(smd) + T3_W1;
    const uint32_t w2_s = smem_u32(smd) + T3_W2;
    const uint32_t w13_s = smem_u32(smd) + T3_W13;
    const int tid = threadIdx.x;
    const int lane = tid & 31, wid = tid >> 5;
    const int m0 = blockIdx.x * 128;

#pragma unroll
    for (int j = 0; j < 2; j++) {
        int f = tid + j * 256;
        int r = f >> 3, c = f & 7;
        CP16(w1_s + r * 128 + ((c ^ (r & 7)) << 4), W1 + (size_t)r * 64 + c * 8);
        CP16(w2_s + r * 128 + ((c ^ (r & 7)) << 4), W2 + (size_t)r * 64 + c * 8);
        CP16(w13_s + r * 128 + ((c ^ (r & 7)) << 4), W13 + (size_t)r * 64 + c * 8);
    }
    CP_COMMIT();
#pragma unroll
    for (int j = 0; j < 4; j++) {
        int f = tid + j * 256;
        int r = f >> 3, c = f & 7;
        uint32_t dst = a_s + r * 128 + ((c ^ (r & 7)) << 4);
        int m = m0 + r;
        if (m < MP) convepi_to_smem(dst, accin, (size_t)m * 64, c, cs, cb);
        else STS_ZERO(dst);
    }
    CP_WAIT(0);
    __syncthreads();

    const int wm = (wid >> 1) * 32;
    const int wn = (wid & 1) * 32;
    const int qr = lane >> 2, qc = lane & 3;

    float acc[2][4][4] = {};
    mma_tile_64(a_s, w1_s, lane, wm, wn, acc);

#pragma unroll
    for (int mt = 0; mt < 2; mt++)
#pragma unroll
        for (int nt = 0; nt < 4; nt++) {
            int col = wn + nt * 8 + qc * 2;
            float2 sv = *(const float2*)&s1[col];
            float2 bv = *(const float2*)&b1[col];
            int lr0 = wm + mt * 16 + qr;
            int lr1 = lr0 + 8;
            epi_to_smem(smB, lr0, lr1, col,
                        lrelu(acc[mt][nt][0] * sv.x + bv.x, 0.01f),
                        lrelu(acc[mt][nt][1] * sv.y + bv.y, 0.01f),
                        lrelu(acc[mt][nt][2] * sv.x + bv.x, 0.01f),
                        lrelu(acc[mt][nt][3] * sv.y + bv.y, 0.01f));
        }
    __syncthreads();

    float acc2[2][4][4] = {};
    mma_tile_64(b_s, w2_s, lane, wm, wn, acc2);
    __syncthreads();

#pragma unroll
    for (int mt = 0; mt < 2; mt++)
#pragma unroll
        for (int nt = 0; nt < 4; nt++) {
            int col = wn + nt * 8 + qc * 2;
            float2 sv = *(const float2*)&s2[col];
            float2 bv = *(const float2*)&b2[col];
            int lr0 = wm + mt * 16 + qr;
            int lr1 = lr0 + 8;
            int r0 = m0 + lr0, r1 = m0 + lr1;
            float v0 = lrelu(acc2[mt][nt][0] * sv.x + bv.x, 0.01f);
            float v1 = lrelu(acc2[mt][nt][1] * sv.y + bv.y, 0.01f);
            float v2 = lrelu(acc2[mt][nt][2] * sv.x + bv.x, 0.01f);
            float v3 = lrelu(acc2[mt][nt][3] * sv.y + bv.y, 0.01f);
            epi_to_smem(smA, lr0, lr1, col, v0, v1, v2, v3);
            if (r0 < MP) *(__half2*)&outh[(size_t)r0 * 64 + col] =
                __float22half2_rn(make_float2(v0, v1));
            if (r1 < MP) *(__half2*)&outh[(size_t)r1 * 64 + col] =
                __float22half2_rn(make_float2(v2, v3));
        }
    __syncthreads();

    float acc3[2][4][4] = {};
    mma_tile_64(a_s, w13_s, lane, wm, wn, acc3);

#pragma unroll
    for (int mt = 0; mt < 2; mt++)
#pragma unroll
        for (int nt = 0; nt < 4; nt++) {
            int col = wn + nt * 8 + qc * 2;
            int r0 = m0 + wm + mt * 16 + qr;
            int r1 = r0 + 8;
            if (r0 < MP) *(__half2*)&accout[(size_t)r0 * 64 + col] =
                __float22half2_rn(make_float2(acc3[mt][nt][0], acc3[mt][nt][1]));
            if (r1 < MP) *(__half2*)&accout[(size_t)r1 * 64 + col] =
                __float22half2_rn(make_float2(acc3[mt][nt][2], acc3[mt][nt][3]));
        }
}

// === fused last: conv-epi(acc16) -> @W1b -> epi + residual -> V fp32 + aux ====
__global__ __launch_bounds__(256) void gemm64h_resf_kernel(
    const __half* __restrict__ accin, const float* __restrict__ cs, const float* __restrict__ cb,
    const __half* __restrict__ W, const float* __restrict__ s, const float* __restrict__ b,
    float* __restrict__ outf, const float* __restrict__ feats,
    const float* __restrict__ aux_w, const float* __restrict__ aux_b,
    float* __restrict__ aux) {
    __shared__ __align__(16) char smA[16384];
    __shared__ __align__(16) char smW[8192];
    __shared__ float Ws20[64 * 20];
    __shared__ float bs20[20];
    const uint32_t a_s = smem_u32(smA);
    const uint32_t w_s = smem_u32(smW);
    const int tid = threadIdx.x;
    const int lane = tid & 31, wid = tid >> 5;
    const int m0 = blockIdx.x * 128;

#pragma unroll
    for (int j = 0; j < 2; j++) {
        int f = tid + j * 256;
        int r = f >> 3, c = f & 7;
        CP16(w_s + r * 128 + ((c ^ (r & 7)) << 4), W + (size_t)r * 64 + c * 8);
    }
    CP_COMMIT();
    for (int f = tid; f < 64 * 20; f += 256) Ws20[f] = aux_w[f];
    if (tid < 20) bs20[tid] = aux_b[tid];
#pragma unroll
    for (int j = 0; j < 4; j++) {
        int f = tid + j * 256;
        int r = f >> 3, c = f & 7;
        uint32_t dst = a_s + r * 128 + ((c ^ (r & 7)) << 4);
        int m = m0 + r;
        if (m < MP) convepi_to_smem(dst, accin, (size_t)m * 64, c, cs, cb);
        else STS_ZERO(dst);
    }
    CP_WAIT(0);
    __syncthreads();

    const int wm = (wid >> 1) * 32;
    const int wn = (wid & 1) * 32;
    float acc[2][4][4] = {};
    mma_tile_64(a_s, w_s, lane, wm, wn, acc);
    __syncthreads();

    const int qr = lane >> 2, qc = lane & 3;
#pragma unroll
    for (int mt = 0; mt < 2; mt++)
#pragma unroll
        for (int nt = 0; nt < 4; nt++) {
            int col = wn + nt * 8 + qc * 2;
            float2 sv = *(const float2*)&s[col];
            float2 bv = *(const float2*)&b[col];
            int lr0 = wm + mt * 16 + qr;
            int lr1 = lr0 + 8;
            int r0 = m0 + lr0, r1 = m0 + lr1;
            float v0 = 0.f, v1 = 0.f, v2 = 0.f, v3 = 0.f;
            if (r0 < MP) {
                float2 fr = *(const float2*)&feats[(size_t)r0 * 64 + col];
                v0 = lrelu(lrelu(acc[mt][nt][0] * sv.x + bv.x, 0.01f) + fr.x, 0.1f);
                v1 = lrelu(lrelu(acc[mt][nt][1] * sv.y + bv.y, 0.01f) + fr.y, 0.1f);
                *(float2*)&outf[(size_t)r0 * 64 + col] = make_float2(v0, v1);
            }
            if (r1 < MP) {
                float2 fr = *(const float2*)&feats[(size_t)r1 * 64 + col];
                v2 = lrelu(lrelu(acc[mt][nt][2] * sv.x + bv.x, 0.01f) + fr.x, 0.1f);
                v3 = lrelu(lrelu(acc[mt][nt][3] * sv.y + bv.y, 0.01f) + fr.y, 0.1f);
                *(float2*)&outf[(size_t)r1 * 64 + col] = make_float2(v2, v3);
            }
            epi_to_smem(smA, lr0, lr1, col, v0, v1, v2, v3);
        }
    __syncthreads();

    {
        int r = tid >> 1, n0 = (tid & 1) * 10;
        int m = m0 + r;
        if (m < MP) {
            float accn[10];
#pragma unroll
            for (int j = 0; j < 10; j++) accn[j] = bs20[n0 + j];
#pragma unroll 8
            for (int c = 0; c < 64; c++) {
                float x = smem_h(smA, r, c);
#pragma unroll
                for (int j = 0; j < 10; j++) accn[j] += x * Ws20[c * 20 + n0 + j];
            }
#pragma unroll
            for (int j = 0; j < 10; j++) aux[(size_t)m * 20 + n0 + j] = accn[j];
        }
    }
}

// ============== bounded zero: only rows [0, nseg+1) per scale =================
__global__ void zero_all_kernel(float* __restrict__ vsum4, float* __restrict__ vcnt4,
                                const int* __restrict__ nseg4) {
    const int si = blockIdx.y;
    const int cap = nseg4[si] + 1;
    const int nf4 = cap * 16;
    float4* dst = (float4*)(vsum4 + (size_t)si * MP * 64);
    for (int i = blockIdx.x * 256 + threadIdx.x; i < nf4; i += gridDim.x * 256)
        dst[i] = make_float4(0.f, 0.f, 0.f, 0.f);
    float* cdst = vcnt4 + (size_t)si * MP;
    for (int i = blockIdx.x * 256 + threadIdx.x; i < cap; i += gridDim.x * 256)
        cdst[i] = 0.f;
}

// =============== scatter: read V once, 4 scales inner loop ====================
__global__ void scatter_all_kernel(const float* __restrict__ V, const int* __restrict__ inv,
                                   float* __restrict__ vsum4, float* __restrict__ vcnt4) {
    int gid = blockIdx.x * 256 + threadIdx.x;
    if (gid >= MP * 64) return;
    int m = gid >> 6, c = gid & 63;
    float v = V[gid];
#pragma unroll
    for (int si = 0; si < 4; si++) {
        int sg = inv[(size_t)si * MP + m];
        atomicAdd(&vsum4[(size_t)si * MP * 64 + sg * 64 + c], v);
        if (c == 0) atomicAdd(&vcnt4[(size_t)si * MP + sg], 1.0f);
    }
}

// ====== proj 4-in-1: V staged in smem, per scale Os build + GEMM -> ms ========
#define P4_V   0        // 32768 fp32 V tile [128][64]
#define P4_A   32768    // 16384
#define P4_W   49152    // 8192
#define P4_TOT 57344

__global__ __launch_bounds__(256) void proj4_mma_kernel(
    const float* __restrict__ V, const int* __restrict__ inv,
    const float* __restrict__ vsum4, const float* __restrict__ vcnt4,
    const __half* __restrict__ Wp, const float* __restrict__ pb,
    const float* __restrict__ ps, const float* __restrict__ pbb,
    __half* __restrict__ ms) {
    extern __shared__ __align__(16) char smd[];
    float* Vs = (float*)(smd + P4_V);
    const uint32_t a_s = smem_u32(smd) + P4_A;
    const uint32_t w_s = smem_u32(smd) + P4_W;
    const int tid = threadIdx.x;
    const int lane = tid & 31, wid = tid >> 5;
    const int m0 = blockIdx.x * 128;

#pragma unroll
    for (int j = 0; j < 8; j++) {
        int idx = tid + j * 256;
        int r = idx >> 4, c4 = idx & 15;
        int m = m0 + r;
        float4 v = make_float4(0.f, 0.f, 0.f, 0.f);
        if (m < MP) v = *(const float4*)&V[(size_t)m * 64 + c4 * 4];
        *(float4*)&Vs[r * 64 + c4 * 4] = v;
    }
    __syncthreads();

    const int wm = (wid >> 1) * 32;
    const int wn = (wid & 1) * 32;
    const int qr = lane >> 2, qc = lane & 3;

    for (int si = 0; si < 4; si++) {
        const int* seg = inv + (size_t)si * MP;
        const float* vsum = vsum4 + (size_t)si * MP * 64;
        const float* vcnt = vcnt4 + (size_t)si * MP;
        __half* msO = ms + (size_t)si * MP * 64;

#pragma unroll
        for (int j = 0; j < 2; j++) {
            int f = tid + j * 256;
            int r = f >> 3, c = f & 7;
            CP16(w_s + r * 128 + ((c ^ (r & 7)) << 4),
                 Wp + (size_t)si * 4096 + r * 64 + c * 8);
        }
        CP_COMMIT();

#pragma unroll
        for (int j = 0; j < 4; j++) {
            int f = tid + j * 256;
            int r = f >> 3, c = f & 7;
            uint32_t dst = a_s + r * 128 + ((c ^ (r & 7)) << 4);
            int m = m0 + r;
            if (m < MP) {
                int sg = seg[m];
                float rc = 1.0f / fmaxf(vcnt[sg], 1.0f);
                float4 v0 = *(const float4*)&Vs[r * 64 + c * 8];
                float4 v1 = *(const float4*)&Vs[r * 64 + c * 8 + 4];
                float4 u0 = *(const float4*)&vsum[(size_t)sg * 64 + c * 8];
                float4 u1 = *(const float4*)&vsum[(size_t)sg * 64 + c * 8 + 4];
                __half2 h0 = __float22half2_rn(make_float2((v0.x - u0.x * rc) * v0.x,
                                                           (v0.y - u0.y * rc) * v0.y));
                __half2 h1 = __float22half2_rn(make_float2((v0.z - u0.z * rc) * v0.z,
                                                           (v0.w - u0.w * rc) * v0.w));
                __half2 h2 = __float22half2_rn(make_float2((v1.x - u1.x * rc) * v1.x,
                                                           (v1.y - u1.y * rc) * v1.y));
                __half2 h3 = __float22half2_rn(make_float2((v1.z - u1.z * rc) * v1.z,
                                                           (v1.w - u1.w * rc) * v1.w));
                uint32_t q0 = *(uint32_t*)&h0, q1 = *(uint32_t*)&h1;
                uint32_t q2 = *(uint32_t*)&h2, q3 = *(uint32_t*)&h3;
                asm volatile("st.shared.v4.b32 [%0], {%1,%2,%3,%4};"
                             :: "r"(dst), "r"(q0), "r"(q1), "r"(q2), "r"(q3));
            } else {
                STS_ZERO(dst);
            }
        }
        CP_WAIT(0);
        __syncthreads();

        float acc[2][4][4] = {};
        mma_tile_64(a_s, w_s, lane, wm, wn, acc);

#pragma unroll
        for (int mt = 0; mt < 2; mt++)
#pragma unroll
            for (int nt = 0; nt < 4; nt++) {
                int col = wn + nt * 8 + qc * 2;
                float2 bv = *(const float2*)&pb[si * 64 + col];
                float2 sv = *(const float2*)&ps[si * 64 + col];
                float2 b2 = *(const float2*)&pbb[si * 64 + col];
                int r0 = m0 + wm + mt * 16 + qr;
                int r1 = r0 + 8;
                if (r0 < MP) *(__half2*)&msO[(size_t)r0 * 64 + col] = __float22half2_rn(
                    make_float2(lrelu((acc[mt][nt][0] + bv.x) * sv.x + b2.x, 0.01f),
                                lrelu((acc[mt][nt][1] + bv.y) * sv.y + b2.y, 0.01f)));
                if (r1 < MP) *(__half2*)&msO[(size_t)r1 * 64 + col] = __float22half2_rn(
                    make_float2(lrelu((acc[mt][nt][2] + bv.x) * sv.x + b2.x, 0.01f),
                                lrelu((acc[mt][nt][3] + bv.y) * sv.y + b2.y, 0.01f)));
            }
        __syncthreads();
    }
}

// ===== attn: ms tiles staged in smem, 4 GEMMs, fused out + head logits ========
#define AT_A   0        // 16384
#define AT_W   16384    // 8192
#define AT_MS  24576    // 4 x 16384 = 65536
#define AT_TOT 90112

__global__ __launch_bounds__(256) void attn_mma_kernel(
    const __half* __restrict__ ms, const __half* __restrict__ Wa,
    const float* __restrict__ ab, const float* __restrict__ as_,
    const float* __restrict__ abb, float* __restrict__ fused,
    const float* __restrict__ head_w, const float* __restrict__ head_b,
    float* __restrict__ logits) {
    extern __shared__ __align__(16) char smd[];
    char* smA = smd + AT_A;
    char* msS = smd + AT_MS;
    const uint32_t a_s = smem_u32(smd) + AT_A;
    const uint32_t w_s = smem_u32(smd) + AT_W;
    __shared__ float Ws20[64 * 20];
    __shared__ float bs20[20];
    const int tid = threadIdx.x;
    const int lane = tid & 31, wid = tid >> 5;
    const int m0 = blockIdx.x * 128;

    for (int f = tid; f < 64 * 20; f += 256) Ws20[f] = head_w[f];
    if (tid < 20) bs20[tid] = head_b[tid];

#pragma unroll
    for (int j = 0; j < 4; j++) {
        int f = tid + j * 256;
        int r = f >> 3, c = f & 7;
        uint32_t dstoff = r * 128 + ((c ^ (r & 7)) << 4);
        int m = m0 + r;
        if (m < MP) {
            float sx[8] = {};
#pragma unroll
            for (int i = 0; i < 4; i++) {
                uint4 q = *(const uint4*)&ms[((size_t)i * MP + m) * 64 + c * 8];
                *(uint4*)(msS + i * 16384 + dstoff) = q;
                const __half2* hp = (const __half2*)&q;
#pragma unroll
                for (int t = 0; t < 4; t++) {
                    float2 fv = __half22float2(hp[t]);
                    sx[t * 2] += fv.x;
                    sx[t * 2 + 1] += fv.y;
                }
            }
            __half2 h0 = __float22half2_rn(make_float2(sx[0], sx[1]));
            __half2 h1 = __float22half2_rn(make_float2(sx[2], sx[3]));
            __half2 h2 = __float22half2_rn(make_float2(sx[4], sx[5]));
            __half2 h3 = __float22half2_rn(make_float2(sx[6], sx[7]));
            uint32_t q0 = *(uint32_t*)&h0, q1 = *(uint32_t*)&h1;
            uint32_t q2 = *(uint32_t*)&h2, q3 = *(uint32_t*)&h3;
            asm volatile("st.shared.v4.b32 [%0], {%1,%2,%3,%4};"
                         :: "r"(a_s + dstoff), "r"(q0), "r"(q1), "r"(q2), "r"(q3));
        } else {
            STS_ZERO(a_s + dstoff);
            uint4 z = make_uint4(0, 0, 0, 0);
#pragma unroll
            for (int i = 0; i < 4; i++)
                *(uint4*)(msS + i * 16384 + dstoff) = z;
        }
    }

    const int wm = (wid >> 1) * 32;
    const int wn = (wid & 1) * 32;
    const int qr = lane >> 2, qc = lane & 3;
    float fac[2][4][4] = {};

    for (int i = 0; i < 4; i++) {
        __syncthreads();
#pragma unroll
        for (int j = 0; j < 2; j++) {
            int f = tid + j * 256;
            int r = f >> 3, c = f & 7;
            CP16(w_s + r * 128 + ((c ^ (r & 7)) << 4),
                 Wa + (size_t)i * 4096 + r * 64 + c * 8);
        }
        CP_COMMIT();
        CP_WAIT(0);
        __syncthreads();

        float acc[2][4][4] = {};
        mma_tile_64(a_s, w_s, lane, wm, wn, acc);

        const char* msT = msS + i * 16384;
#pragma unroll
        for (int mt = 0; mt < 2; mt++)
#pragma unroll
            for (int nt = 0; nt < 4; nt++) {
                int col = wn + nt * 8 + qc * 2;
                float2 bv = *(const float2*)&ab[i * 64 + col];
                float2 sv = *(const float2*)&as_[i * 64 + col];
                float2 b2 = *(const float2*)&abb[i * 64 + col];
                int lr0 = wm + mt * 16 + qr;
                int lr1 = lr0 + 8;
                {
                    float2 mv = smem_h2(msT, lr0, col);
                    float a0 = 1.0f / (1.0f + __expf(-((acc[mt][nt][0] + bv.x) * sv.x + b2.x)));
                    float a1 = 1.0f / (1.0f + __expf(-((acc[mt][nt][1] + bv.y) * sv.y + b2.y)));
                    fac[mt][nt][0] += a0 * mv.x;
                    fac[mt][nt][1] += a1 * mv.y;
                }
                {
                    float2 mv = smem_h2(msT, lr1, col);
                    float a2 = 1.0f / (1.0f + __expf(-((acc[mt][nt][2] + bv.x) * sv.x + b2.x)));
                    float a3 = 1.0f / (1.0f + __expf(-((acc[mt][nt][3] + bv.y) * sv.y + b2.y)));
                    fac[mt][nt][2] += a2 * mv.x;
                    fac[mt][nt][3] += a3 * mv.y;
                }
            }
    }
    __syncthreads();

#pragma unroll
    for (int mt = 0; mt < 2; mt++)
#pragma unroll
        for (int nt = 0; nt < 4; nt++) {
            int col = wn + nt * 8 + qc * 2;
            int lr0 = wm + mt * 16 + qr;
            int lr1 = lr0 + 8;
            int r0 = m0 + lr0, r1 = m0 + lr1;
            if (r0 < MP) *(float2*)&fused[(size_t)r0 * 64 + col] =
                make_float2(fac[mt][nt][0], fac[mt][nt][1]);
            if (r1 < MP) *(float2*)&fused[(size_t)r1 * 64 + col] =
                make_float2(fac[mt][nt][2], fac[mt][nt][3]);
            epi_to_smem(smA, lr0, lr1, col,
                        fac[mt][nt][0], fac[mt][nt][1], fac[mt][nt][2], fac[mt][nt][3]);
        }
    __syncthreads();

    {
        int r = tid >> 1, n0 = (tid & 1) * 10;
        int m = m0 + r;
        if (m < MP) {
            float accn[10];
#pragma unroll
            for (int j = 0; j < 10; j++) accn[j] = bs20[n0 + j];
#pragma unroll 8
            for (int c = 0; c < 64; c++) {
                float x = smem_h(smA, r, c);
#pragma unroll
                for (int j = 0; j < 10; j++) accn[j] += x * Ws20[c * 20 + n0 + j];
            }
#pragma unroll
            for (int j = 0; j < 10; j++) logits[(size_t)m * 20 + n0 + j] = accn[j];
        }
    }
}

// ==============================================================================
extern "C" void kernel_launch(void* const* d_in, const int* in_sizes, int n_in,
                              void* d_out, int out_size) {
    const float* feats   = (const float*)d_in[0];
    const float* w1a     = (const float*)d_in[1];
    const float* s1a     = (const float*)d_in[2];
    const float* b1a     = (const float*)d_in[3];
    const float* w3      = (const float*)d_in[4];
    const float* s3      = (const float*)d_in[5];
    const float* b3      = (const float*)d_in[6];
    const float* w1b     = (const float*)d_in[7];
    const float* s1b     = (const float*)d_in[8];
    const float* b1b     = (const float*)d_in[9];
    const float* aux_w   = (const float*)d_in[10];
    const float* aux_b   = (const float*)d_in[11];
    const float* proj_w  = (const float*)d_in[12];
    const float* proj_b  = (const float*)d_in[13];
    const float* proj_s  = (const float*)d_in[14];
    const float* proj_bb = (const float*)d_in[15];
    const float* attn_w  = (const float*)d_in[16];
    const float* attn_b  = (const float*)d_in[17];
    const float* attn_s  = (const float*)d_in[18];
    const float* attn_bb = (const float*)d_in[19];
    const float* head_w  = (const float*)d_in[20];
    const float* head_b  = (const float*)d_in[21];
    const int*   nbr     = (const int*)d_in[22];
    const int*   inv     = (const int*)d_in[23];

    float* out    = (float*)d_out;
    float* fused  = out;
    float* logits = out + (size_t)MP * 64;
    float* aux    = out + (size_t)MP * 84;

    float *pV, *pvs, *pvc;
    __half *pH16, *pW1a, *pW1b, *pWp, *pWa, *pW13, *pW3n, *pms, *pacc;
    int2 *pent; int *pecnt, *pnseg;
    cudaGetSymbolAddress((void**)&pV, g_V);
    cudaGetSymbolAddress((void**)&pms, g_ms16);
    cudaGetSymbolAddress((void**)&pvs, g_vsum4);
    cudaGetSymbolAddress((void**)&pvc, g_vcnt4);
    cudaGetSymbolAddress((void**)&pacc, g_acc16);
    cudaGetSymbolAddress((void**)&pH16, g_H16);
    cudaGetSymbolAddress((void**)&pW1a, g_W1a16);
    cudaGetSymbolAddress((void**)&pW1b, g_W1b16);
    cudaGetSymbolAddress((void**)&pWp, g_Wp16);
    cudaGetSymbolAddress((void**)&pWa, g_Wa16);
    cudaGetSymbolAddress((void**)&pW13, g_W13t);
    cudaGetSymbolAddress((void**)&pW3n, g_W3n);
    cudaGetSymbolAddress((void**)&pent, g_ent);
    cudaGetSymbolAddress((void**)&pecnt, g_ecnt);
    cudaGetSymbolAddress((void**)&pnseg, g_nseg4);

    cudaFuncSetAttribute(gemm64h3f_kernel, cudaFuncAttributeMaxDynamicSharedMemorySize, T3_TOT);
    cudaFuncSetAttribute(proj4_mma_kernel, cudaFuncAttributeMaxDynamicSharedMemorySize, P4_TOT);
    cudaFuncSetAttribute(attn_mma_kernel, cudaFuncAttributeMaxDynamicSharedMemorySize, AT_TOT);

    wprep_kernel<<<320, 256>>>(w1a, w1b, proj_w, attn_w, w3,
                               pW1a, pW1b, pWp, pWa, pW13, pecnt, pnseg);
    w3n_kernel<<<1728, 256>>>(w3, pW3n);
    entprep_kernel<<<469, 256>>>(nbr, inv, pent, pecnt, pnseg);

    gemm64hf2_kernel<<<GTC, 256>>>(feats, pW1a, s1a, b1a, pW13, pH16, pacc);
    for (int i = 0; i < 4; i++) {
        {
            dim3 grid(128, 26);
            sparse_conv_kernel<<<grid, 256>>>(pH16, pW3n + (size_t)i * 27 * 4096,
                                              pent, pecnt, pacc);
        }
        if (i < 3) {
            gemm64h3f_kernel<<<GTC, 256, T3_TOT>>>(pacc, s3 + i * 64, b3 + i * 64,
                                           pW1b + (size_t)i * 4096, s1b + i * 64, b1b + i * 64,
                                           pW1a + (size_t)(i + 1) * 4096, s1a + (i + 1) * 64,
                                           b1a + (i + 1) * 64,
                                           pW13 + (size_t)(i + 1) * 4096,
                                           pH16, pacc);
        } else {
            gemm64h_resf_kernel<<<GTC, 256>>>(pacc, s3 + i * 64, b3 + i * 64,
                                              pW1b + (size_t)i * 4096, s1b + i * 64,
                                              b1b + i * 64, pV, feats,
                                              aux_w, aux_b, aux);
        }
    }

    {
        dim3 zgrid(469, 4);
        zero_all_kernel<<<zgrid, 256>>>(pvs, pvc, pnseg);
    }
    scatter_all_kernel<<<30000, 256>>>(pV, inv, pvs, pvc);
    proj4_mma_kernel<<<GTC, 256, P4_TOT>>>(pV, inv, pvs, pvc, pWp,
                                           proj_b, proj_s, proj_bb, pms);
    attn_mma_kernel<<<GTC, 256, AT_TOT>>>(pms, pWa, attn_b, attn_s, attn_bb, fused,
                                          head_w, head_b, logits);
}